// round 2
// baseline (speedup 1.0000x reference)
#include <cuda_runtime.h>
#include <math.h>

#define SEQ 2048
#define EMB 1024
#define NH  16
#define HD  64

// Scratch (no runtime allocation allowed)
__device__ float g_Q[SEQ * EMB];
__device__ float g_K[SEQ * EMB];
__device__ float g_V[SEQ * EMB];
__device__ float g_ctx[SEQ * EMB];

// ---------------------------------------------------------------------------
// NT GEMM: C = alpha * (A @ B^T) + bias
// A: [M,K] row-major (lda), B: [N,K] row-major (ldb), C: [M,N] (ldc)
// Tiles: BM=BN=128, BK=8. 256 threads, each computes an 8x8 microtile.
// All dims must divide the tiles (true for every use here).
// Per-z offsets allow batching over heads.
// ---------------------------------------------------------------------------
__global__ __launch_bounds__(256, 2)
void gemm_nt_128(const float* __restrict__ A, const float* __restrict__ B,
                 float* __restrict__ C, const float* __restrict__ bias,
                 int K, int lda, int ldb, int ldc,
                 long long sAz, long long sBz, long long sCz, float alpha)
{
    A += (size_t)blockIdx.z * sAz;
    B += (size_t)blockIdx.z * sBz;
    C += (size_t)blockIdx.z * sCz;

    __shared__ float As[8][128];
    __shared__ float Bs[8][128];

    const int tid  = threadIdx.x;
    const int row0 = blockIdx.y * 128;
    const int col0 = blockIdx.x * 128;

    // loader: 128 rows x 8 k; each thread loads one float4
    const int lr = tid >> 1;          // 0..127
    const int lk = (tid & 1) * 4;     // 0 or 4

    // compute layout: 16x16 threads, 8x8 each
    const int ty = tid >> 4;
    const int tx = tid & 15;

    const float* Aptr = A + (long long)(row0 + lr) * lda + lk;
    const float* Bptr = B + (long long)(col0 + lr) * ldb + lk;

    float acc[8][8];
#pragma unroll
    for (int i = 0; i < 8; i++)
#pragma unroll
        for (int j = 0; j < 8; j++) acc[i][j] = 0.f;

    for (int k0 = 0; k0 < K; k0 += 8) {
        float4 av = *(const float4*)(Aptr + k0);
        float4 bv = *(const float4*)(Bptr + k0);
        As[lk + 0][lr] = av.x; As[lk + 1][lr] = av.y;
        As[lk + 2][lr] = av.z; As[lk + 3][lr] = av.w;
        Bs[lk + 0][lr] = bv.x; Bs[lk + 1][lr] = bv.y;
        Bs[lk + 2][lr] = bv.z; Bs[lk + 3][lr] = bv.w;
        __syncthreads();

#pragma unroll
        for (int kk = 0; kk < 8; kk++) {
            float a[8], b[8];
#pragma unroll
            for (int i = 0; i < 8; i++) a[i] = As[kk][ty * 8 + i];
#pragma unroll
            for (int j = 0; j < 8; j++) b[j] = Bs[kk][tx * 8 + j];
#pragma unroll
            for (int i = 0; i < 8; i++)
#pragma unroll
                for (int j = 0; j < 8; j++)
                    acc[i][j] = fmaf(a[i], b[j], acc[i][j]);
        }
        __syncthreads();
    }

#pragma unroll
    for (int i = 0; i < 8; i++) {
        const long long row = row0 + ty * 8 + i;
#pragma unroll
        for (int j = 0; j < 8; j++) {
            const int col = col0 + tx * 8 + j;
            float v = acc[i][j] * alpha;
            if (bias) v += bias[col];
            C[row * ldc + col] = v;
        }
    }
}

// ---------------------------------------------------------------------------
// NN GEMM: C = A @ B   (used for ctx = attn @ V_h, N = 64)
// A: [M,K] (lda), B: [K,N] (ldb), C: [M,N] (ldc)
// Tiles: BM=128, BN=64, BK=16. 256 threads, each computes 8x4.
// ---------------------------------------------------------------------------
__global__ __launch_bounds__(256, 2)
void gemm_nn_128x64(const float* __restrict__ A, const float* __restrict__ B,
                    float* __restrict__ C,
                    int K, int lda, int ldb, int ldc,
                    long long sAz, long long sBz, long long sCz)
{
    A += (size_t)blockIdx.z * sAz;
    B += (size_t)blockIdx.z * sBz;
    C += (size_t)blockIdx.z * sCz;

    __shared__ float As[16][128];
    __shared__ float Bs[16][64];

    const int tid  = threadIdx.x;
    const int row0 = blockIdx.y * 128;
    const int col0 = blockIdx.x * 64;

    const int ty = tid >> 4;   // 0..15 -> 8 rows each
    const int tx = tid & 15;   // 0..15 -> 4 cols each

    float acc[8][4];
#pragma unroll
    for (int i = 0; i < 8; i++)
#pragma unroll
        for (int j = 0; j < 4; j++) acc[i][j] = 0.f;

    // B loader indices: 16 k-rows x 64 cols, one float4 per thread
    const int bk = tid >> 4;          // 0..15
    const int bc = (tid & 15) * 4;    // 0..60

    for (int k0 = 0; k0 < K; k0 += 16) {
        // A tile: 128x16, two float4 per thread
#pragma unroll
        for (int l = 0; l < 2; l++) {
            const int idx = tid + l * 256;       // 0..511
            const int r  = idx >> 2;             // 0..127
            const int kq = (idx & 3) * 4;        // 0,4,8,12
            float4 v = *(const float4*)(A + (long long)(row0 + r) * lda + k0 + kq);
            As[kq + 0][r] = v.x; As[kq + 1][r] = v.y;
            As[kq + 2][r] = v.z; As[kq + 3][r] = v.w;
        }
        // B tile: 16x64
        {
            float4 v = *(const float4*)(B + (long long)(k0 + bk) * ldb + col0 + bc);
            *(float4*)&Bs[bk][bc] = v;
        }
        __syncthreads();

#pragma unroll
        for (int kk = 0; kk < 16; kk++) {
            float a[8], b[4];
#pragma unroll
            for (int i = 0; i < 8; i++) a[i] = As[kk][ty * 8 + i];
#pragma unroll
            for (int j = 0; j < 4; j++) b[j] = Bs[kk][tx * 4 + j];
#pragma unroll
            for (int i = 0; i < 8; i++)
#pragma unroll
                for (int j = 0; j < 4; j++)
                    acc[i][j] = fmaf(a[i], b[j], acc[i][j]);
        }
        __syncthreads();
    }

#pragma unroll
    for (int i = 0; i < 8; i++) {
        const long long row = row0 + ty * 8 + i;
#pragma unroll
        for (int j = 0; j < 4; j++) {
            C[row * ldc + col0 + tx * 4 + j] = acc[i][j];
        }
    }
}

// ---------------------------------------------------------------------------
// Row softmax, in place. One block per row of 2048 floats. 256 threads.
// ---------------------------------------------------------------------------
__global__ __launch_bounds__(256)
void softmax_rows(float* __restrict__ attn)
{
    const long long row = blockIdx.x;
    float* p = attn + row * (long long)SEQ;
    const int tid = threadIdx.x;

    float v[8];
    float m = -1e30f;
#pragma unroll
    for (int i = 0; i < 8; i++) {
        v[i] = p[tid + i * 256];
        m = fmaxf(m, v[i]);
    }

    __shared__ float red[32];
    // max reduce
#pragma unroll
    for (int o = 16; o > 0; o >>= 1)
        m = fmaxf(m, __shfl_xor_sync(0xffffffffu, m, o));
    if ((tid & 31) == 0) red[tid >> 5] = m;
    __syncthreads();
    if (tid < 32) {
        float t = (tid < 8) ? red[tid] : -1e30f;
#pragma unroll
        for (int o = 4; o > 0; o >>= 1)
            t = fmaxf(t, __shfl_xor_sync(0xffffffffu, t, o));
        if (tid == 0) red[0] = t;
    }
    __syncthreads();
    const float mx = red[0];

    float s = 0.f;
#pragma unroll
    for (int i = 0; i < 8; i++) {
        v[i] = expf(v[i] - mx);
        s += v[i];
    }
    __syncthreads();  // re-use red[]
    // sum reduce
#pragma unroll
    for (int o = 16; o > 0; o >>= 1)
        s += __shfl_xor_sync(0xffffffffu, s, o);
    if ((tid & 31) == 0) red[tid >> 5] = s;
    __syncthreads();
    if (tid < 32) {
        float t = (tid < 8) ? red[tid] : 0.f;
#pragma unroll
        for (int o = 4; o > 0; o >>= 1)
            t += __shfl_xor_sync(0xffffffffu, t, o);
        if (tid == 0) red[0] = t;
    }
    __syncthreads();
    const float inv = 1.0f / red[0];

#pragma unroll
    for (int i = 0; i < 8; i++)
        p[tid + i * 256] = v[i] * inv;
}

// ---------------------------------------------------------------------------
extern "C" void kernel_launch(void* const* d_in, const int* in_sizes, int n_in,
                              void* d_out, int out_size)
{
    const float* x  = (const float*)d_in[0];
    const float* Wq = (const float*)d_in[1];
    const float* bq = (const float*)d_in[2];
    const float* Wk = (const float*)d_in[3];
    const float* bk = (const float*)d_in[4];
    const float* Wv = (const float*)d_in[5];
    const float* bv = (const float*)d_in[6];
    const float* Wo = (const float*)d_in[7];
    const float* bo = (const float*)d_in[8];

    float* out  = (float*)d_out;                       // [SEQ, EMB]
    float* attn = out + (size_t)SEQ * EMB;             // [NH, SEQ, SEQ]

    float *Q, *K, *V, *ctx;
    cudaGetSymbolAddress((void**)&Q,   g_Q);
    cudaGetSymbolAddress((void**)&K,   g_K);
    cudaGetSymbolAddress((void**)&V,   g_V);
    cudaGetSymbolAddress((void**)&ctx, g_ctx);

    // 1) Q/K/V projections: [2048,1024] = x @ W^T + b
    dim3 gProj(EMB / 128, SEQ / 128, 1);
    gemm_nt_128<<<gProj, 256>>>(x, Wq, Q, bq, EMB, EMB, EMB, EMB, 0, 0, 0, 1.0f);
    gemm_nt_128<<<gProj, 256>>>(x, Wk, K, bk, EMB, EMB, EMB, EMB, 0, 0, 0, 1.0f);
    gemm_nt_128<<<gProj, 256>>>(x, Wv, V, bv, EMB, EMB, EMB, EMB, 0, 0, 0, 1.0f);

    // 2) scores[h] = (Q_h @ K_h^T) * (1/sqrt(EMB))  -> written into attn region
    dim3 gScore(SEQ / 128, SEQ / 128, NH);
    gemm_nt_128<<<gScore, 256>>>(Q, K, attn, nullptr, HD, EMB, EMB, SEQ,
                                 HD, HD, (long long)SEQ * SEQ, 0.03125f);

    // 3) softmax rows in place
    softmax_rows<<<NH * SEQ, 256>>>(attn);

    // 4) ctx[h] = attn[h] @ V_h  -> g_ctx laid out as [SEQ, EMB]
    dim3 gCtx(1, SEQ / 128, NH);
    gemm_nn_128x64<<<gCtx, 256>>>(attn, V, ctx, SEQ, SEQ, EMB, EMB,
                                  (long long)SEQ * SEQ, HD, HD);

    // 5) out = ctx @ Wo^T + bo
    gemm_nt_128<<<gProj, 256>>>(ctx, Wo, out, bo, EMB, EMB, EMB, EMB, 0, 0, 0, 1.0f);
}

// round 4
// speedup vs baseline: 2.2947x; 2.2947x over previous
#include <cuda_runtime.h>
#include <cuda_bf16.h>
#include <cstdint>
#include <math.h>

#define SEQ 2048
#define EMB 1024
#define NH  16
#define HD  64

// ============================ helpers ============================
#define CP_ASYNC16(dst, src) \
    asm volatile("cp.async.cg.shared.global [%0], [%1], 16;" :: "r"(dst), "l"(src) : "memory")
#define CP_ASYNC_COMMIT() asm volatile("cp.async.commit_group;" ::: "memory")
#define CP_ASYNC_WAIT0()  asm volatile("cp.async.wait_group 0;" ::: "memory")

__device__ __forceinline__ uint32_t lds32(uint32_t addr) {
    uint32_t v;
    asm volatile("ld.shared.b32 %0, [%1];" : "=r"(v) : "r"(addr));
    return v;
}

__device__ __forceinline__ void mma16816(float* d, const uint32_t* a, const uint32_t* b) {
    asm volatile(
        "mma.sync.aligned.m16n8k16.row.col.f32.bf16.bf16.f32 "
        "{%0,%1,%2,%3}, {%4,%5,%6,%7}, {%8,%9}, {%0,%1,%2,%3};"
        : "+f"(d[0]), "+f"(d[1]), "+f"(d[2]), "+f"(d[3])
        : "r"(a[0]), "r"(a[1]), "r"(a[2]), "r"(a[3]), "r"(b[0]), "r"(b[1]));
}

// ============================ device scratch ============================
__device__ __align__(256) float g_Qf[SEQ * EMB];
__device__ __align__(256) float g_Kf[SEQ * EMB];
__device__ __align__(256) float g_Vf[SEQ * EMB];
__device__ __align__(256) float g_ctxf[SEQ * EMB];

__device__ __align__(256) __nv_bfloat16 g_xhi[SEQ * EMB],  g_xlo[SEQ * EMB];
__device__ __align__(256) __nv_bfloat16 g_Wqhi[EMB * EMB], g_Wqlo[EMB * EMB];
__device__ __align__(256) __nv_bfloat16 g_Wkhi[EMB * EMB], g_Wklo[EMB * EMB];
__device__ __align__(256) __nv_bfloat16 g_Wvhi[EMB * EMB], g_Wvlo[EMB * EMB];
__device__ __align__(256) __nv_bfloat16 g_Wohi[EMB * EMB], g_Wolo[EMB * EMB];
__device__ __align__(256) __nv_bfloat16 g_Qhi[SEQ * EMB],  g_Qlo[SEQ * EMB];   // [NH][SEQ][HD]
__device__ __align__(256) __nv_bfloat16 g_Khi[SEQ * EMB],  g_Klo[SEQ * EMB];   // [NH][SEQ][HD]
__device__ __align__(256) __nv_bfloat16 g_Vthi[EMB * SEQ], g_Vtlo[EMB * SEQ];  // V^T [EMB][SEQ]
__device__ __align__(256) __nv_bfloat16 g_chi[SEQ * EMB],  g_clo[SEQ * EMB];
__device__ __align__(256) __nv_bfloat16 g_Phi[(size_t)NH * SEQ * SEQ];
__device__ __align__(256) __nv_bfloat16 g_Plo[(size_t)NH * SEQ * SEQ];

// ============================ split / pack kernels ============================
__global__ __launch_bounds__(256)
void split_pair(const float* __restrict__ src, __nv_bfloat16* __restrict__ hi,
                __nv_bfloat16* __restrict__ lo, int n)
{
    int i = blockIdx.x * 256 + threadIdx.x;
    if (i < n) {
        float v = src[i];
        __nv_bfloat16 h = __float2bfloat16(v);
        hi[i] = h;
        lo[i] = __float2bfloat16(v - __bfloat162float(h));
    }
}

// Q/K [SEQ][EMB] -> packed [NH][SEQ][HD] hi/lo
__global__ __launch_bounds__(256)
void split_qk(const float* __restrict__ src, __nv_bfloat16* __restrict__ hi,
              __nv_bfloat16* __restrict__ lo)
{
    int i = blockIdx.x * 256 + threadIdx.x;
    int d = i & 63;
    int s = (i >> 6) & 2047;
    int h = i >> 17;
    float v = src[s * EMB + h * 64 + d];
    __nv_bfloat16 hh = __float2bfloat16(v);
    hi[i] = hh;
    lo[i] = __float2bfloat16(v - __bfloat162float(hh));
}

// V [SEQ][EMB] -> V^T [EMB][SEQ] hi/lo
__global__ __launch_bounds__(256)
void transpose_split(const float* __restrict__ V, __nv_bfloat16* __restrict__ hi,
                     __nv_bfloat16* __restrict__ lo)
{
    __shared__ float t[32][33];
    int e0 = blockIdx.x * 32, s0 = blockIdx.y * 32;
    int tx = threadIdx.x, ty = threadIdx.y;  // 32 x 8
#pragma unroll
    for (int i = 0; i < 32; i += 8)
        t[ty + i][tx] = V[(size_t)(s0 + ty + i) * EMB + e0 + tx];
    __syncthreads();
#pragma unroll
    for (int i = 0; i < 32; i += 8) {
        float v = t[tx][ty + i];
        size_t o = (size_t)(e0 + ty + i) * SEQ + s0 + tx;
        __nv_bfloat16 hh = __float2bfloat16(v);
        hi[o] = hh;
        lo[o] = __float2bfloat16(v - __bfloat162float(hh));
    }
}

// ============================ softmax (+ bf16 split planes) ============================
__global__ __launch_bounds__(256)
void softmax_split(float* __restrict__ attn, __nv_bfloat16* __restrict__ phi,
                   __nv_bfloat16* __restrict__ plo)
{
    const size_t row = blockIdx.x;
    float* p = attn + row * (size_t)SEQ;
    const int tid = threadIdx.x;

    float v[8];
    float m = -1e30f;
#pragma unroll
    for (int i = 0; i < 8; i++) {
        v[i] = p[tid + i * 256];
        m = fmaxf(m, v[i]);
    }

    __shared__ float red[32];
#pragma unroll
    for (int o = 16; o > 0; o >>= 1)
        m = fmaxf(m, __shfl_xor_sync(0xffffffffu, m, o));
    if ((tid & 31) == 0) red[tid >> 5] = m;
    __syncthreads();
    if (tid < 32) {
        float t = (tid < 8) ? red[tid] : -1e30f;
#pragma unroll
        for (int o = 4; o > 0; o >>= 1)
            t = fmaxf(t, __shfl_xor_sync(0xffffffffu, t, o));
        if (tid == 0) red[0] = t;
    }
    __syncthreads();
    const float mx = red[0];

    float s = 0.f;
#pragma unroll
    for (int i = 0; i < 8; i++) {
        v[i] = expf(v[i] - mx);
        s += v[i];
    }
    __syncthreads();
#pragma unroll
    for (int o = 16; o > 0; o >>= 1)
        s += __shfl_xor_sync(0xffffffffu, s, o);
    if ((tid & 31) == 0) red[tid >> 5] = s;
    __syncthreads();
    if (tid < 32) {
        float t = (tid < 8) ? red[tid] : 0.f;
#pragma unroll
        for (int o = 4; o > 0; o >>= 1)
            t += __shfl_xor_sync(0xffffffffu, t, o);
        if (tid == 0) red[0] = t;
    }
    __syncthreads();
    const float inv = 1.0f / red[0];

#pragma unroll
    for (int i = 0; i < 8; i++) {
        float f = v[i] * inv;
        size_t idx = row * (size_t)SEQ + tid + i * 256;
        p[tid + i * 256] = f;
        __nv_bfloat16 hh = __float2bfloat16(f);
        phi[idx] = hh;
        plo[idx] = __float2bfloat16(f - __bfloat162float(hh));
    }
}

// ============================ split-bf16 HMMA NT GEMM ============================
// C[M,N] = alpha * (A @ B^T) + bias (fp32), A/B given as bf16 hi/lo planes.
// A: [M,Ktot] rows (stride Ktot), B: [N,Ktot] rows (stride Ktot).
// Block tile 128 x BN, BK = 32, double-buffered cp.async.
// 8 warps: 4 (m) x 2 (n); warp tile 32 x BN/2; mma m16n8k16 x 3 split products.
template <int BN>
__global__ __launch_bounds__(256, 1)
void mma_gemm(const __nv_bfloat16* __restrict__ Ahi, const __nv_bfloat16* __restrict__ Alo,
              const __nv_bfloat16* __restrict__ Bhi, const __nv_bfloat16* __restrict__ Blo,
              float* __restrict__ C, const float* __restrict__ bias,
              int Ktot, int ldc, long long sAz, long long sBz, long long sCz, float alpha)
{
    constexpr int NT = BN / 16;              // n8 tiles per warp
    constexpr int APLANE = 128 * 40 * 2;     // bytes, pad to 40 elems/row
    constexpr int BPLANE = BN * 40 * 2;
    constexpr int STAGE  = 2 * APLANE + 2 * BPLANE;

    extern __shared__ char dsm[];
    const uint32_t smem0 = (uint32_t)__cvta_generic_to_shared(dsm);

    const int tid  = threadIdx.x;
    const int wid  = tid >> 5;
    const int lane = tid & 31;
    const int wm = wid & 3;         // warp m index (0..3)
    const int wn = wid >> 2;        // warp n index (0..1)
    const int rl = lane >> 2;       // 0..7
    const int clb = (lane & 3) * 4; // byte offset of k-pair within row

    Ahi += blockIdx.z * sAz; Alo += blockIdx.z * sAz;
    Bhi += blockIdx.z * sBz; Blo += blockIdx.z * sBz;
    C   += blockIdx.z * sCz;
    const int row0 = blockIdx.y * 128;
    const int col0 = blockIdx.x * BN;

    float acc[2][NT][4];
#pragma unroll
    for (int mi = 0; mi < 2; mi++)
#pragma unroll
        for (int ni = 0; ni < NT; ni++)
#pragma unroll
            for (int j = 0; j < 4; j++) acc[mi][ni][j] = 0.f;

    const int NC = Ktot >> 5;   // chunks of 32

    auto load_chunk = [&](int c, int s) {
        const uint32_t sb = smem0 + s * STAGE;
        // A: 128 rows x 32 k x 2 planes -> 1024 x 16B
        for (int i = tid; i < 1024; i += 256) {
            int pl = i >> 9;
            int rem = i & 511;
            int r = rem >> 2, g = rem & 3;
            const __nv_bfloat16* src =
                (pl ? Alo : Ahi) + (size_t)(row0 + r) * Ktot + c * 32 + g * 8;
            CP_ASYNC16(sb + pl * APLANE + r * 80 + g * 16, src);
        }
        // B: BN rows x 32 k x 2 planes
        for (int i = tid; i < BN * 8; i += 256) {
            int pl = (i >= BN * 4) ? 1 : 0;
            int j = i - pl * BN * 4;
            int r = j >> 2, g = j & 3;
            const __nv_bfloat16* src =
                (pl ? Blo : Bhi) + (size_t)(col0 + r) * Ktot + c * 32 + g * 8;
            CP_ASYNC16(sb + 2 * APLANE + pl * BPLANE + r * 80 + g * 16, src);
        }
        CP_ASYNC_COMMIT();
    };

    auto compute = [&](int s) {
        const uint32_t sb = smem0 + s * STAGE;
        const uint32_t aBase = sb + (wm * 32 + rl) * 80 + clb;
        const uint32_t bBase = sb + 2 * APLANE + (wn * (BN / 2) + rl) * 80 + clb;
#pragma unroll
        for (int kk = 0; kk < 2; kk++) {
            uint32_t a[2][2][4];   // [plane][mi][reg]
#pragma unroll
            for (int pl = 0; pl < 2; pl++)
#pragma unroll
                for (int mi = 0; mi < 2; mi++) {
                    uint32_t o = aBase + pl * APLANE + mi * 16 * 80 + kk * 32;
                    a[pl][mi][0] = lds32(o);
                    a[pl][mi][1] = lds32(o + 8 * 80);
                    a[pl][mi][2] = lds32(o + 16);
                    a[pl][mi][3] = lds32(o + 8 * 80 + 16);
                }
            uint32_t b[2][NT][2];
#pragma unroll
            for (int pl = 0; pl < 2; pl++)
#pragma unroll
                for (int ni = 0; ni < NT; ni++) {
                    uint32_t o = bBase + pl * BPLANE + ni * 8 * 80 + kk * 32;
                    b[pl][ni][0] = lds32(o);
                    b[pl][ni][1] = lds32(o + 16);
                }
#pragma unroll
            for (int mi = 0; mi < 2; mi++)
#pragma unroll
                for (int ni = 0; ni < NT; ni++) {
                    mma16816(acc[mi][ni], a[0][mi], b[0][ni]);
                    mma16816(acc[mi][ni], a[0][mi], b[1][ni]);
                    mma16816(acc[mi][ni], a[1][mi], b[0][ni]);
                }
        }
    };

    load_chunk(0, 0);
    for (int c = 0; c < NC; c++) {
        CP_ASYNC_WAIT0();
        __syncthreads();
        if (c + 1 < NC) load_chunk(c + 1, (c + 1) & 1);
        compute(c & 1);
        __syncthreads();
    }

    // epilogue
    const int cl = (lane & 3) * 2;
#pragma unroll
    for (int mi = 0; mi < 2; mi++) {
        const int r = row0 + wm * 32 + mi * 16 + rl;
#pragma unroll
        for (int ni = 0; ni < NT; ni++) {
            const int cc = col0 + wn * (BN / 2) + ni * 8 + cl;
            float b0 = 0.f, b1 = 0.f;
            if (bias) { b0 = bias[cc]; b1 = bias[cc + 1]; }
            float2 v0 = { acc[mi][ni][0] * alpha + b0, acc[mi][ni][1] * alpha + b1 };
            float2 v1 = { acc[mi][ni][2] * alpha + b0, acc[mi][ni][3] * alpha + b1 };
            *(float2*)(C + (size_t)r * ldc + cc) = v0;
            *(float2*)(C + (size_t)(r + 8) * ldc + cc) = v1;
        }
    }
}

// ============================ host launch ============================
static constexpr int APL = 128 * 40 * 2;
static constexpr int SMEM128 = 2 * (2 * APL + 2 * 128 * 40 * 2);  // 81920
static constexpr int SMEM64  = 2 * (2 * APL + 2 * 64 * 40 * 2);   // 61440

extern "C" void kernel_launch(void* const* d_in, const int* in_sizes, int n_in,
                              void* d_out, int out_size)
{
    const float* x  = (const float*)d_in[0];
    const float* Wq = (const float*)d_in[1];
    const float* bq = (const float*)d_in[2];
    const float* Wk = (const float*)d_in[3];
    const float* bk = (const float*)d_in[4];
    const float* Wv = (const float*)d_in[5];
    const float* bv = (const float*)d_in[6];
    const float* Wo = (const float*)d_in[7];
    const float* bo = (const float*)d_in[8];

    float* out  = (float*)d_out;
    float* attn = out + (size_t)SEQ * EMB;

#define SYM(p, s) void* p##_v; cudaGetSymbolAddress(&p##_v, s);
    SYM(Qf, g_Qf) SYM(Kf, g_Kf) SYM(Vf, g_Vf) SYM(ctxf, g_ctxf)
    SYM(xhi, g_xhi) SYM(xlo, g_xlo)
    SYM(Wqhi, g_Wqhi) SYM(Wqlo, g_Wqlo) SYM(Wkhi, g_Wkhi) SYM(Wklo, g_Wklo)
    SYM(Wvhi, g_Wvhi) SYM(Wvlo, g_Wvlo) SYM(Wohi, g_Wohi) SYM(Wolo, g_Wolo)
    SYM(Qhi, g_Qhi) SYM(Qlo, g_Qlo) SYM(Khi, g_Khi) SYM(Klo, g_Klo)
    SYM(Vthi, g_Vthi) SYM(Vtlo, g_Vtlo)
    SYM(chi, g_chi) SYM(clo, g_clo)
    SYM(Phi, g_Phi) SYM(Plo, g_Plo)
#undef SYM
#define BF(p) ((__nv_bfloat16*)p##_v)
#define FL(p) ((float*)p##_v)

    cudaFuncSetAttribute(mma_gemm<128>, cudaFuncAttributeMaxDynamicSharedMemorySize, SMEM128);
    cudaFuncSetAttribute(mma_gemm<64>,  cudaFuncAttributeMaxDynamicSharedMemorySize, SMEM64);

    const int nSE = SEQ * EMB;
    const int nEE = EMB * EMB;

    // split inputs
    split_pair<<<nSE / 256, 256>>>(x,  BF(xhi),  BF(xlo),  nSE);
    split_pair<<<nEE / 256, 256>>>(Wq, BF(Wqhi), BF(Wqlo), nEE);
    split_pair<<<nEE / 256, 256>>>(Wk, BF(Wkhi), BF(Wklo), nEE);
    split_pair<<<nEE / 256, 256>>>(Wv, BF(Wvhi), BF(Wvlo), nEE);
    split_pair<<<nEE / 256, 256>>>(Wo, BF(Wohi), BF(Wolo), nEE);

    // Q/K/V projections
    dim3 gProj(EMB / 128, SEQ / 128, 1);
    mma_gemm<128><<<gProj, 256, SMEM128>>>(BF(xhi), BF(xlo), BF(Wqhi), BF(Wqlo),
                                           FL(Qf), bq, EMB, EMB, 0, 0, 0, 1.0f);
    mma_gemm<128><<<gProj, 256, SMEM128>>>(BF(xhi), BF(xlo), BF(Wkhi), BF(Wklo),
                                           FL(Kf), bk, EMB, EMB, 0, 0, 0, 1.0f);
    mma_gemm<128><<<gProj, 256, SMEM128>>>(BF(xhi), BF(xlo), BF(Wvhi), BF(Wvlo),
                                           FL(Vf), bv, EMB, EMB, 0, 0, 0, 1.0f);

    // pack per-head operands
    split_qk<<<nSE / 256, 256>>>(FL(Qf), BF(Qhi), BF(Qlo));
    split_qk<<<nSE / 256, 256>>>(FL(Kf), BF(Khi), BF(Klo));
    transpose_split<<<dim3(EMB / 32, SEQ / 32), dim3(32, 8)>>>(FL(Vf), BF(Vthi), BF(Vtlo));

    // scores[h] = (Q_h @ K_h^T) / 32
    dim3 gScore(SEQ / 128, SEQ / 128, NH);
    mma_gemm<128><<<gScore, 256, SMEM128>>>(BF(Qhi), BF(Qlo), BF(Khi), BF(Klo),
                                            attn, nullptr, HD, SEQ,
                                            (long long)SEQ * HD, (long long)SEQ * HD,
                                            (long long)SEQ * SEQ, 0.03125f);

    // softmax in place + bf16 split planes
    softmax_split<<<NH * SEQ, 256>>>(attn, BF(Phi), BF(Plo));

    // ctx[h] = P_h @ V_h (NT with B = V^T rows of head h)
    dim3 gCtx(1, SEQ / 128, NH);
    mma_gemm<64><<<gCtx, 256, SMEM64>>>(BF(Phi), BF(Plo), BF(Vthi), BF(Vtlo),
                                        FL(ctxf), nullptr, SEQ, EMB,
                                        (long long)SEQ * SEQ, (long long)HD * SEQ,
                                        HD, 1.0f);

    // out = ctx @ Wo^T + bo
    split_pair<<<nSE / 256, 256>>>(FL(ctxf), BF(chi), BF(clo), nSE);
    mma_gemm<128><<<gProj, 256, SMEM128>>>(BF(chi), BF(clo), BF(Wohi), BF(Wolo),
                                           out, bo, EMB, EMB, 0, 0, 0, 1.0f);
#undef BF
#undef FL
}

// round 5
// speedup vs baseline: 2.4833x; 1.0822x over previous
#include <cuda_runtime.h>
#include <cuda_bf16.h>
#include <cstdint>
#include <math.h>

#define SEQ 2048
#define EMB 1024
#define NH  16
#define HD  64

// ============================ helpers ============================
#define CP_ASYNC16(dst, src) \
    asm volatile("cp.async.cg.shared.global [%0], [%1], 16;" :: "r"(dst), "l"(src) : "memory")
#define CP_ASYNC_COMMIT() asm volatile("cp.async.commit_group;" ::: "memory")
#define CP_ASYNC_WAIT0()  asm volatile("cp.async.wait_group 0;" ::: "memory")

#define LDSM4(r, addr) \
    asm volatile("ldmatrix.sync.aligned.m8n8.x4.shared.b16 {%0,%1,%2,%3}, [%4];" \
        : "=r"((r)[0]), "=r"((r)[1]), "=r"((r)[2]), "=r"((r)[3]) : "r"(addr))

__device__ __forceinline__ void mma16816(float* d, const uint32_t* a, const uint32_t* b) {
    asm volatile(
        "mma.sync.aligned.m16n8k16.row.col.f32.bf16.bf16.f32 "
        "{%0,%1,%2,%3}, {%4,%5,%6,%7}, {%8,%9}, {%0,%1,%2,%3};"
        : "+f"(d[0]), "+f"(d[1]), "+f"(d[2]), "+f"(d[3])
        : "r"(a[0]), "r"(a[1]), "r"(a[2]), "r"(a[3]), "r"(b[0]), "r"(b[1]));
}

__device__ __forceinline__ uint32_t pack2(float x, float y) {
    __nv_bfloat162 t = __floats2bfloat162_rn(x, y);
    return *(uint32_t*)&t;
}

// ============================ device scratch ============================
__device__ __align__(256) float g_Vf[SEQ * EMB];

__device__ __align__(256) __nv_bfloat16 g_xhi[SEQ * EMB],  g_xlo[SEQ * EMB];
__device__ __align__(256) __nv_bfloat16 g_Wqhi[EMB * EMB], g_Wqlo[EMB * EMB];
__device__ __align__(256) __nv_bfloat16 g_Wkhi[EMB * EMB], g_Wklo[EMB * EMB];
__device__ __align__(256) __nv_bfloat16 g_Wvhi[EMB * EMB], g_Wvlo[EMB * EMB];
__device__ __align__(256) __nv_bfloat16 g_Wohi[EMB * EMB], g_Wolo[EMB * EMB];
__device__ __align__(256) __nv_bfloat16 g_Qhi[SEQ * EMB],  g_Qlo[SEQ * EMB];   // [NH][SEQ][HD]
__device__ __align__(256) __nv_bfloat16 g_Khi[SEQ * EMB],  g_Klo[SEQ * EMB];   // [NH][SEQ][HD]
__device__ __align__(256) __nv_bfloat16 g_Vthi[EMB * SEQ], g_Vtlo[EMB * SEQ];  // V^T [EMB][SEQ]
__device__ __align__(256) __nv_bfloat16 g_chi[SEQ * EMB],  g_clo[SEQ * EMB];   // ctx [SEQ][EMB]

// ============================ split / transpose ============================
__global__ __launch_bounds__(256)
void split_pair(const float* __restrict__ src, __nv_bfloat16* __restrict__ hi,
                __nv_bfloat16* __restrict__ lo, int n)
{
    int i = blockIdx.x * 256 + threadIdx.x;
    if (i < n) {
        float v = src[i];
        __nv_bfloat16 h = __float2bfloat16(v);
        hi[i] = h;
        lo[i] = __float2bfloat16(v - __bfloat162float(h));
    }
}

// V [SEQ][EMB] -> V^T [EMB][SEQ] hi/lo
__global__ __launch_bounds__(256)
void transpose_split(const float* __restrict__ V, __nv_bfloat16* __restrict__ hi,
                     __nv_bfloat16* __restrict__ lo)
{
    __shared__ float t[32][33];
    int e0 = blockIdx.x * 32, s0 = blockIdx.y * 32;
    int tx = threadIdx.x, ty = threadIdx.y;  // 32 x 8
#pragma unroll
    for (int i = 0; i < 32; i += 8)
        t[ty + i][tx] = V[(size_t)(s0 + ty + i) * EMB + e0 + tx];
    __syncthreads();
#pragma unroll
    for (int i = 0; i < 32; i += 8) {
        float v = t[tx][ty + i];
        size_t o = (size_t)(e0 + ty + i) * SEQ + s0 + tx;
        __nv_bfloat16 hh = __float2bfloat16(v);
        hi[o] = hh;
        lo[o] = __float2bfloat16(v - __bfloat162float(hh));
    }
}

// ============================ softmax (in place) ============================
__global__ __launch_bounds__(256)
void softmax_rows(float* __restrict__ attn)
{
    const size_t row = blockIdx.x;
    float* p = attn + row * (size_t)SEQ;
    const int tid = threadIdx.x;

    float v[8];
    float m = -1e30f;
#pragma unroll
    for (int i = 0; i < 8; i++) {
        v[i] = p[tid + i * 256];
        m = fmaxf(m, v[i]);
    }

    __shared__ float red[32];
#pragma unroll
    for (int o = 16; o > 0; o >>= 1)
        m = fmaxf(m, __shfl_xor_sync(0xffffffffu, m, o));
    if ((tid & 31) == 0) red[tid >> 5] = m;
    __syncthreads();
    if (tid < 32) {
        float t = (tid < 8) ? red[tid] : -1e30f;
#pragma unroll
        for (int o = 4; o > 0; o >>= 1)
            t = fmaxf(t, __shfl_xor_sync(0xffffffffu, t, o));
        if (tid == 0) red[0] = t;
    }
    __syncthreads();
    const float mx = red[0];

    float s = 0.f;
#pragma unroll
    for (int i = 0; i < 8; i++) {
        v[i] = expf(v[i] - mx);
        s += v[i];
    }
    __syncthreads();
#pragma unroll
    for (int o = 16; o > 0; o >>= 1)
        s += __shfl_xor_sync(0xffffffffu, s, o);
    if ((tid & 31) == 0) red[tid >> 5] = s;
    __syncthreads();
    if (tid < 32) {
        float t = (tid < 8) ? red[tid] : 0.f;
#pragma unroll
        for (int o = 4; o > 0; o >>= 1)
            t += __shfl_xor_sync(0xffffffffu, t, o);
        if (tid == 0) red[0] = t;
    }
    __syncthreads();
    const float inv = 1.0f / red[0];

#pragma unroll
    for (int i = 0; i < 8; i++)
        p[tid + i * 256] = v[i] * inv;
}

// ============================ split-bf16 HMMA NT GEMM ============================
// C = alpha * (A @ B^T) + bias.
// AFP32=0: A given as bf16 hi/lo planes (row stride Ktot).
// AFP32=1: A given as fp32 (row stride Ktot); loader makes hi/lo planes on the fly.
// mode 0: write fp32 C; mode 1: write bf16 hi/lo planes; mode 2: like 1 but packed
//         per-head output layout [NH][SEQ][HD] (col = h*64+d).
// Block tile 128 x BN, BK=32, double-buffered. 8 warps = 4(m) x 2(n).
template <int BN, int AFP32>
__global__ __launch_bounds__(256, 1)
void mma_gemm(const __nv_bfloat16* __restrict__ Ahi, const __nv_bfloat16* __restrict__ Alo,
              const float* __restrict__ Af,
              const __nv_bfloat16* __restrict__ Bhi, const __nv_bfloat16* __restrict__ Blo,
              float* __restrict__ C, __nv_bfloat16* __restrict__ Chi,
              __nv_bfloat16* __restrict__ Clo, const float* __restrict__ bias,
              int Ktot, int ldc, long long sAz, long long sBz, long long sCz,
              float alpha, int mode)
{
    constexpr int NT = BN / 16;
    constexpr int APLANE = 128 * 80;   // bytes (row = 40 bf16 = 80B)
    constexpr int BPLANE = BN * 80;
    constexpr int STAGE  = 2 * APLANE + 2 * BPLANE;

    extern __shared__ char dsm[];
    const uint32_t smem0 = (uint32_t)__cvta_generic_to_shared(dsm);

    const int tid  = threadIdx.x;
    const int wid  = tid >> 5;
    const int lane = tid & 31;
    const int wm = wid & 3;
    const int wn = wid >> 2;
    const int rl = lane >> 2;

    if (AFP32) Af += blockIdx.z * sAz;
    else { Ahi += blockIdx.z * sAz; Alo += blockIdx.z * sAz; }
    Bhi += blockIdx.z * sBz; Blo += blockIdx.z * sBz;
    const long long coff = blockIdx.z * sCz;
    const int row0 = blockIdx.y * 128;
    const int col0 = blockIdx.x * BN;

    float acc[2][NT][4];
#pragma unroll
    for (int mi = 0; mi < 2; mi++)
#pragma unroll
        for (int ni = 0; ni < NT; ni++)
#pragma unroll
            for (int j = 0; j < 4; j++) acc[mi][ni][j] = 0.f;

    const int NC = Ktot >> 5;

    auto load_B = [&](int c, int s) {
        const uint32_t sb = smem0 + s * STAGE + 2 * APLANE;
        for (int i = tid; i < BN * 8; i += 256) {
            int pl = (i >= BN * 4) ? 1 : 0;
            int j = i - pl * BN * 4;
            int r = j >> 2, g = j & 3;
            const __nv_bfloat16* src =
                (pl ? Blo : Bhi) + (size_t)(col0 + r) * Ktot + c * 32 + g * 8;
            CP_ASYNC16(sb + pl * BPLANE + r * 80 + g * 16, src);
        }
    };
    auto load_A_bf = [&](int c, int s) {
        const uint32_t sb = smem0 + s * STAGE;
        for (int i = tid; i < 1024; i += 256) {
            int pl = i >> 9;
            int rem = i & 511;
            int r = rem >> 2, g = rem & 3;
            const __nv_bfloat16* src =
                (pl ? Alo : Ahi) + (size_t)(row0 + r) * Ktot + c * 32 + g * 8;
            CP_ASYNC16(sb + pl * APLANE + r * 80 + g * 16, src);
        }
    };

    // fp32-A path registers
    float4 areg[4];
    const int ar = tid >> 1;          // 0..127
    const int aseg = (tid & 1) * 16;  // float col offset
    auto ldg_A = [&](int c) {
        const float* src = Af + (size_t)(row0 + ar) * Ktot + c * 32 + aseg;
#pragma unroll
        for (int i = 0; i < 4; i++) areg[i] = *(const float4*)(src + i * 4);
    };
    auto sts_A = [&](int s) {
        const uint32_t sb = smem0 + s * STAGE + ar * 80 + aseg * 2;
        uint4 hi4, lo4;
        uint32_t* h = (uint32_t*)&hi4;
        uint32_t* l = (uint32_t*)&lo4;
#pragma unroll
        for (int i = 0; i < 2; i++) {
            float4 v0 = areg[i * 2], v1 = areg[i * 2 + 1];
            h[0] = pack2(v0.x, v0.y); h[1] = pack2(v0.z, v0.w);
            h[2] = pack2(v1.x, v1.y); h[3] = pack2(v1.z, v1.w);
            __nv_bfloat162* hb = (__nv_bfloat162*)h;
            l[0] = pack2(v0.x - __low2float(hb[0]), v0.y - __high2float(hb[0]));
            l[1] = pack2(v0.z - __low2float(hb[1]), v0.w - __high2float(hb[1]));
            l[2] = pack2(v1.x - __low2float(hb[2]), v1.y - __high2float(hb[2]));
            l[3] = pack2(v1.z - __low2float(hb[3]), v1.w - __high2float(hb[3]));
            *(uint4*)(dsm + (sb - smem0) + i * 16) = hi4;
            *(uint4*)(dsm + (sb - smem0) + APLANE + i * 16) = lo4;
        }
    };

    auto compute = [&](int s) {
        const uint32_t sb = smem0 + s * STAGE;
        const int r16 = lane & 15, ah = lane >> 4;
        const uint32_t aAddr = sb + (wm * 32 + r16) * 80 + ah * 16;
        const int bp = lane >> 4, bh = (lane >> 3) & 1, br = lane & 7;
        const uint32_t bAddr = sb + 2 * APLANE + (wn * (BN / 2) + bp * 8 + br) * 80 + bh * 16;
#pragma unroll
        for (int kk = 0; kk < 2; kk++) {
            uint32_t a[2][2][4];
#pragma unroll
            for (int pl = 0; pl < 2; pl++)
#pragma unroll
                for (int mi = 0; mi < 2; mi++)
                    LDSM4(a[pl][mi], aAddr + pl * APLANE + mi * 16 * 80 + kk * 32);
            uint32_t b[2][NT][2];
#pragma unroll
            for (int pl = 0; pl < 2; pl++)
#pragma unroll
                for (int np = 0; np < NT / 2; np++) {
                    uint32_t r4[4];
                    LDSM4(r4, bAddr + pl * BPLANE + np * 16 * 80 + kk * 32);
                    b[pl][2 * np][0] = r4[0]; b[pl][2 * np][1] = r4[1];
                    b[pl][2 * np + 1][0] = r4[2]; b[pl][2 * np + 1][1] = r4[3];
                }
#pragma unroll
            for (int mi = 0; mi < 2; mi++)
#pragma unroll
                for (int ni = 0; ni < NT; ni++) {
                    mma16816(acc[mi][ni], a[0][mi], b[0][ni]);
                    mma16816(acc[mi][ni], a[0][mi], b[1][ni]);
                    mma16816(acc[mi][ni], a[1][mi], b[0][ni]);
                }
        }
    };

    if (AFP32) {
        ldg_A(0); load_B(0, 0); CP_ASYNC_COMMIT();
        sts_A(0);
        CP_ASYNC_WAIT0(); __syncthreads();
        for (int c = 0; c < NC; c++) {
            int s = c & 1;
            if (c + 1 < NC) { ldg_A(c + 1); load_B(c + 1, s ^ 1); CP_ASYNC_COMMIT(); }
            compute(s);
            if (c + 1 < NC) { sts_A(s ^ 1); CP_ASYNC_WAIT0(); __syncthreads(); }
        }
    } else {
        load_A_bf(0, 0); load_B(0, 0); CP_ASYNC_COMMIT();
        for (int c = 0; c < NC; c++) {
            CP_ASYNC_WAIT0();
            __syncthreads();
            if (c + 1 < NC) {
                load_A_bf(c + 1, (c + 1) & 1); load_B(c + 1, (c + 1) & 1);
                CP_ASYNC_COMMIT();
            }
            compute(c & 1);
            __syncthreads();
        }
    }

    // ---------------- epilogue ----------------
    const int cl = (lane & 3) * 2;
#pragma unroll
    for (int mi = 0; mi < 2; mi++) {
        const int r = row0 + wm * 32 + mi * 16 + rl;
#pragma unroll
        for (int ni = 0; ni < NT; ni++) {
            const int cc = col0 + wn * (BN / 2) + ni * 8 + cl;
            float b0 = 0.f, b1 = 0.f;
            if (bias) { b0 = bias[cc]; b1 = bias[cc + 1]; }
            float v00 = acc[mi][ni][0] * alpha + b0;
            float v01 = acc[mi][ni][1] * alpha + b1;
            float v10 = acc[mi][ni][2] * alpha + b0;
            float v11 = acc[mi][ni][3] * alpha + b1;
            if (mode == 0) {
                float* Cb = C + coff;
                *(float2*)(Cb + (size_t)r * ldc + cc) = make_float2(v00, v01);
                *(float2*)(Cb + (size_t)(r + 8) * ldc + cc) = make_float2(v10, v11);
            } else {
                size_t o0, o1;
                if (mode == 2) {
                    o0 = (size_t)(cc >> 6) * ((size_t)SEQ * 64) + (size_t)r * 64 + (cc & 63);
                    o1 = o0 + 8 * 64;
                } else {
                    o0 = coff + (size_t)r * ldc + cc;
                    o1 = coff + (size_t)(r + 8) * ldc + cc;
                }
                uint32_t h0 = pack2(v00, v01), h1 = pack2(v10, v11);
                __nv_bfloat162 hb0 = *(__nv_bfloat162*)&h0;
                __nv_bfloat162 hb1 = *(__nv_bfloat162*)&h1;
                uint32_t l0 = pack2(v00 - __low2float(hb0), v01 - __high2float(hb0));
                uint32_t l1 = pack2(v10 - __low2float(hb1), v11 - __high2float(hb1));
                *(uint32_t*)(Chi + o0) = h0;
                *(uint32_t*)(Chi + o1) = h1;
                *(uint32_t*)(Clo + o0) = l0;
                *(uint32_t*)(Clo + o1) = l1;
            }
        }
    }
}

// ============================ host launch ============================
static constexpr int APL = 128 * 80;
static constexpr int SMEM128 = 2 * (2 * APL + 2 * 128 * 80);  // 81920
static constexpr int SMEM64  = 2 * (2 * APL + 2 * 64 * 80);   // 61440

extern "C" void kernel_launch(void* const* d_in, const int* in_sizes, int n_in,
                              void* d_out, int out_size)
{
    const float* x  = (const float*)d_in[0];
    const float* Wq = (const float*)d_in[1];
    const float* bq = (const float*)d_in[2];
    const float* Wk = (const float*)d_in[3];
    const float* bk = (const float*)d_in[4];
    const float* Wv = (const float*)d_in[5];
    const float* bv = (const float*)d_in[6];
    const float* Wo = (const float*)d_in[7];
    const float* bo = (const float*)d_in[8];

    float* out  = (float*)d_out;
    float* attn = out + (size_t)SEQ * EMB;

#define SYM(p, s) void* p##_v; cudaGetSymbolAddress(&p##_v, s);
    SYM(Vf, g_Vf)
    SYM(xhi, g_xhi) SYM(xlo, g_xlo)
    SYM(Wqhi, g_Wqhi) SYM(Wqlo, g_Wqlo) SYM(Wkhi, g_Wkhi) SYM(Wklo, g_Wklo)
    SYM(Wvhi, g_Wvhi) SYM(Wvlo, g_Wvlo) SYM(Wohi, g_Wohi) SYM(Wolo, g_Wolo)
    SYM(Qhi, g_Qhi) SYM(Qlo, g_Qlo) SYM(Khi, g_Khi) SYM(Klo, g_Klo)
    SYM(Vthi, g_Vthi) SYM(Vtlo, g_Vtlo)
    SYM(chi, g_chi) SYM(clo, g_clo)
#undef SYM
#define BF(p) ((__nv_bfloat16*)p##_v)
#define FL(p) ((float*)p##_v)

    cudaFuncSetAttribute(mma_gemm<128, 0>, cudaFuncAttributeMaxDynamicSharedMemorySize, SMEM128);
    cudaFuncSetAttribute(mma_gemm<64, 1>,  cudaFuncAttributeMaxDynamicSharedMemorySize, SMEM64);

    const int nSE = SEQ * EMB;
    const int nEE = EMB * EMB;

    // split inputs
    split_pair<<<nSE / 256, 256>>>(x,  BF(xhi),  BF(xlo),  nSE);
    split_pair<<<nEE / 256, 256>>>(Wq, BF(Wqhi), BF(Wqlo), nEE);
    split_pair<<<nEE / 256, 256>>>(Wk, BF(Wkhi), BF(Wklo), nEE);
    split_pair<<<nEE / 256, 256>>>(Wv, BF(Wvhi), BF(Wvlo), nEE);
    split_pair<<<nEE / 256, 256>>>(Wo, BF(Wohi), BF(Wolo), nEE);

    dim3 gProj(EMB / 128, SEQ / 128, 1);
    // Q/K projections: write split packed-head planes directly (mode 2)
    mma_gemm<128, 0><<<gProj, 256, SMEM128>>>(BF(xhi), BF(xlo), nullptr,
        BF(Wqhi), BF(Wqlo), nullptr, BF(Qhi), BF(Qlo), bq,
        EMB, EMB, 0, 0, 0, 1.0f, 2);
    mma_gemm<128, 0><<<gProj, 256, SMEM128>>>(BF(xhi), BF(xlo), nullptr,
        BF(Wkhi), BF(Wklo), nullptr, BF(Khi), BF(Klo), bk,
        EMB, EMB, 0, 0, 0, 1.0f, 2);
    // V projection: fp32 (mode 0), then transpose+split
    mma_gemm<128, 0><<<gProj, 256, SMEM128>>>(BF(xhi), BF(xlo), nullptr,
        BF(Wvhi), BF(Wvlo), FL(Vf), nullptr, nullptr, bv,
        EMB, EMB, 0, 0, 0, 1.0f, 0);
    transpose_split<<<dim3(EMB / 32, SEQ / 32), dim3(32, 8)>>>(FL(Vf), BF(Vthi), BF(Vtlo));

    // scores[h] = (Q_h @ K_h^T) / 32 -> attn (mode 0)
    dim3 gScore(SEQ / 128, SEQ / 128, NH);
    mma_gemm<128, 0><<<gScore, 256, SMEM128>>>(BF(Qhi), BF(Qlo), nullptr,
        BF(Khi), BF(Klo), attn, nullptr, nullptr, nullptr,
        HD, SEQ, (long long)SEQ * HD, (long long)SEQ * HD,
        (long long)SEQ * SEQ, 0.03125f, 0);

    // softmax in place
    softmax_rows<<<NH * SEQ, 256>>>(attn);

    // ctx[h] = P_h @ V_h; A = attn fp32 (converted in loader), out split chi/clo (mode 1)
    dim3 gCtx(1, SEQ / 128, NH);
    mma_gemm<64, 1><<<gCtx, 256, SMEM64>>>(nullptr, nullptr, attn,
        BF(Vthi), BF(Vtlo), nullptr, BF(chi), BF(clo), nullptr,
        SEQ, EMB, (long long)SEQ * SEQ, (long long)HD * SEQ,
        HD, 1.0f, 1);

    // out = ctx @ Wo^T + bo (mode 0)
    mma_gemm<128, 0><<<gProj, 256, SMEM128>>>(BF(chi), BF(clo), nullptr,
        BF(Wohi), BF(Wolo), out, nullptr, nullptr, bo,
        EMB, EMB, 0, 0, 0, 1.0f, 0);
#undef BF
#undef FL
}

// round 6
// speedup vs baseline: 2.8355x; 1.1418x over previous
#include <cuda_runtime.h>
#include <cuda_bf16.h>
#include <cstdint>
#include <math.h>

#define SEQ 2048
#define EMB 1024
#define NH  16
#define HD  64

// ============================ helpers ============================
#define CP_ASYNC16(dst, src) \
    asm volatile("cp.async.cg.shared.global [%0], [%1], 16;" :: "r"(dst), "l"(src) : "memory")
#define CP_ASYNC_COMMIT() asm volatile("cp.async.commit_group;" ::: "memory")
#define CP_ASYNC_WAIT0()  asm volatile("cp.async.wait_group 0;" ::: "memory")
#define CP_ASYNC_WAIT1()  asm volatile("cp.async.wait_group 1;" ::: "memory")

#define LDSM4(r, addr) \
    asm volatile("ldmatrix.sync.aligned.m8n8.x4.shared.b16 {%0,%1,%2,%3}, [%4];" \
        : "=r"((r)[0]), "=r"((r)[1]), "=r"((r)[2]), "=r"((r)[3]) : "r"(addr))

__device__ __forceinline__ void mma16816(float* d, const uint32_t* a, const uint32_t* b) {
    asm volatile(
        "mma.sync.aligned.m16n8k16.row.col.f32.bf16.bf16.f32 "
        "{%0,%1,%2,%3}, {%4,%5,%6,%7}, {%8,%9}, {%0,%1,%2,%3};"
        : "+f"(d[0]), "+f"(d[1]), "+f"(d[2]), "+f"(d[3])
        : "r"(a[0]), "r"(a[1]), "r"(a[2]), "r"(a[3]), "r"(b[0]), "r"(b[1]));
}

__device__ __forceinline__ uint32_t pack2(float x, float y) {
    __nv_bfloat162 t = __floats2bfloat162_rn(x, y);
    return *(uint32_t*)&t;
}

// ============================ device scratch ============================
__device__ __align__(256) float g_Vf[SEQ * EMB];

__device__ __align__(256) __nv_bfloat16 g_xhi[SEQ * EMB],  g_xlo[SEQ * EMB];
__device__ __align__(256) __nv_bfloat16 g_Wqhi[EMB * EMB], g_Wqlo[EMB * EMB];
__device__ __align__(256) __nv_bfloat16 g_Wkhi[EMB * EMB], g_Wklo[EMB * EMB];
__device__ __align__(256) __nv_bfloat16 g_Wvhi[EMB * EMB], g_Wvlo[EMB * EMB];
__device__ __align__(256) __nv_bfloat16 g_Wohi[EMB * EMB], g_Wolo[EMB * EMB];
__device__ __align__(256) __nv_bfloat16 g_Qhi[SEQ * EMB],  g_Qlo[SEQ * EMB];   // [NH][SEQ][64]
__device__ __align__(256) __nv_bfloat16 g_Khi[SEQ * EMB],  g_Klo[SEQ * EMB];   // [NH][SEQ][64]
__device__ __align__(256) __nv_bfloat16 g_Vthi[EMB * SEQ], g_Vtlo[EMB * SEQ];  // V^T [EMB][SEQ]
__device__ __align__(256) __nv_bfloat16 g_chi[SEQ * EMB],  g_clo[SEQ * EMB];   // ctx [SEQ][EMB]

// ============================ split / transpose ============================
__global__ __launch_bounds__(256)
void split_pair(const float* __restrict__ src, __nv_bfloat16* __restrict__ hi,
                __nv_bfloat16* __restrict__ lo, int n)
{
    int i = blockIdx.x * 256 + threadIdx.x;
    if (i < n) {
        float v = src[i];
        __nv_bfloat16 h = __float2bfloat16(v);
        hi[i] = h;
        lo[i] = __float2bfloat16(v - __bfloat162float(h));
    }
}

__global__ __launch_bounds__(256)
void transpose_split(const float* __restrict__ V, __nv_bfloat16* __restrict__ hi,
                     __nv_bfloat16* __restrict__ lo)
{
    __shared__ float t[32][33];
    int e0 = blockIdx.x * 32, s0 = blockIdx.y * 32;
    int tx = threadIdx.x, ty = threadIdx.y;  // 32 x 8
#pragma unroll
    for (int i = 0; i < 32; i += 8)
        t[ty + i][tx] = V[(size_t)(s0 + ty + i) * EMB + e0 + tx];
    __syncthreads();
#pragma unroll
    for (int i = 0; i < 32; i += 8) {
        float v = t[tx][ty + i];
        size_t o = (size_t)(e0 + ty + i) * SEQ + s0 + tx;
        __nv_bfloat16 hh = __float2bfloat16(v);
        hi[o] = hh;
        lo[o] = __float2bfloat16(v - __bfloat162float(hh));
    }
}

// ============================ split-bf16 HMMA NT GEMM (projections) ============================
// C = (A @ B^T) + bias. A,B bf16 hi/lo planes, row stride Ktot.
// mode 0: fp32 C [M,ldc]; mode 2: bf16 hi/lo planes, packed [NH][SEQ][64] layout.
__global__ __launch_bounds__(256, 1)
void mma_gemm(const __nv_bfloat16* __restrict__ Ahi, const __nv_bfloat16* __restrict__ Alo,
              const __nv_bfloat16* __restrict__ Bhi, const __nv_bfloat16* __restrict__ Blo,
              float* __restrict__ C, __nv_bfloat16* __restrict__ Chi,
              __nv_bfloat16* __restrict__ Clo, const float* __restrict__ bias,
              int Ktot, int ldc, int mode)
{
    constexpr int BN = 128;
    constexpr int NT = BN / 16;
    constexpr int APLANE = 128 * 80;
    constexpr int BPLANE = BN * 80;
    constexpr int STAGE  = 2 * APLANE + 2 * BPLANE;

    extern __shared__ char dsm[];
    const uint32_t smem0 = (uint32_t)__cvta_generic_to_shared(dsm);

    const int tid  = threadIdx.x;
    const int wid  = tid >> 5;
    const int lane = tid & 31;
    const int wm = wid & 3;
    const int wn = wid >> 2;
    const int rl = lane >> 2;

    const int row0 = blockIdx.y * 128;
    const int col0 = blockIdx.x * BN;

    float acc[2][NT][4];
#pragma unroll
    for (int mi = 0; mi < 2; mi++)
#pragma unroll
        for (int ni = 0; ni < NT; ni++)
#pragma unroll
            for (int j = 0; j < 4; j++) acc[mi][ni][j] = 0.f;

    const int NC = Ktot >> 5;

    auto load_chunk = [&](int c, int s) {
        const uint32_t sb = smem0 + s * STAGE;
        for (int i = tid; i < 1024; i += 256) {
            int pl = i >> 9;
            int rem = i & 511;
            int r = rem >> 2, g = rem & 3;
            const __nv_bfloat16* src =
                (pl ? Alo : Ahi) + (size_t)(row0 + r) * Ktot + c * 32 + g * 8;
            CP_ASYNC16(sb + pl * APLANE + r * 80 + g * 16, src);
        }
        const uint32_t sbB = sb + 2 * APLANE;
        for (int i = tid; i < BN * 8; i += 256) {
            int pl = (i >= BN * 4) ? 1 : 0;
            int j = i - pl * BN * 4;
            int r = j >> 2, g = j & 3;
            const __nv_bfloat16* src =
                (pl ? Blo : Bhi) + (size_t)(col0 + r) * Ktot + c * 32 + g * 8;
            CP_ASYNC16(sbB + pl * BPLANE + r * 80 + g * 16, src);
        }
        CP_ASYNC_COMMIT();
    };

    auto compute = [&](int s) {
        const uint32_t sb = smem0 + s * STAGE;
        const int r16 = lane & 15, ah = lane >> 4;
        const uint32_t aAddr = sb + (wm * 32 + r16) * 80 + ah * 16;
        const int bp = lane >> 4, bh = (lane >> 3) & 1, br = lane & 7;
        const uint32_t bAddr = sb + 2 * APLANE + (wn * (BN / 2) + bp * 8 + br) * 80 + bh * 16;
#pragma unroll
        for (int kk = 0; kk < 2; kk++) {
            uint32_t a[2][2][4];
#pragma unroll
            for (int pl = 0; pl < 2; pl++)
#pragma unroll
                for (int mi = 0; mi < 2; mi++)
                    LDSM4(a[pl][mi], aAddr + pl * APLANE + mi * 16 * 80 + kk * 32);
            uint32_t b[2][NT][2];
#pragma unroll
            for (int pl = 0; pl < 2; pl++)
#pragma unroll
                for (int np = 0; np < NT / 2; np++) {
                    uint32_t r4[4];
                    LDSM4(r4, bAddr + pl * BPLANE + np * 16 * 80 + kk * 32);
                    b[pl][2 * np][0] = r4[0]; b[pl][2 * np][1] = r4[1];
                    b[pl][2 * np + 1][0] = r4[2]; b[pl][2 * np + 1][1] = r4[3];
                }
#pragma unroll
            for (int mi = 0; mi < 2; mi++)
#pragma unroll
                for (int ni = 0; ni < NT; ni++) {
                    mma16816(acc[mi][ni], a[0][mi], b[0][ni]);
                    mma16816(acc[mi][ni], a[0][mi], b[1][ni]);
                    mma16816(acc[mi][ni], a[1][mi], b[0][ni]);
                }
        }
    };

    load_chunk(0, 0);
    for (int c = 0; c < NC; c++) {
        CP_ASYNC_WAIT0();
        __syncthreads();
        if (c + 1 < NC) load_chunk(c + 1, (c + 1) & 1);
        compute(c & 1);
        __syncthreads();
    }

    const int cl = (lane & 3) * 2;
#pragma unroll
    for (int mi = 0; mi < 2; mi++) {
        const int r = row0 + wm * 32 + mi * 16 + rl;
#pragma unroll
        for (int ni = 0; ni < NT; ni++) {
            const int cc = col0 + wn * (BN / 2) + ni * 8 + cl;
            float b0 = 0.f, b1 = 0.f;
            if (bias) { b0 = bias[cc]; b1 = bias[cc + 1]; }
            float v00 = acc[mi][ni][0] + b0;
            float v01 = acc[mi][ni][1] + b1;
            float v10 = acc[mi][ni][2] + b0;
            float v11 = acc[mi][ni][3] + b1;
            if (mode == 0) {
                *(float2*)(C + (size_t)r * ldc + cc) = make_float2(v00, v01);
                *(float2*)(C + (size_t)(r + 8) * ldc + cc) = make_float2(v10, v11);
            } else {
                size_t o0 = (size_t)(cc >> 6) * ((size_t)SEQ * 64) + (size_t)r * 64 + (cc & 63);
                size_t o1 = o0 + 8 * 64;
                uint32_t h0 = pack2(v00, v01), h1 = pack2(v10, v11);
                __nv_bfloat162 hb0 = *(__nv_bfloat162*)&h0;
                __nv_bfloat162 hb1 = *(__nv_bfloat162*)&h1;
                uint32_t l0 = pack2(v00 - __low2float(hb0), v01 - __high2float(hb0));
                uint32_t l1 = pack2(v10 - __low2float(hb1), v11 - __high2float(hb1));
                *(uint32_t*)(Chi + o0) = h0;
                *(uint32_t*)(Chi + o1) = h1;
                *(uint32_t*)(Clo + o0) = l0;
                *(uint32_t*)(Clo + o1) = l1;
            }
        }
    }
}

// ============================ fused attention ============================
// Per CTA: head = blockIdx.y, 128 Q rows = blockIdx.x*128.
// Phase 1: S = Q@K^T/32, P=exp(S), rowsum, ctx += P@V (unnormalized).
// Phase 2: recompute S, write exp(S)*inv_sum to attn.
// smem: Q 2x18432 | K 2 stages x 36864 | V 2 stages x 34816 | red 1536
static constexpr int FA_OFF_K   = 36864;
static constexpr int FA_OFF_V   = 110592;
static constexpr int FA_OFF_RED = 180224;
static constexpr int FA_SMEM    = 181760;

__global__ __launch_bounds__(256, 1)
void attention_fused(const __nv_bfloat16* __restrict__ Qhi, const __nv_bfloat16* __restrict__ Qlo,
                     const __nv_bfloat16* __restrict__ Khi, const __nv_bfloat16* __restrict__ Klo,
                     const __nv_bfloat16* __restrict__ Vthi, const __nv_bfloat16* __restrict__ Vtlo,
                     float* __restrict__ attn,
                     __nv_bfloat16* __restrict__ chi, __nv_bfloat16* __restrict__ clo)
{
    extern __shared__ char sm[];
    const uint32_t sb = (uint32_t)__cvta_generic_to_shared(sm);

    const int tid  = threadIdx.x;
    const int lane = tid & 31, wid = tid >> 5;
    const int wm = wid & 3, wn = wid >> 2;
    const int rl = lane >> 2;
    const int h  = blockIdx.y;
    const int q0 = blockIdx.x * 128;

    auto loadQ = [&]() {
        for (int i = tid; i < 2048; i += 256) {
            int pl = i >> 10, rem = i & 1023, r = rem >> 3, g = rem & 7;
            const __nv_bfloat16* src = (pl ? Qlo : Qhi) + ((size_t)h * SEQ + q0 + r) * 64 + g * 8;
            CP_ASYNC16(sb + pl * 18432 + r * 144 + g * 16, src);
        }
    };
    auto loadK = [&](int j) {
        int st = (j & 1) * 36864;
        for (int i = tid; i < 2048; i += 256) {
            int pl = i >> 10, rem = i & 1023, r = rem >> 3, g = rem & 7;
            const __nv_bfloat16* src = (pl ? Klo : Khi) + ((size_t)h * SEQ + j * 128 + r) * 64 + g * 8;
            CP_ASYNC16(sb + FA_OFF_K + st + pl * 18432 + r * 144 + g * 16, src);
        }
    };
    auto loadV = [&](int j) {
        int st = (j & 1) * 34816;
        for (int i = tid; i < 2048; i += 256) {
            int pl = i >> 10, rem = i & 1023, d = rem >> 4, g = rem & 15;
            const __nv_bfloat16* src = (pl ? Vtlo : Vthi) + ((size_t)(h * 64 + d)) * SEQ + j * 128 + g * 8;
            CP_ASYNC16(sb + FA_OFF_V + st + pl * 17408 + d * 272 + g * 16, src);
        }
    };

    const uint32_t aBase  = sb + (wm * 32 + (lane & 15)) * 144 + (lane >> 4) * 16;
    const uint32_t bBaseK = sb + FA_OFF_K + (wn * 64 + (lane >> 4) * 8 + (lane & 7)) * 144
                            + ((lane >> 3) & 1) * 16;
    const uint32_t bBaseV = sb + FA_OFF_V + ((lane >> 4) * 8 + (lane & 7)) * 272
                            + ((lane >> 3) & 1) * 16 + wn * 128;

    float ctx[2][8][4];
#pragma unroll
    for (int mi = 0; mi < 2; mi++)
#pragma unroll
        for (int nd = 0; nd < 8; nd++)
#pragma unroll
            for (int j = 0; j < 4; j++) ctx[mi][nd][j] = 0.f;
    float rs[4] = {0.f, 0.f, 0.f, 0.f};

    // compute S tile (stage parity p01) into s[2][8][4], scaled by 1/32
    auto computeS = [&](int j, float s[2][8][4]) {
        const uint32_t kst = (uint32_t)((j & 1) * 36864);
#pragma unroll
        for (int kk = 0; kk < 4; kk++) {
            uint32_t a[2][2][4];
#pragma unroll
            for (int pl = 0; pl < 2; pl++)
#pragma unroll
                for (int mi = 0; mi < 2; mi++)
                    LDSM4(a[pl][mi], aBase + pl * 18432 + mi * 2304 + kk * 32);
            uint32_t bk[2][8][2];
#pragma unroll
            for (int pl = 0; pl < 2; pl++)
#pragma unroll
                for (int np = 0; np < 4; np++) {
                    uint32_t r4[4];
                    LDSM4(r4, bBaseK + kst + pl * 18432 + np * 2304 + kk * 32);
                    bk[pl][2 * np][0] = r4[0]; bk[pl][2 * np][1] = r4[1];
                    bk[pl][2 * np + 1][0] = r4[2]; bk[pl][2 * np + 1][1] = r4[3];
                }
#pragma unroll
            for (int mi = 0; mi < 2; mi++)
#pragma unroll
                for (int ni = 0; ni < 8; ni++) {
                    mma16816(s[mi][ni], a[0][mi], bk[0][ni]);
                    mma16816(s[mi][ni], a[0][mi], bk[1][ni]);
                    mma16816(s[mi][ni], a[1][mi], bk[0][ni]);
                }
        }
    };

    // ---------------- prologue ----------------
    loadQ(); loadK(0); loadV(0); CP_ASYNC_COMMIT();
    loadK(1); loadV(1); CP_ASYNC_COMMIT();

    // ---------------- phase 1 ----------------
    for (int j = 0; j < 16; j++) {
        if (j < 15) { CP_ASYNC_WAIT1(); } else { CP_ASYNC_WAIT0(); }
        __syncthreads();

        float s[2][8][4];
#pragma unroll
        for (int mi = 0; mi < 2; mi++)
#pragma unroll
            for (int ni = 0; ni < 8; ni++)
#pragma unroll
                for (int q = 0; q < 4; q++) s[mi][ni][q] = 0.f;
        computeS(j, s);

        // PV: per k16 step, build P frags from s, mma against V
        const uint32_t vst = (uint32_t)((j & 1) * 34816);
#pragma unroll
        for (int kk = 0; kk < 4; kk++) {
            uint32_t bv[2][8][2];
#pragma unroll
            for (int pl = 0; pl < 2; pl++)
#pragma unroll
                for (int np = 0; np < 4; np++) {
                    uint32_t r4[4];
                    LDSM4(r4, bBaseV + vst + pl * 17408 + np * 4352 + kk * 32);
                    bv[pl][2 * np][0] = r4[0]; bv[pl][2 * np][1] = r4[1];
                    bv[pl][2 * np + 1][0] = r4[2]; bv[pl][2 * np + 1][1] = r4[3];
                }
#pragma unroll
            for (int mi = 0; mi < 2; mi++) {
                const int e = 2 * kk, o = 2 * kk + 1;
                float pe0 = __expf(s[mi][e][0] * 0.03125f);
                float pe1 = __expf(s[mi][e][1] * 0.03125f);
                float pe2 = __expf(s[mi][e][2] * 0.03125f);
                float pe3 = __expf(s[mi][e][3] * 0.03125f);
                float po0 = __expf(s[mi][o][0] * 0.03125f);
                float po1 = __expf(s[mi][o][1] * 0.03125f);
                float po2 = __expf(s[mi][o][2] * 0.03125f);
                float po3 = __expf(s[mi][o][3] * 0.03125f);
                rs[mi * 2 + 0] += pe0 + pe1 + po0 + po1;
                rs[mi * 2 + 1] += pe2 + pe3 + po2 + po3;
                uint32_t ah[4], al[4];
                ah[0] = pack2(pe0, pe1); ah[1] = pack2(pe2, pe3);
                ah[2] = pack2(po0, po1); ah[3] = pack2(po2, po3);
                __nv_bfloat162* hb = (__nv_bfloat162*)ah;
                al[0] = pack2(pe0 - __low2float(hb[0]), pe1 - __high2float(hb[0]));
                al[1] = pack2(pe2 - __low2float(hb[1]), pe3 - __high2float(hb[1]));
                al[2] = pack2(po0 - __low2float(hb[2]), po1 - __high2float(hb[2]));
                al[3] = pack2(po2 - __low2float(hb[3]), po3 - __high2float(hb[3]));
#pragma unroll
                for (int nd = 0; nd < 8; nd++) {
                    mma16816(ctx[mi][nd], ah, bv[0][nd]);
                    mma16816(ctx[mi][nd], ah, bv[1][nd]);
                    mma16816(ctx[mi][nd], al, bv[0][nd]);
                }
            }
        }
        __syncthreads();
        if (j + 2 < 16) { loadK(j + 2); loadV(j + 2); CP_ASYNC_COMMIT(); }
    }

    // ---------------- rowsum reduce ----------------
#pragma unroll
    for (int i = 0; i < 4; i++) {
        rs[i] += __shfl_xor_sync(0xffffffffu, rs[i], 1);
        rs[i] += __shfl_xor_sync(0xffffffffu, rs[i], 2);
    }
    float* redp = (float*)(sm + FA_OFF_RED);            // [2][128]
    float* invp = (float*)(sm + FA_OFF_RED + 1024);     // [128]
    if ((lane & 3) == 0) {
#pragma unroll
        for (int mi = 0; mi < 2; mi++) {
            redp[wn * 128 + wm * 32 + mi * 16 + rl]     = rs[mi * 2 + 0];
            redp[wn * 128 + wm * 32 + mi * 16 + rl + 8] = rs[mi * 2 + 1];
        }
    }
    __syncthreads();
    if (tid < 128) invp[tid] = 1.0f / (redp[tid] + redp[128 + tid]);
    __syncthreads();

    // ---------------- ctx cross-warp reduce + write ----------------
    float* credp = (float*)(sm + FA_OFF_V);   // reuse V area: [128][64] fp32
    if (wn == 1) {
#pragma unroll
        for (int mi = 0; mi < 2; mi++) {
            const int r = wm * 32 + mi * 16 + rl;
#pragma unroll
            for (int nd = 0; nd < 8; nd++) {
                const int c = nd * 8 + (lane & 3) * 2;
                *(float2*)(credp + r * 64 + c)       = make_float2(ctx[mi][nd][0], ctx[mi][nd][1]);
                *(float2*)(credp + (r + 8) * 64 + c) = make_float2(ctx[mi][nd][2], ctx[mi][nd][3]);
            }
        }
    }
    __syncthreads();
    if (wn == 0) {
#pragma unroll
        for (int mi = 0; mi < 2; mi++) {
            const int r = wm * 32 + mi * 16 + rl;
            const float i0 = invp[r], i1 = invp[r + 8];
#pragma unroll
            for (int nd = 0; nd < 8; nd++) {
                const int c = nd * 8 + (lane & 3) * 2;
                float2 p0 = *(float2*)(credp + r * 64 + c);
                float2 p1 = *(float2*)(credp + (r + 8) * 64 + c);
                float v00 = (ctx[mi][nd][0] + p0.x) * i0;
                float v01 = (ctx[mi][nd][1] + p0.y) * i0;
                float v10 = (ctx[mi][nd][2] + p1.x) * i1;
                float v11 = (ctx[mi][nd][3] + p1.y) * i1;
                size_t o0 = (size_t)(q0 + r) * EMB + h * 64 + c;
                size_t o1 = (size_t)(q0 + r + 8) * EMB + h * 64 + c;
                uint32_t h0 = pack2(v00, v01), h1 = pack2(v10, v11);
                __nv_bfloat162 hb0 = *(__nv_bfloat162*)&h0;
                __nv_bfloat162 hb1 = *(__nv_bfloat162*)&h1;
                uint32_t l0 = pack2(v00 - __low2float(hb0), v01 - __high2float(hb0));
                uint32_t l1 = pack2(v10 - __low2float(hb1), v11 - __high2float(hb1));
                *(uint32_t*)(chi + o0) = h0;
                *(uint32_t*)(chi + o1) = h1;
                *(uint32_t*)(clo + o0) = l0;
                *(uint32_t*)(clo + o1) = l1;
            }
        }
    }
    __syncthreads();

    // ---------------- phase 2: recompute S, write normalized attn ----------------
    loadK(0); CP_ASYNC_COMMIT();
    loadK(1); CP_ASYNC_COMMIT();
    for (int j = 0; j < 16; j++) {
        if (j < 15) { CP_ASYNC_WAIT1(); } else { CP_ASYNC_WAIT0(); }
        __syncthreads();

        float s[2][8][4];
#pragma unroll
        for (int mi = 0; mi < 2; mi++)
#pragma unroll
            for (int ni = 0; ni < 8; ni++)
#pragma unroll
                for (int q = 0; q < 4; q++) s[mi][ni][q] = 0.f;
        computeS(j, s);

#pragma unroll
        for (int mi = 0; mi < 2; mi++) {
            const int r = wm * 32 + mi * 16 + rl;
            const float i0 = invp[r], i1 = invp[r + 8];
#pragma unroll
            for (int ni = 0; ni < 8; ni++) {
                const int c = wn * 64 + ni * 8 + (lane & 3) * 2;
                float2 v0 = make_float2(__expf(s[mi][ni][0] * 0.03125f) * i0,
                                        __expf(s[mi][ni][1] * 0.03125f) * i0);
                float2 v1 = make_float2(__expf(s[mi][ni][2] * 0.03125f) * i1,
                                        __expf(s[mi][ni][3] * 0.03125f) * i1);
                size_t base = ((size_t)h * SEQ + q0 + r) * (size_t)SEQ + j * 128 + c;
                *(float2*)(attn + base) = v0;
                *(float2*)(attn + base + 8 * SEQ) = v1;
            }
        }
        __syncthreads();
        if (j + 2 < 16) { loadK(j + 2); CP_ASYNC_COMMIT(); }
    }
}

// ============================ host launch ============================
static constexpr int APL = 128 * 80;
static constexpr int SMEM128 = 2 * (2 * APL + 2 * 128 * 80);  // 81920

extern "C" void kernel_launch(void* const* d_in, const int* in_sizes, int n_in,
                              void* d_out, int out_size)
{
    const float* x  = (const float*)d_in[0];
    const float* Wq = (const float*)d_in[1];
    const float* bq = (const float*)d_in[2];
    const float* Wk = (const float*)d_in[3];
    const float* bk = (const float*)d_in[4];
    const float* Wv = (const float*)d_in[5];
    const float* bv = (const float*)d_in[6];
    const float* Wo = (const float*)d_in[7];
    const float* bo = (const float*)d_in[8];

    float* out  = (float*)d_out;
    float* attn = out + (size_t)SEQ * EMB;

#define SYM(p, s) void* p##_v; cudaGetSymbolAddress(&p##_v, s);
    SYM(Vf, g_Vf)
    SYM(xhi, g_xhi) SYM(xlo, g_xlo)
    SYM(Wqhi, g_Wqhi) SYM(Wqlo, g_Wqlo) SYM(Wkhi, g_Wkhi) SYM(Wklo, g_Wklo)
    SYM(Wvhi, g_Wvhi) SYM(Wvlo, g_Wvlo) SYM(Wohi, g_Wohi) SYM(Wolo, g_Wolo)
    SYM(Qhi, g_Qhi) SYM(Qlo, g_Qlo) SYM(Khi, g_Khi) SYM(Klo, g_Klo)
    SYM(Vthi, g_Vthi) SYM(Vtlo, g_Vtlo)
    SYM(chi, g_chi) SYM(clo, g_clo)
#undef SYM
#define BF(p) ((__nv_bfloat16*)p##_v)
#define FL(p) ((float*)p##_v)

    cudaFuncSetAttribute(mma_gemm, cudaFuncAttributeMaxDynamicSharedMemorySize, SMEM128);
    cudaFuncSetAttribute(attention_fused, cudaFuncAttributeMaxDynamicSharedMemorySize, FA_SMEM);

    const int nSE = SEQ * EMB;
    const int nEE = EMB * EMB;

    split_pair<<<nSE / 256, 256>>>(x,  BF(xhi),  BF(xlo),  nSE);
    split_pair<<<nEE / 256, 256>>>(Wq, BF(Wqhi), BF(Wqlo), nEE);
    split_pair<<<nEE / 256, 256>>>(Wk, BF(Wkhi), BF(Wklo), nEE);
    split_pair<<<nEE / 256, 256>>>(Wv, BF(Wvhi), BF(Wvlo), nEE);
    split_pair<<<nEE / 256, 256>>>(Wo, BF(Wohi), BF(Wolo), nEE);

    dim3 gProj(EMB / 128, SEQ / 128, 1);
    // Q/K projections -> packed split planes (mode 2)
    mma_gemm<<<gProj, 256, SMEM128>>>(BF(xhi), BF(xlo), BF(Wqhi), BF(Wqlo),
                                      nullptr, BF(Qhi), BF(Qlo), bq, EMB, EMB, 2);
    mma_gemm<<<gProj, 256, SMEM128>>>(BF(xhi), BF(xlo), BF(Wkhi), BF(Wklo),
                                      nullptr, BF(Khi), BF(Klo), bk, EMB, EMB, 2);
    // V projection -> fp32, then transpose+split
    mma_gemm<<<gProj, 256, SMEM128>>>(BF(xhi), BF(xlo), BF(Wvhi), BF(Wvlo),
                                      FL(Vf), nullptr, nullptr, bv, EMB, EMB, 0);
    transpose_split<<<dim3(EMB / 32, SEQ / 32), dim3(32, 8)>>>(FL(Vf), BF(Vthi), BF(Vtlo));

    // fused attention: scores + softmax + ctx, attn written once
    attention_fused<<<dim3(SEQ / 128, NH), 256, FA_SMEM>>>(
        BF(Qhi), BF(Qlo), BF(Khi), BF(Klo), BF(Vthi), BF(Vtlo),
        attn, BF(chi), BF(clo));

    // out = ctx @ Wo^T + bo
    mma_gemm<<<gProj, 256, SMEM128>>>(BF(chi), BF(clo), BF(Wohi), BF(Wolo),
                                      out, nullptr, nullptr, bo, EMB, EMB, 0);
#undef BF
#undef FL
}

// round 7
// speedup vs baseline: 3.0221x; 1.0658x over previous
#include <cuda_runtime.h>
#include <cuda_bf16.h>
#include <cstdint>
#include <math.h>

#define SEQ 2048
#define EMB 1024
#define NH  16
#define HD  64

// ============================ helpers ============================
#define CP_ASYNC16(dst, src) \
    asm volatile("cp.async.cg.shared.global [%0], [%1], 16;" :: "r"(dst), "l"(src) : "memory")
#define CP_ASYNC_COMMIT() asm volatile("cp.async.commit_group;" ::: "memory")
#define CP_ASYNC_WAIT0()  asm volatile("cp.async.wait_group 0;" ::: "memory")
#define CP_ASYNC_WAIT1()  asm volatile("cp.async.wait_group 1;" ::: "memory")

#define LDSM4(r, addr) \
    asm volatile("ldmatrix.sync.aligned.m8n8.x4.shared.b16 {%0,%1,%2,%3}, [%4];" \
        : "=r"((r)[0]), "=r"((r)[1]), "=r"((r)[2]), "=r"((r)[3]) : "r"(addr))

__device__ __forceinline__ void mma16816(float* d, const uint32_t* a, const uint32_t* b) {
    asm volatile(
        "mma.sync.aligned.m16n8k16.row.col.f32.bf16.bf16.f32 "
        "{%0,%1,%2,%3}, {%4,%5,%6,%7}, {%8,%9}, {%0,%1,%2,%3};"
        : "+f"(d[0]), "+f"(d[1]), "+f"(d[2]), "+f"(d[3])
        : "r"(a[0]), "r"(a[1]), "r"(a[2]), "r"(a[3]), "r"(b[0]), "r"(b[1]));
}

__device__ __forceinline__ uint32_t pack2(float x, float y) {
    __nv_bfloat162 t = __floats2bfloat162_rn(x, y);
    return *(uint32_t*)&t;
}

// ============================ device scratch ============================
__device__ __align__(256) float g_Vf[SEQ * EMB];

__device__ __align__(256) __nv_bfloat16 g_xhi[SEQ * EMB],  g_xlo[SEQ * EMB];
__device__ __align__(256) __nv_bfloat16 g_Qhi[SEQ * EMB],  g_Qlo[SEQ * EMB];   // [NH][SEQ][64]
__device__ __align__(256) __nv_bfloat16 g_Khi[SEQ * EMB],  g_Klo[SEQ * EMB];   // [NH][SEQ][64]
__device__ __align__(256) __nv_bfloat16 g_Vthi[EMB * SEQ], g_Vtlo[EMB * SEQ];  // V^T [EMB][SEQ]
__device__ __align__(256) __nv_bfloat16 g_chi[SEQ * EMB],  g_clo[SEQ * EMB];   // ctx [SEQ][EMB]

// ============================ split / transpose ============================
__global__ __launch_bounds__(256)
void split_pair(const float* __restrict__ src, __nv_bfloat16* __restrict__ hi,
                __nv_bfloat16* __restrict__ lo, int n)
{
    int i = blockIdx.x * 256 + threadIdx.x;
    if (i < n) {
        float v = src[i];
        __nv_bfloat16 h = __float2bfloat16(v);
        hi[i] = h;
        lo[i] = __float2bfloat16(v - __bfloat162float(h));
    }
}

__global__ __launch_bounds__(256)
void transpose_split(const float* __restrict__ V, __nv_bfloat16* __restrict__ hi,
                     __nv_bfloat16* __restrict__ lo)
{
    __shared__ float t[32][33];
    int e0 = blockIdx.x * 32, s0 = blockIdx.y * 32;
    int tx = threadIdx.x, ty = threadIdx.y;  // 32 x 8
#pragma unroll
    for (int i = 0; i < 32; i += 8)
        t[ty + i][tx] = V[(size_t)(s0 + ty + i) * EMB + e0 + tx];
    __syncthreads();
#pragma unroll
    for (int i = 0; i < 32; i += 8) {
        float v = t[tx][ty + i];
        size_t o = (size_t)(e0 + ty + i) * SEQ + s0 + tx;
        __nv_bfloat16 hh = __float2bfloat16(v);
        hi[o] = hh;
        lo[o] = __float2bfloat16(v - __bfloat162float(hh));
    }
}

// ============================ split-bf16 HMMA NT GEMM (projections) ============================
// C = (A @ B^T) + bias. A = bf16 hi/lo planes (row stride Ktot).
// B = fp32 weights [N,Ktot]; loader converts to hi/lo planes on the fly.
// mode 0: fp32 C [M,ldc]; mode 2: bf16 hi/lo planes, packed [NH][SEQ][64] layout.
__global__ __launch_bounds__(256, 1)
void mma_gemm(const __nv_bfloat16* __restrict__ Ahi, const __nv_bfloat16* __restrict__ Alo,
              const float* __restrict__ Bf,
              float* __restrict__ C, __nv_bfloat16* __restrict__ Chi,
              __nv_bfloat16* __restrict__ Clo, const float* __restrict__ bias,
              int Ktot, int ldc, int mode)
{
    constexpr int BN = 128;
    constexpr int NT = BN / 16;
    constexpr int APLANE = 128 * 80;
    constexpr int BPLANE = BN * 80;
    constexpr int STAGE  = 2 * APLANE + 2 * BPLANE;

    extern __shared__ char dsm[];
    const uint32_t smem0 = (uint32_t)__cvta_generic_to_shared(dsm);

    const int tid  = threadIdx.x;
    const int wid  = tid >> 5;
    const int lane = tid & 31;
    const int wm = wid & 3;
    const int wn = wid >> 2;
    const int rl = lane >> 2;

    const int row0 = blockIdx.y * 128;
    const int col0 = blockIdx.x * BN;

    float acc[2][NT][4];
#pragma unroll
    for (int mi = 0; mi < 2; mi++)
#pragma unroll
        for (int ni = 0; ni < NT; ni++)
#pragma unroll
            for (int j = 0; j < 4; j++) acc[mi][ni][j] = 0.f;

    const int NC = Ktot >> 5;

    auto load_A = [&](int c, int s) {
        const uint32_t sb = smem0 + s * STAGE;
        for (int i = tid; i < 1024; i += 256) {
            int pl = i >> 9;
            int rem = i & 511;
            int r = rem >> 2, g = rem & 3;
            const __nv_bfloat16* src =
                (pl ? Alo : Ahi) + (size_t)(row0 + r) * Ktot + c * 32 + g * 8;
            CP_ASYNC16(sb + pl * APLANE + r * 80 + g * 16, src);
        }
        CP_ASYNC_COMMIT();
    };

    // fp32 B loader: each thread handles row (tid>>1), 16-float segment (tid&1)
    float4 breg[4];
    const int br = tid >> 1;
    const int bseg = (tid & 1) * 16;
    auto ldg_B = [&](int c) {
        const float* src = Bf + (size_t)(col0 + br) * Ktot + c * 32 + bseg;
#pragma unroll
        for (int i = 0; i < 4; i++) breg[i] = *(const float4*)(src + i * 4);
    };
    auto sts_B = [&](int s) {
        const uint32_t off = (uint32_t)(s * STAGE + 2 * APLANE + br * 80 + bseg * 2);
        uint4 hi4, lo4;
        uint32_t* h = (uint32_t*)&hi4;
        uint32_t* l = (uint32_t*)&lo4;
#pragma unroll
        for (int i = 0; i < 2; i++) {
            float4 v0 = breg[i * 2], v1 = breg[i * 2 + 1];
            h[0] = pack2(v0.x, v0.y); h[1] = pack2(v0.z, v0.w);
            h[2] = pack2(v1.x, v1.y); h[3] = pack2(v1.z, v1.w);
            __nv_bfloat162* hb = (__nv_bfloat162*)h;
            l[0] = pack2(v0.x - __low2float(hb[0]), v0.y - __high2float(hb[0]));
            l[1] = pack2(v0.z - __low2float(hb[1]), v0.w - __high2float(hb[1]));
            l[2] = pack2(v1.x - __low2float(hb[2]), v1.y - __high2float(hb[2]));
            l[3] = pack2(v1.z - __low2float(hb[3]), v1.w - __high2float(hb[3]));
            *(uint4*)(dsm + off + i * 16) = hi4;
            *(uint4*)(dsm + off + BPLANE + i * 16) = lo4;
        }
    };

    auto compute = [&](int s) {
        const uint32_t sb = smem0 + s * STAGE;
        const int r16 = lane & 15, ah = lane >> 4;
        const uint32_t aAddr = sb + (wm * 32 + r16) * 80 + ah * 16;
        const int bp = lane >> 4, bh = (lane >> 3) & 1, brr = lane & 7;
        const uint32_t bAddr = sb + 2 * APLANE + (wn * (BN / 2) + bp * 8 + brr) * 80 + bh * 16;
#pragma unroll
        for (int kk = 0; kk < 2; kk++) {
            uint32_t a[2][2][4];
#pragma unroll
            for (int pl = 0; pl < 2; pl++)
#pragma unroll
                for (int mi = 0; mi < 2; mi++)
                    LDSM4(a[pl][mi], aAddr + pl * APLANE + mi * 16 * 80 + kk * 32);
            uint32_t b[2][NT][2];
#pragma unroll
            for (int pl = 0; pl < 2; pl++)
#pragma unroll
                for (int np = 0; np < NT / 2; np++) {
                    uint32_t r4[4];
                    LDSM4(r4, bAddr + pl * BPLANE + np * 16 * 80 + kk * 32);
                    b[pl][2 * np][0] = r4[0]; b[pl][2 * np][1] = r4[1];
                    b[pl][2 * np + 1][0] = r4[2]; b[pl][2 * np + 1][1] = r4[3];
                }
#pragma unroll
            for (int mi = 0; mi < 2; mi++)
#pragma unroll
                for (int ni = 0; ni < NT; ni++) {
                    mma16816(acc[mi][ni], a[0][mi], b[0][ni]);
                    mma16816(acc[mi][ni], a[0][mi], b[1][ni]);
                    mma16816(acc[mi][ni], a[1][mi], b[0][ni]);
                }
        }
    };

    ldg_B(0); load_A(0, 0);
    sts_B(0);
    CP_ASYNC_WAIT0(); __syncthreads();
    for (int c = 0; c < NC; c++) {
        const int s = c & 1;
        if (c + 1 < NC) { ldg_B(c + 1); load_A(c + 1, s ^ 1); }
        compute(s);
        if (c + 1 < NC) { sts_B(s ^ 1); CP_ASYNC_WAIT0(); __syncthreads(); }
    }

    const int cl = (lane & 3) * 2;
#pragma unroll
    for (int mi = 0; mi < 2; mi++) {
        const int r = row0 + wm * 32 + mi * 16 + rl;
#pragma unroll
        for (int ni = 0; ni < NT; ni++) {
            const int cc = col0 + wn * (BN / 2) + ni * 8 + cl;
            float b0 = 0.f, b1 = 0.f;
            if (bias) { b0 = bias[cc]; b1 = bias[cc + 1]; }
            float v00 = acc[mi][ni][0] + b0;
            float v01 = acc[mi][ni][1] + b1;
            float v10 = acc[mi][ni][2] + b0;
            float v11 = acc[mi][ni][3] + b1;
            if (mode == 0) {
                *(float2*)(C + (size_t)r * ldc + cc) = make_float2(v00, v01);
                *(float2*)(C + (size_t)(r + 8) * ldc + cc) = make_float2(v10, v11);
            } else {
                size_t o0 = (size_t)(cc >> 6) * ((size_t)SEQ * 64) + (size_t)r * 64 + (cc & 63);
                size_t o1 = o0 + 8 * 64;
                uint32_t h0 = pack2(v00, v01), h1 = pack2(v10, v11);
                __nv_bfloat162 hb0 = *(__nv_bfloat162*)&h0;
                __nv_bfloat162 hb1 = *(__nv_bfloat162*)&h1;
                uint32_t l0 = pack2(v00 - __low2float(hb0), v01 - __high2float(hb0));
                uint32_t l1 = pack2(v10 - __low2float(hb1), v11 - __high2float(hb1));
                *(uint32_t*)(Chi + o0) = h0;
                *(uint32_t*)(Chi + o1) = h1;
                *(uint32_t*)(Clo + o0) = l0;
                *(uint32_t*)(Clo + o1) = l1;
            }
        }
    }
}

// ============================ fused attention ============================
// Per CTA: head = blockIdx.y, 128 Q rows = blockIdx.x*128.
// Phase 1: S = Q@K^T/32 (3-product), P=exp(S), rowsum, ctx += P@V (unnormalized).
// Phase 2: recompute S with 2 products (Qhi*Khi + Qlo*Khi), write exp(S)*inv_sum.
static constexpr int FA_OFF_K   = 36864;
static constexpr int FA_OFF_V   = 110592;
static constexpr int FA_OFF_RED = 180224;
static constexpr int FA_SMEM    = 181760;

__global__ __launch_bounds__(256, 1)
void attention_fused(const __nv_bfloat16* __restrict__ Qhi, const __nv_bfloat16* __restrict__ Qlo,
                     const __nv_bfloat16* __restrict__ Khi, const __nv_bfloat16* __restrict__ Klo,
                     const __nv_bfloat16* __restrict__ Vthi, const __nv_bfloat16* __restrict__ Vtlo,
                     float* __restrict__ attn,
                     __nv_bfloat16* __restrict__ chi, __nv_bfloat16* __restrict__ clo)
{
    extern __shared__ char sm[];
    const uint32_t sb = (uint32_t)__cvta_generic_to_shared(sm);

    const int tid  = threadIdx.x;
    const int lane = tid & 31, wid = tid >> 5;
    const int wm = wid & 3, wn = wid >> 2;
    const int rl = lane >> 2;
    const int h  = blockIdx.y;
    const int q0 = blockIdx.x * 128;

    auto loadQ = [&]() {
        for (int i = tid; i < 2048; i += 256) {
            int pl = i >> 10, rem = i & 1023, r = rem >> 3, g = rem & 7;
            const __nv_bfloat16* src = (pl ? Qlo : Qhi) + ((size_t)h * SEQ + q0 + r) * 64 + g * 8;
            CP_ASYNC16(sb + pl * 18432 + r * 144 + g * 16, src);
        }
    };
    auto loadK = [&](int j) {
        int st = (j & 1) * 36864;
        for (int i = tid; i < 2048; i += 256) {
            int pl = i >> 10, rem = i & 1023, r = rem >> 3, g = rem & 7;
            const __nv_bfloat16* src = (pl ? Klo : Khi) + ((size_t)h * SEQ + j * 128 + r) * 64 + g * 8;
            CP_ASYNC16(sb + FA_OFF_K + st + pl * 18432 + r * 144 + g * 16, src);
        }
    };
    auto loadK_hi = [&](int j) {   // phase 2: hi plane only
        int st = (j & 1) * 36864;
        for (int i = tid; i < 1024; i += 256) {
            int r = i >> 3, g = i & 7;
            const __nv_bfloat16* src = Khi + ((size_t)h * SEQ + j * 128 + r) * 64 + g * 8;
            CP_ASYNC16(sb + FA_OFF_K + st + r * 144 + g * 16, src);
        }
    };
    auto loadV = [&](int j) {
        int st = (j & 1) * 34816;
        for (int i = tid; i < 2048; i += 256) {
            int pl = i >> 10, rem = i & 1023, d = rem >> 4, g = rem & 15;
            const __nv_bfloat16* src = (pl ? Vtlo : Vthi) + ((size_t)(h * 64 + d)) * SEQ + j * 128 + g * 8;
            CP_ASYNC16(sb + FA_OFF_V + st + pl * 17408 + d * 272 + g * 16, src);
        }
    };

    const uint32_t aBase  = sb + (wm * 32 + (lane & 15)) * 144 + (lane >> 4) * 16;
    const uint32_t bBaseK = sb + FA_OFF_K + (wn * 64 + (lane >> 4) * 8 + (lane & 7)) * 144
                            + ((lane >> 3) & 1) * 16;
    const uint32_t bBaseV = sb + FA_OFF_V + ((lane >> 4) * 8 + (lane & 7)) * 272
                            + ((lane >> 3) & 1) * 16 + wn * 128;

    float ctx[2][8][4];
#pragma unroll
    for (int mi = 0; mi < 2; mi++)
#pragma unroll
        for (int nd = 0; nd < 8; nd++)
#pragma unroll
            for (int j = 0; j < 4; j++) ctx[mi][nd][j] = 0.f;
    float rs[4] = {0.f, 0.f, 0.f, 0.f};

    auto computeS = [&](int j, float s[2][8][4]) {  // 3-product (phase 1)
        const uint32_t kst = (uint32_t)((j & 1) * 36864);
#pragma unroll
        for (int kk = 0; kk < 4; kk++) {
            uint32_t a[2][2][4];
#pragma unroll
            for (int pl = 0; pl < 2; pl++)
#pragma unroll
                for (int mi = 0; mi < 2; mi++)
                    LDSM4(a[pl][mi], aBase + pl * 18432 + mi * 2304 + kk * 32);
            uint32_t bk[2][8][2];
#pragma unroll
            for (int pl = 0; pl < 2; pl++)
#pragma unroll
                for (int np = 0; np < 4; np++) {
                    uint32_t r4[4];
                    LDSM4(r4, bBaseK + kst + pl * 18432 + np * 2304 + kk * 32);
                    bk[pl][2 * np][0] = r4[0]; bk[pl][2 * np][1] = r4[1];
                    bk[pl][2 * np + 1][0] = r4[2]; bk[pl][2 * np + 1][1] = r4[3];
                }
#pragma unroll
            for (int mi = 0; mi < 2; mi++)
#pragma unroll
                for (int ni = 0; ni < 8; ni++) {
                    mma16816(s[mi][ni], a[0][mi], bk[0][ni]);
                    mma16816(s[mi][ni], a[0][mi], bk[1][ni]);
                    mma16816(s[mi][ni], a[1][mi], bk[0][ni]);
                }
        }
    };

    auto computeS2 = [&](int j, float s[2][8][4]) {  // 2-product, K hi only (phase 2)
        const uint32_t kst = (uint32_t)((j & 1) * 36864);
#pragma unroll
        for (int kk = 0; kk < 4; kk++) {
            uint32_t a[2][2][4];
#pragma unroll
            for (int pl = 0; pl < 2; pl++)
#pragma unroll
                for (int mi = 0; mi < 2; mi++)
                    LDSM4(a[pl][mi], aBase + pl * 18432 + mi * 2304 + kk * 32);
            uint32_t bk[8][2];
#pragma unroll
            for (int np = 0; np < 4; np++) {
                uint32_t r4[4];
                LDSM4(r4, bBaseK + kst + np * 2304 + kk * 32);
                bk[2 * np][0] = r4[0]; bk[2 * np][1] = r4[1];
                bk[2 * np + 1][0] = r4[2]; bk[2 * np + 1][1] = r4[3];
            }
#pragma unroll
            for (int mi = 0; mi < 2; mi++)
#pragma unroll
                for (int ni = 0; ni < 8; ni++) {
                    mma16816(s[mi][ni], a[0][mi], bk[ni]);
                    mma16816(s[mi][ni], a[1][mi], bk[ni]);
                }
        }
    };

    // ---------------- prologue ----------------
    loadQ(); loadK(0); loadV(0); CP_ASYNC_COMMIT();
    loadK(1); loadV(1); CP_ASYNC_COMMIT();

    // ---------------- phase 1 ----------------
    for (int j = 0; j < 16; j++) {
        if (j < 15) { CP_ASYNC_WAIT1(); } else { CP_ASYNC_WAIT0(); }
        __syncthreads();

        float s[2][8][4];
#pragma unroll
        for (int mi = 0; mi < 2; mi++)
#pragma unroll
            for (int ni = 0; ni < 8; ni++)
#pragma unroll
                for (int q = 0; q < 4; q++) s[mi][ni][q] = 0.f;
        computeS(j, s);

        const uint32_t vst = (uint32_t)((j & 1) * 34816);
#pragma unroll
        for (int kk = 0; kk < 4; kk++) {
            uint32_t bv[2][8][2];
#pragma unroll
            for (int pl = 0; pl < 2; pl++)
#pragma unroll
                for (int np = 0; np < 4; np++) {
                    uint32_t r4[4];
                    LDSM4(r4, bBaseV + vst + pl * 17408 + np * 4352 + kk * 32);
                    bv[pl][2 * np][0] = r4[0]; bv[pl][2 * np][1] = r4[1];
                    bv[pl][2 * np + 1][0] = r4[2]; bv[pl][2 * np + 1][1] = r4[3];
                }
#pragma unroll
            for (int mi = 0; mi < 2; mi++) {
                const int e = 2 * kk, o = 2 * kk + 1;
                float pe0 = __expf(s[mi][e][0] * 0.03125f);
                float pe1 = __expf(s[mi][e][1] * 0.03125f);
                float pe2 = __expf(s[mi][e][2] * 0.03125f);
                float pe3 = __expf(s[mi][e][3] * 0.03125f);
                float po0 = __expf(s[mi][o][0] * 0.03125f);
                float po1 = __expf(s[mi][o][1] * 0.03125f);
                float po2 = __expf(s[mi][o][2] * 0.03125f);
                float po3 = __expf(s[mi][o][3] * 0.03125f);
                rs[mi * 2 + 0] += pe0 + pe1 + po0 + po1;
                rs[mi * 2 + 1] += pe2 + pe3 + po2 + po3;
                uint32_t ah[4], al[4];
                ah[0] = pack2(pe0, pe1); ah[1] = pack2(pe2, pe3);
                ah[2] = pack2(po0, po1); ah[3] = pack2(po2, po3);
                __nv_bfloat162* hb = (__nv_bfloat162*)ah;
                al[0] = pack2(pe0 - __low2float(hb[0]), pe1 - __high2float(hb[0]));
                al[1] = pack2(pe2 - __low2float(hb[1]), pe3 - __high2float(hb[1]));
                al[2] = pack2(po0 - __low2float(hb[2]), po1 - __high2float(hb[2]));
                al[3] = pack2(po2 - __low2float(hb[3]), po3 - __high2float(hb[3]));
#pragma unroll
                for (int nd = 0; nd < 8; nd++) {
                    mma16816(ctx[mi][nd], ah, bv[0][nd]);
                    mma16816(ctx[mi][nd], ah, bv[1][nd]);
                    mma16816(ctx[mi][nd], al, bv[0][nd]);
                }
            }
        }
        __syncthreads();
        if (j + 2 < 16) { loadK(j + 2); loadV(j + 2); CP_ASYNC_COMMIT(); }
    }

    // ---------------- rowsum reduce ----------------
#pragma unroll
    for (int i = 0; i < 4; i++) {
        rs[i] += __shfl_xor_sync(0xffffffffu, rs[i], 1);
        rs[i] += __shfl_xor_sync(0xffffffffu, rs[i], 2);
    }
    float* redp = (float*)(sm + FA_OFF_RED);            // [2][128]
    float* invp = (float*)(sm + FA_OFF_RED + 1024);     // [128]
    if ((lane & 3) == 0) {
#pragma unroll
        for (int mi = 0; mi < 2; mi++) {
            redp[wn * 128 + wm * 32 + mi * 16 + rl]     = rs[mi * 2 + 0];
            redp[wn * 128 + wm * 32 + mi * 16 + rl + 8] = rs[mi * 2 + 1];
        }
    }
    __syncthreads();
    if (tid < 128) invp[tid] = 1.0f / (redp[tid] + redp[128 + tid]);
    __syncthreads();

    // ---------------- ctx cross-warp reduce + write ----------------
    float* credp = (float*)(sm + FA_OFF_V);   // reuse V area: [128][64] fp32
    if (wn == 1) {
#pragma unroll
        for (int mi = 0; mi < 2; mi++) {
            const int r = wm * 32 + mi * 16 + rl;
#pragma unroll
            for (int nd = 0; nd < 8; nd++) {
                const int c = nd * 8 + (lane & 3) * 2;
                *(float2*)(credp + r * 64 + c)       = make_float2(ctx[mi][nd][0], ctx[mi][nd][1]);
                *(float2*)(credp + (r + 8) * 64 + c) = make_float2(ctx[mi][nd][2], ctx[mi][nd][3]);
            }
        }
    }
    __syncthreads();
    if (wn == 0) {
#pragma unroll
        for (int mi = 0; mi < 2; mi++) {
            const int r = wm * 32 + mi * 16 + rl;
            const float i0 = invp[r], i1 = invp[r + 8];
#pragma unroll
            for (int nd = 0; nd < 8; nd++) {
                const int c = nd * 8 + (lane & 3) * 2;
                float2 p0 = *(float2*)(credp + r * 64 + c);
                float2 p1 = *(float2*)(credp + (r + 8) * 64 + c);
                float v00 = (ctx[mi][nd][0] + p0.x) * i0;
                float v01 = (ctx[mi][nd][1] + p0.y) * i0;
                float v10 = (ctx[mi][nd][2] + p1.x) * i1;
                float v11 = (ctx[mi][nd][3] + p1.y) * i1;
                size_t o0 = (size_t)(q0 + r) * EMB + h * 64 + c;
                size_t o1 = (size_t)(q0 + r + 8) * EMB + h * 64 + c;
                uint32_t h0 = pack2(v00, v01), h1 = pack2(v10, v11);
                __nv_bfloat162 hb0 = *(__nv_bfloat162*)&h0;
                __nv_bfloat162 hb1 = *(__nv_bfloat162*)&h1;
                uint32_t l0 = pack2(v00 - __low2float(hb0), v01 - __high2float(hb0));
                uint32_t l1 = pack2(v10 - __low2float(hb1), v11 - __high2float(hb1));
                *(uint32_t*)(chi + o0) = h0;
                *(uint32_t*)(chi + o1) = h1;
                *(uint32_t*)(clo + o0) = l0;
                *(uint32_t*)(clo + o1) = l1;
            }
        }
    }
    __syncthreads();

    // ---------------- phase 2: 2-product S recompute, write normalized attn ----------------
    loadK_hi(0); CP_ASYNC_COMMIT();
    loadK_hi(1); CP_ASYNC_COMMIT();
    for (int j = 0; j < 16; j++) {
        if (j < 15) { CP_ASYNC_WAIT1(); } else { CP_ASYNC_WAIT0(); }
        __syncthreads();

        float s[2][8][4];
#pragma unroll
        for (int mi = 0; mi < 2; mi++)
#pragma unroll
            for (int ni = 0; ni < 8; ni++)
#pragma unroll
                for (int q = 0; q < 4; q++) s[mi][ni][q] = 0.f;
        computeS2(j, s);

#pragma unroll
        for (int mi = 0; mi < 2; mi++) {
            const int r = wm * 32 + mi * 16 + rl;
            const float i0 = invp[r], i1 = invp[r + 8];
#pragma unroll
            for (int ni = 0; ni < 8; ni++) {
                const int c = wn * 64 + ni * 8 + (lane & 3) * 2;
                float2 v0 = make_float2(__expf(s[mi][ni][0] * 0.03125f) * i0,
                                        __expf(s[mi][ni][1] * 0.03125f) * i0);
                float2 v1 = make_float2(__expf(s[mi][ni][2] * 0.03125f) * i1,
                                        __expf(s[mi][ni][3] * 0.03125f) * i1);
                size_t base = ((size_t)h * SEQ + q0 + r) * (size_t)SEQ + j * 128 + c;
                *(float2*)(attn + base) = v0;
                *(float2*)(attn + base + 8 * SEQ) = v1;
            }
        }
        __syncthreads();
        if (j + 2 < 16) { loadK_hi(j + 2); CP_ASYNC_COMMIT(); }
    }
}

// ============================ host launch ============================
static constexpr int APL = 128 * 80;
static constexpr int SMEM128 = 2 * (2 * APL + 2 * 128 * 80);  // 81920

extern "C" void kernel_launch(void* const* d_in, const int* in_sizes, int n_in,
                              void* d_out, int out_size)
{
    const float* x  = (const float*)d_in[0];
    const float* Wq = (const float*)d_in[1];
    const float* bq = (const float*)d_in[2];
    const float* Wk = (const float*)d_in[3];
    const float* bk = (const float*)d_in[4];
    const float* Wv = (const float*)d_in[5];
    const float* bv = (const float*)d_in[6];
    const float* Wo = (const float*)d_in[7];
    const float* bo = (const float*)d_in[8];

    float* out  = (float*)d_out;
    float* attn = out + (size_t)SEQ * EMB;

#define SYM(p, s) void* p##_v; cudaGetSymbolAddress(&p##_v, s);
    SYM(Vf, g_Vf)
    SYM(xhi, g_xhi) SYM(xlo, g_xlo)
    SYM(Qhi, g_Qhi) SYM(Qlo, g_Qlo) SYM(Khi, g_Khi) SYM(Klo, g_Klo)
    SYM(Vthi, g_Vthi) SYM(Vtlo, g_Vtlo)
    SYM(chi, g_chi) SYM(clo, g_clo)
#undef SYM
#define BF(p) ((__nv_bfloat16*)p##_v)
#define FL(p) ((float*)p##_v)

    cudaFuncSetAttribute(mma_gemm, cudaFuncAttributeMaxDynamicSharedMemorySize, SMEM128);
    cudaFuncSetAttribute(attention_fused, cudaFuncAttributeMaxDynamicSharedMemorySize, FA_SMEM);

    const int nSE = SEQ * EMB;

    split_pair<<<nSE / 256, 256>>>(x, BF(xhi), BF(xlo), nSE);

    dim3 gProj(EMB / 128, SEQ / 128, 1);
    // Q/K projections -> packed split planes (mode 2); W split in-loader
    mma_gemm<<<gProj, 256, SMEM128>>>(BF(xhi), BF(xlo), Wq,
                                      nullptr, BF(Qhi), BF(Qlo), bq, EMB, EMB, 2);
    mma_gemm<<<gProj, 256, SMEM128>>>(BF(xhi), BF(xlo), Wk,
                                      nullptr, BF(Khi), BF(Klo), bk, EMB, EMB, 2);
    // V projection -> fp32, then transpose+split
    mma_gemm<<<gProj, 256, SMEM128>>>(BF(xhi), BF(xlo), Wv,
                                      FL(Vf), nullptr, nullptr, bv, EMB, EMB, 0);
    transpose_split<<<dim3(EMB / 32, SEQ / 32), dim3(32, 8)>>>(FL(Vf), BF(Vthi), BF(Vtlo));

    // fused attention: scores + softmax + ctx, attn written once
    attention_fused<<<dim3(SEQ / 128, NH), 256, FA_SMEM>>>(
        BF(Qhi), BF(Qlo), BF(Khi), BF(Klo), BF(Vthi), BF(Vtlo),
        attn, BF(chi), BF(clo));

    // out = ctx @ Wo^T + bo
    mma_gemm<<<gProj, 256, SMEM128>>>(BF(chi), BF(clo), Wo,
                                      out, nullptr, nullptr, bo, EMB, EMB, 0);
#undef BF
#undef FL
}

// round 8
// speedup vs baseline: 3.0264x; 1.0014x over previous
#include <cuda_runtime.h>
#include <cuda_bf16.h>
#include <cstdint>
#include <math.h>

#define SEQ 2048
#define EMB 1024
#define NH  16
#define HD  64

// ============================ helpers ============================
#define CP_ASYNC16(dst, src) \
    asm volatile("cp.async.cg.shared.global [%0], [%1], 16;" :: "r"(dst), "l"(src) : "memory")
#define CP_ASYNC_COMMIT() asm volatile("cp.async.commit_group;" ::: "memory")
#define CP_ASYNC_WAIT0()  asm volatile("cp.async.wait_group 0;" ::: "memory")
#define CP_ASYNC_WAIT1()  asm volatile("cp.async.wait_group 1;" ::: "memory")

#define LDSM4(r, addr) \
    asm volatile("ldmatrix.sync.aligned.m8n8.x4.shared.b16 {%0,%1,%2,%3}, [%4];" \
        : "=r"((r)[0]), "=r"((r)[1]), "=r"((r)[2]), "=r"((r)[3]) : "r"(addr))

__device__ __forceinline__ void mma16816(float* d, const uint32_t* a, const uint32_t* b) {
    asm volatile(
        "mma.sync.aligned.m16n8k16.row.col.f32.bf16.bf16.f32 "
        "{%0,%1,%2,%3}, {%4,%5,%6,%7}, {%8,%9}, {%0,%1,%2,%3};"
        : "+f"(d[0]), "+f"(d[1]), "+f"(d[2]), "+f"(d[3])
        : "r"(a[0]), "r"(a[1]), "r"(a[2]), "r"(a[3]), "r"(b[0]), "r"(b[1]));
}

__device__ __forceinline__ uint32_t pack2(float x, float y) {
    __nv_bfloat162 t = __floats2bfloat162_rn(x, y);
    return *(uint32_t*)&t;
}

// ============================ device scratch ============================
__device__ __align__(256) float g_Vf[SEQ * EMB];

__device__ __align__(256) __nv_bfloat16 g_xhi[SEQ * EMB],  g_xlo[SEQ * EMB];
__device__ __align__(256) __nv_bfloat16 g_Qhi[SEQ * EMB],  g_Qlo[SEQ * EMB];   // [NH][SEQ][64]
__device__ __align__(256) __nv_bfloat16 g_Khi[SEQ * EMB],  g_Klo[SEQ * EMB];   // [NH][SEQ][64]
__device__ __align__(256) __nv_bfloat16 g_Vthi[EMB * SEQ], g_Vtlo[EMB * SEQ];  // V^T [EMB][SEQ]
__device__ __align__(256) __nv_bfloat16 g_chi[SEQ * EMB],  g_clo[SEQ * EMB];   // ctx [SEQ][EMB]

// ============================ split / transpose ============================
__global__ __launch_bounds__(256)
void split_pair(const float* __restrict__ src, __nv_bfloat16* __restrict__ hi,
                __nv_bfloat16* __restrict__ lo, int n)
{
    int i = blockIdx.x * 256 + threadIdx.x;
    if (i < n) {
        float v = src[i];
        __nv_bfloat16 h = __float2bfloat16(v);
        hi[i] = h;
        lo[i] = __float2bfloat16(v - __bfloat162float(h));
    }
}

__global__ __launch_bounds__(256)
void transpose_split(const float* __restrict__ V, __nv_bfloat16* __restrict__ hi,
                     __nv_bfloat16* __restrict__ lo)
{
    __shared__ float t[32][33];
    int e0 = blockIdx.x * 32, s0 = blockIdx.y * 32;
    int tx = threadIdx.x, ty = threadIdx.y;  // 32 x 8
#pragma unroll
    for (int i = 0; i < 32; i += 8)
        t[ty + i][tx] = V[(size_t)(s0 + ty + i) * EMB + e0 + tx];
    __syncthreads();
#pragma unroll
    for (int i = 0; i < 32; i += 8) {
        float v = t[tx][ty + i];
        size_t o = (size_t)(e0 + ty + i) * SEQ + s0 + tx;
        __nv_bfloat16 hh = __float2bfloat16(v);
        hi[o] = hh;
        lo[o] = __float2bfloat16(v - __bfloat162float(hh));
    }
}

// ============================ split-bf16 HMMA NT projection GEMM ============================
// kind 0 (QKV): blockIdx.z selects {Wq->Q planes packed, Wk->K planes packed, Wv->fp32 Vf}.
// kind 1 (Wo):  single z, fp32 out.
// A = bf16 hi/lo planes (row stride 1024). B = fp32 weights, split in-loader.
// 3-stage cp.async pipeline, BK=32. 8 warps = 4(m) x 2(n).
__global__ __launch_bounds__(256, 1)
void proj_gemm(const __nv_bfloat16* __restrict__ Ahi, const __nv_bfloat16* __restrict__ Alo,
               const float* __restrict__ W0, const float* __restrict__ W1,
               const float* __restrict__ W2,
               const float* __restrict__ b0, const float* __restrict__ b1,
               const float* __restrict__ b2,
               __nv_bfloat16* __restrict__ P0hi, __nv_bfloat16* __restrict__ P0lo,
               __nv_bfloat16* __restrict__ P1hi, __nv_bfloat16* __restrict__ P1lo,
               float* __restrict__ Cf, int kind)
{
    constexpr int BN = 128;
    constexpr int NT = BN / 16;
    constexpr int APLANE = 128 * 80;
    constexpr int BPLANE = BN * 80;
    constexpr int STAGE  = 2 * APLANE + 2 * BPLANE;   // 40960
    constexpr int Ktot = EMB;
    constexpr int NC = Ktot / 32;

    extern __shared__ char dsm[];
    const uint32_t smem0 = (uint32_t)__cvta_generic_to_shared(dsm);

    const int tid  = threadIdx.x;
    const int wid  = tid >> 5;
    const int lane = tid & 31;
    const int wm = wid & 3;
    const int wn = wid >> 2;
    const int rl = lane >> 2;

    const int z = blockIdx.z;
    const float* Bf   = (z == 0) ? W0 : (z == 1) ? W1 : W2;
    const float* bias = (z == 0) ? b0 : (z == 1) ? b1 : b2;
    // mode: 2 = packed bf16 planes, 0 = fp32
    const int mode = (kind == 1 || z == 2) ? 0 : 2;
    __nv_bfloat16* Chi = (z == 0) ? P0hi : P1hi;
    __nv_bfloat16* Clo = (z == 0) ? P0lo : P1lo;

    const int row0 = blockIdx.y * 128;
    const int col0 = blockIdx.x * BN;

    float acc[2][NT][4];
#pragma unroll
    for (int mi = 0; mi < 2; mi++)
#pragma unroll
        for (int ni = 0; ni < NT; ni++)
#pragma unroll
            for (int j = 0; j < 4; j++) acc[mi][ni][j] = 0.f;

    auto load_A = [&](int c) {
        const uint32_t sb = smem0 + (c % 3) * STAGE;
        for (int i = tid; i < 1024; i += 256) {
            int pl = i >> 9;
            int rem = i & 511;
            int r = rem >> 2, g = rem & 3;
            const __nv_bfloat16* src =
                (pl ? Alo : Ahi) + (size_t)(row0 + r) * Ktot + c * 32 + g * 8;
            CP_ASYNC16(sb + pl * APLANE + r * 80 + g * 16, src);
        }
        CP_ASYNC_COMMIT();
    };

    float4 breg[4];
    const int br = tid >> 1;
    const int bseg = (tid & 1) * 16;
    auto ldg_B = [&](int c) {
        const float* src = Bf + (size_t)(col0 + br) * Ktot + c * 32 + bseg;
#pragma unroll
        for (int i = 0; i < 4; i++) breg[i] = *(const float4*)(src + i * 4);
    };
    auto sts_B = [&](int c) {
        const uint32_t off = (uint32_t)((c % 3) * STAGE + 2 * APLANE + br * 80 + bseg * 2);
        uint4 hi4, lo4;
        uint32_t* h = (uint32_t*)&hi4;
        uint32_t* l = (uint32_t*)&lo4;
#pragma unroll
        for (int i = 0; i < 2; i++) {
            float4 v0 = breg[i * 2], v1 = breg[i * 2 + 1];
            h[0] = pack2(v0.x, v0.y); h[1] = pack2(v0.z, v0.w);
            h[2] = pack2(v1.x, v1.y); h[3] = pack2(v1.z, v1.w);
            __nv_bfloat162* hb = (__nv_bfloat162*)h;
            l[0] = pack2(v0.x - __low2float(hb[0]), v0.y - __high2float(hb[0]));
            l[1] = pack2(v0.z - __low2float(hb[1]), v0.w - __high2float(hb[1]));
            l[2] = pack2(v1.x - __low2float(hb[2]), v1.y - __high2float(hb[2]));
            l[3] = pack2(v1.z - __low2float(hb[3]), v1.w - __high2float(hb[3]));
            *(uint4*)(dsm + off + i * 16) = hi4;
            *(uint4*)(dsm + off + BPLANE + i * 16) = lo4;
        }
    };

    auto compute = [&](int c) {
        const uint32_t sb = smem0 + (c % 3) * STAGE;
        const int r16 = lane & 15, ah = lane >> 4;
        const uint32_t aAddr = sb + (wm * 32 + r16) * 80 + ah * 16;
        const int bp = lane >> 4, bh = (lane >> 3) & 1, brr = lane & 7;
        const uint32_t bAddr = sb + 2 * APLANE + (wn * (BN / 2) + bp * 8 + brr) * 80 + bh * 16;
#pragma unroll
        for (int kk = 0; kk < 2; kk++) {
            uint32_t a[2][2][4];
#pragma unroll
            for (int pl = 0; pl < 2; pl++)
#pragma unroll
                for (int mi = 0; mi < 2; mi++)
                    LDSM4(a[pl][mi], aAddr + pl * APLANE + mi * 16 * 80 + kk * 32);
            uint32_t b[2][NT][2];
#pragma unroll
            for (int pl = 0; pl < 2; pl++)
#pragma unroll
                for (int np = 0; np < NT / 2; np++) {
                    uint32_t r4[4];
                    LDSM4(r4, bAddr + pl * BPLANE + np * 16 * 80 + kk * 32);
                    b[pl][2 * np][0] = r4[0]; b[pl][2 * np][1] = r4[1];
                    b[pl][2 * np + 1][0] = r4[2]; b[pl][2 * np + 1][1] = r4[3];
                }
#pragma unroll
            for (int mi = 0; mi < 2; mi++)
#pragma unroll
                for (int ni = 0; ni < NT; ni++) {
                    mma16816(acc[mi][ni], a[0][mi], b[0][ni]);
                    mma16816(acc[mi][ni], a[0][mi], b[1][ni]);
                    mma16816(acc[mi][ni], a[1][mi], b[0][ni]);
                }
        }
    };

    // prologue: stages 0,1 filled; B regs for stage 2 in flight
    ldg_B(0); sts_B(0); load_A(0);
    ldg_B(1); sts_B(1); load_A(1);
    ldg_B(2);

    for (int c = 0; c < NC; c++) {
        if (c + 1 < NC) { CP_ASYNC_WAIT1(); } else { CP_ASYNC_WAIT0(); }
        __syncthreads();
        compute(c);
        if (c + 2 < NC) {
            sts_B(c + 2);
            load_A(c + 2);
            if (c + 3 < NC) ldg_B(c + 3);
        }
    }

    const int cl = (lane & 3) * 2;
#pragma unroll
    for (int mi = 0; mi < 2; mi++) {
        const int r = row0 + wm * 32 + mi * 16 + rl;
#pragma unroll
        for (int ni = 0; ni < NT; ni++) {
            const int cc = col0 + wn * (BN / 2) + ni * 8 + cl;
            const float bb0 = bias[cc], bb1 = bias[cc + 1];
            float v00 = acc[mi][ni][0] + bb0;
            float v01 = acc[mi][ni][1] + bb1;
            float v10 = acc[mi][ni][2] + bb0;
            float v11 = acc[mi][ni][3] + bb1;
            if (mode == 0) {
                *(float2*)(Cf + (size_t)r * EMB + cc) = make_float2(v00, v01);
                *(float2*)(Cf + (size_t)(r + 8) * EMB + cc) = make_float2(v10, v11);
            } else {
                size_t o0 = (size_t)(cc >> 6) * ((size_t)SEQ * 64) + (size_t)r * 64 + (cc & 63);
                size_t o1 = o0 + 8 * 64;
                uint32_t h0 = pack2(v00, v01), h1 = pack2(v10, v11);
                __nv_bfloat162 hb0 = *(__nv_bfloat162*)&h0;
                __nv_bfloat162 hb1 = *(__nv_bfloat162*)&h1;
                uint32_t l0 = pack2(v00 - __low2float(hb0), v01 - __high2float(hb0));
                uint32_t l1 = pack2(v10 - __low2float(hb1), v11 - __high2float(hb1));
                *(uint32_t*)(Chi + o0) = h0;
                *(uint32_t*)(Chi + o1) = h1;
                *(uint32_t*)(Clo + o0) = l0;
                *(uint32_t*)(Clo + o1) = l1;
            }
        }
    }
}

// ============================ fused attention ============================
// Per CTA: head = blockIdx.y, 128 Q rows = blockIdx.x*128.
// Phase 1: S = Q@K^T/32 (3-product), P=exp(S), rowsum, ctx += P@V (unnormalized).
// Phase 2: recompute S with 2 products (Qhi*Khi + Qlo*Khi), write exp(S)*inv_sum.
static constexpr int FA_OFF_K   = 36864;
static constexpr int FA_OFF_V   = 110592;
static constexpr int FA_OFF_RED = 180224;
static constexpr int FA_SMEM    = 181760;

__global__ __launch_bounds__(256, 1)
void attention_fused(const __nv_bfloat16* __restrict__ Qhi, const __nv_bfloat16* __restrict__ Qlo,
                     const __nv_bfloat16* __restrict__ Khi, const __nv_bfloat16* __restrict__ Klo,
                     const __nv_bfloat16* __restrict__ Vthi, const __nv_bfloat16* __restrict__ Vtlo,
                     float* __restrict__ attn,
                     __nv_bfloat16* __restrict__ chi, __nv_bfloat16* __restrict__ clo)
{
    extern __shared__ char sm[];
    const uint32_t sb = (uint32_t)__cvta_generic_to_shared(sm);

    const int tid  = threadIdx.x;
    const int lane = tid & 31, wid = tid >> 5;
    const int wm = wid & 3, wn = wid >> 2;
    const int rl = lane >> 2;
    const int h  = blockIdx.y;
    const int q0 = blockIdx.x * 128;

    auto loadQ = [&]() {
        for (int i = tid; i < 2048; i += 256) {
            int pl = i >> 10, rem = i & 1023, r = rem >> 3, g = rem & 7;
            const __nv_bfloat16* src = (pl ? Qlo : Qhi) + ((size_t)h * SEQ + q0 + r) * 64 + g * 8;
            CP_ASYNC16(sb + pl * 18432 + r * 144 + g * 16, src);
        }
    };
    auto loadK = [&](int j) {
        int st = (j & 1) * 36864;
        for (int i = tid; i < 2048; i += 256) {
            int pl = i >> 10, rem = i & 1023, r = rem >> 3, g = rem & 7;
            const __nv_bfloat16* src = (pl ? Klo : Khi) + ((size_t)h * SEQ + j * 128 + r) * 64 + g * 8;
            CP_ASYNC16(sb + FA_OFF_K + st + pl * 18432 + r * 144 + g * 16, src);
        }
    };
    auto loadK_hi = [&](int j) {
        int st = (j & 1) * 36864;
        for (int i = tid; i < 1024; i += 256) {
            int r = i >> 3, g = i & 7;
            const __nv_bfloat16* src = Khi + ((size_t)h * SEQ + j * 128 + r) * 64 + g * 8;
            CP_ASYNC16(sb + FA_OFF_K + st + r * 144 + g * 16, src);
        }
    };
    auto loadV = [&](int j) {
        int st = (j & 1) * 34816;
        for (int i = tid; i < 2048; i += 256) {
            int pl = i >> 10, rem = i & 1023, d = rem >> 4, g = rem & 15;
            const __nv_bfloat16* src = (pl ? Vtlo : Vthi) + ((size_t)(h * 64 + d)) * SEQ + j * 128 + g * 8;
            CP_ASYNC16(sb + FA_OFF_V + st + pl * 17408 + d * 272 + g * 16, src);
        }
    };

    const uint32_t aBase  = sb + (wm * 32 + (lane & 15)) * 144 + (lane >> 4) * 16;
    const uint32_t bBaseK = sb + FA_OFF_K + (wn * 64 + (lane >> 4) * 8 + (lane & 7)) * 144
                            + ((lane >> 3) & 1) * 16;
    const uint32_t bBaseV = sb + FA_OFF_V + ((lane >> 4) * 8 + (lane & 7)) * 272
                            + ((lane >> 3) & 1) * 16 + wn * 128;

    float ctx[2][8][4];
#pragma unroll
    for (int mi = 0; mi < 2; mi++)
#pragma unroll
        for (int nd = 0; nd < 8; nd++)
#pragma unroll
            for (int j = 0; j < 4; j++) ctx[mi][nd][j] = 0.f;
    float rs[4] = {0.f, 0.f, 0.f, 0.f};

    auto computeS = [&](int j, float s[2][8][4]) {
        const uint32_t kst = (uint32_t)((j & 1) * 36864);
#pragma unroll
        for (int kk = 0; kk < 4; kk++) {
            uint32_t a[2][2][4];
#pragma unroll
            for (int pl = 0; pl < 2; pl++)
#pragma unroll
                for (int mi = 0; mi < 2; mi++)
                    LDSM4(a[pl][mi], aBase + pl * 18432 + mi * 2304 + kk * 32);
            uint32_t bk[2][8][2];
#pragma unroll
            for (int pl = 0; pl < 2; pl++)
#pragma unroll
                for (int np = 0; np < 4; np++) {
                    uint32_t r4[4];
                    LDSM4(r4, bBaseK + kst + pl * 18432 + np * 2304 + kk * 32);
                    bk[pl][2 * np][0] = r4[0]; bk[pl][2 * np][1] = r4[1];
                    bk[pl][2 * np + 1][0] = r4[2]; bk[pl][2 * np + 1][1] = r4[3];
                }
#pragma unroll
            for (int mi = 0; mi < 2; mi++)
#pragma unroll
                for (int ni = 0; ni < 8; ni++) {
                    mma16816(s[mi][ni], a[0][mi], bk[0][ni]);
                    mma16816(s[mi][ni], a[0][mi], bk[1][ni]);
                    mma16816(s[mi][ni], a[1][mi], bk[0][ni]);
                }
        }
    };

    auto computeS2 = [&](int j, float s[2][8][4]) {
        const uint32_t kst = (uint32_t)((j & 1) * 36864);
#pragma unroll
        for (int kk = 0; kk < 4; kk++) {
            uint32_t a[2][2][4];
#pragma unroll
            for (int pl = 0; pl < 2; pl++)
#pragma unroll
                for (int mi = 0; mi < 2; mi++)
                    LDSM4(a[pl][mi], aBase + pl * 18432 + mi * 2304 + kk * 32);
            uint32_t bk[8][2];
#pragma unroll
            for (int np = 0; np < 4; np++) {
                uint32_t r4[4];
                LDSM4(r4, bBaseK + kst + np * 2304 + kk * 32);
                bk[2 * np][0] = r4[0]; bk[2 * np][1] = r4[1];
                bk[2 * np + 1][0] = r4[2]; bk[2 * np + 1][1] = r4[3];
            }
#pragma unroll
            for (int mi = 0; mi < 2; mi++)
#pragma unroll
                for (int ni = 0; ni < 8; ni++) {
                    mma16816(s[mi][ni], a[0][mi], bk[ni]);
                    mma16816(s[mi][ni], a[1][mi], bk[ni]);
                }
        }
    };

    loadQ(); loadK(0); loadV(0); CP_ASYNC_COMMIT();
    loadK(1); loadV(1); CP_ASYNC_COMMIT();

    for (int j = 0; j < 16; j++) {
        if (j < 15) { CP_ASYNC_WAIT1(); } else { CP_ASYNC_WAIT0(); }
        __syncthreads();

        float s[2][8][4];
#pragma unroll
        for (int mi = 0; mi < 2; mi++)
#pragma unroll
            for (int ni = 0; ni < 8; ni++)
#pragma unroll
                for (int q = 0; q < 4; q++) s[mi][ni][q] = 0.f;
        computeS(j, s);

        const uint32_t vst = (uint32_t)((j & 1) * 34816);
#pragma unroll
        for (int kk = 0; kk < 4; kk++) {
            uint32_t bv[2][8][2];
#pragma unroll
            for (int pl = 0; pl < 2; pl++)
#pragma unroll
                for (int np = 0; np < 4; np++) {
                    uint32_t r4[4];
                    LDSM4(r4, bBaseV + vst + pl * 17408 + np * 4352 + kk * 32);
                    bv[pl][2 * np][0] = r4[0]; bv[pl][2 * np][1] = r4[1];
                    bv[pl][2 * np + 1][0] = r4[2]; bv[pl][2 * np + 1][1] = r4[3];
                }
#pragma unroll
            for (int mi = 0; mi < 2; mi++) {
                const int e = 2 * kk, o = 2 * kk + 1;
                float pe0 = __expf(s[mi][e][0] * 0.03125f);
                float pe1 = __expf(s[mi][e][1] * 0.03125f);
                float pe2 = __expf(s[mi][e][2] * 0.03125f);
                float pe3 = __expf(s[mi][e][3] * 0.03125f);
                float po0 = __expf(s[mi][o][0] * 0.03125f);
                float po1 = __expf(s[mi][o][1] * 0.03125f);
                float po2 = __expf(s[mi][o][2] * 0.03125f);
                float po3 = __expf(s[mi][o][3] * 0.03125f);
                rs[mi * 2 + 0] += pe0 + pe1 + po0 + po1;
                rs[mi * 2 + 1] += pe2 + pe3 + po2 + po3;
                uint32_t ah[4], al[4];
                ah[0] = pack2(pe0, pe1); ah[1] = pack2(pe2, pe3);
                ah[2] = pack2(po0, po1); ah[3] = pack2(po2, po3);
                __nv_bfloat162* hb = (__nv_bfloat162*)ah;
                al[0] = pack2(pe0 - __low2float(hb[0]), pe1 - __high2float(hb[0]));
                al[1] = pack2(pe2 - __low2float(hb[1]), pe3 - __high2float(hb[1]));
                al[2] = pack2(po0 - __low2float(hb[2]), po1 - __high2float(hb[2]));
                al[3] = pack2(po2 - __low2float(hb[3]), po3 - __high2float(hb[3]));
#pragma unroll
                for (int nd = 0; nd < 8; nd++) {
                    mma16816(ctx[mi][nd], ah, bv[0][nd]);
                    mma16816(ctx[mi][nd], ah, bv[1][nd]);
                    mma16816(ctx[mi][nd], al, bv[0][nd]);
                }
            }
        }
        __syncthreads();
        if (j + 2 < 16) { loadK(j + 2); loadV(j + 2); CP_ASYNC_COMMIT(); }
    }

#pragma unroll
    for (int i = 0; i < 4; i++) {
        rs[i] += __shfl_xor_sync(0xffffffffu, rs[i], 1);
        rs[i] += __shfl_xor_sync(0xffffffffu, rs[i], 2);
    }
    float* redp = (float*)(sm + FA_OFF_RED);
    float* invp = (float*)(sm + FA_OFF_RED + 1024);
    if ((lane & 3) == 0) {
#pragma unroll
        for (int mi = 0; mi < 2; mi++) {
            redp[wn * 128 + wm * 32 + mi * 16 + rl]     = rs[mi * 2 + 0];
            redp[wn * 128 + wm * 32 + mi * 16 + rl + 8] = rs[mi * 2 + 1];
        }
    }
    __syncthreads();
    if (tid < 128) invp[tid] = 1.0f / (redp[tid] + redp[128 + tid]);
    __syncthreads();

    float* credp = (float*)(sm + FA_OFF_V);
    if (wn == 1) {
#pragma unroll
        for (int mi = 0; mi < 2; mi++) {
            const int r = wm * 32 + mi * 16 + rl;
#pragma unroll
            for (int nd = 0; nd < 8; nd++) {
                const int c = nd * 8 + (lane & 3) * 2;
                *(float2*)(credp + r * 64 + c)       = make_float2(ctx[mi][nd][0], ctx[mi][nd][1]);
                *(float2*)(credp + (r + 8) * 64 + c) = make_float2(ctx[mi][nd][2], ctx[mi][nd][3]);
            }
        }
    }
    __syncthreads();
    if (wn == 0) {
#pragma unroll
        for (int mi = 0; mi < 2; mi++) {
            const int r = wm * 32 + mi * 16 + rl;
            const float i0 = invp[r], i1 = invp[r + 8];
#pragma unroll
            for (int nd = 0; nd < 8; nd++) {
                const int c = nd * 8 + (lane & 3) * 2;
                float2 p0 = *(float2*)(credp + r * 64 + c);
                float2 p1 = *(float2*)(credp + (r + 8) * 64 + c);
                float v00 = (ctx[mi][nd][0] + p0.x) * i0;
                float v01 = (ctx[mi][nd][1] + p0.y) * i0;
                float v10 = (ctx[mi][nd][2] + p1.x) * i1;
                float v11 = (ctx[mi][nd][3] + p1.y) * i1;
                size_t o0 = (size_t)(q0 + r) * EMB + h * 64 + c;
                size_t o1 = (size_t)(q0 + r + 8) * EMB + h * 64 + c;
                uint32_t h0 = pack2(v00, v01), h1 = pack2(v10, v11);
                __nv_bfloat162 hb0 = *(__nv_bfloat162*)&h0;
                __nv_bfloat162 hb1 = *(__nv_bfloat162*)&h1;
                uint32_t l0 = pack2(v00 - __low2float(hb0), v01 - __high2float(hb0));
                uint32_t l1 = pack2(v10 - __low2float(hb1), v11 - __high2float(hb1));
                *(uint32_t*)(chi + o0) = h0;
                *(uint32_t*)(chi + o1) = h1;
                *(uint32_t*)(clo + o0) = l0;
                *(uint32_t*)(clo + o1) = l1;
            }
        }
    }
    __syncthreads();

    loadK_hi(0); CP_ASYNC_COMMIT();
    loadK_hi(1); CP_ASYNC_COMMIT();
    for (int j = 0; j < 16; j++) {
        if (j < 15) { CP_ASYNC_WAIT1(); } else { CP_ASYNC_WAIT0(); }
        __syncthreads();

        float s[2][8][4];
#pragma unroll
        for (int mi = 0; mi < 2; mi++)
#pragma unroll
            for (int ni = 0; ni < 8; ni++)
#pragma unroll
                for (int q = 0; q < 4; q++) s[mi][ni][q] = 0.f;
        computeS2(j, s);

#pragma unroll
        for (int mi = 0; mi < 2; mi++) {
            const int r = wm * 32 + mi * 16 + rl;
            const float i0 = invp[r], i1 = invp[r + 8];
#pragma unroll
            for (int ni = 0; ni < 8; ni++) {
                const int c = wn * 64 + ni * 8 + (lane & 3) * 2;
                float2 v0 = make_float2(__expf(s[mi][ni][0] * 0.03125f) * i0,
                                        __expf(s[mi][ni][1] * 0.03125f) * i0);
                float2 v1 = make_float2(__expf(s[mi][ni][2] * 0.03125f) * i1,
                                        __expf(s[mi][ni][3] * 0.03125f) * i1);
                size_t base = ((size_t)h * SEQ + q0 + r) * (size_t)SEQ + j * 128 + c;
                *(float2*)(attn + base) = v0;
                *(float2*)(attn + base + 8 * SEQ) = v1;
            }
        }
        __syncthreads();
        if (j + 2 < 16) { loadK_hi(j + 2); CP_ASYNC_COMMIT(); }
    }
}

// ============================ host launch ============================
static constexpr int SMEM3 = 3 * (2 * 128 * 80 + 2 * 128 * 80);  // 122880

extern "C" void kernel_launch(void* const* d_in, const int* in_sizes, int n_in,
                              void* d_out, int out_size)
{
    const float* x  = (const float*)d_in[0];
    const float* Wq = (const float*)d_in[1];
    const float* bq = (const float*)d_in[2];
    const float* Wk = (const float*)d_in[3];
    const float* bk = (const float*)d_in[4];
    const float* Wv = (const float*)d_in[5];
    const float* bv = (const float*)d_in[6];
    const float* Wo = (const float*)d_in[7];
    const float* bo = (const float*)d_in[8];

    float* out  = (float*)d_out;
    float* attn = out + (size_t)SEQ * EMB;

#define SYM(p, s) void* p##_v; cudaGetSymbolAddress(&p##_v, s);
    SYM(Vf, g_Vf)
    SYM(xhi, g_xhi) SYM(xlo, g_xlo)
    SYM(Qhi, g_Qhi) SYM(Qlo, g_Qlo) SYM(Khi, g_Khi) SYM(Klo, g_Klo)
    SYM(Vthi, g_Vthi) SYM(Vtlo, g_Vtlo)
    SYM(chi, g_chi) SYM(clo, g_clo)
#undef SYM
#define BF(p) ((__nv_bfloat16*)p##_v)
#define FL(p) ((float*)p##_v)

    cudaFuncSetAttribute(proj_gemm, cudaFuncAttributeMaxDynamicSharedMemorySize, SMEM3);
    cudaFuncSetAttribute(attention_fused, cudaFuncAttributeMaxDynamicSharedMemorySize, FA_SMEM);

    const int nSE = SEQ * EMB;

    split_pair<<<nSE / 256, 256>>>(x, BF(xhi), BF(xlo), nSE);

    // QKV in one launch (z selects weight/output)
    proj_gemm<<<dim3(EMB / 128, SEQ / 128, 3), 256, SMEM3>>>(
        BF(xhi), BF(xlo), Wq, Wk, Wv, bq, bk, bv,
        BF(Qhi), BF(Qlo), BF(Khi), BF(Klo), FL(Vf), 0);

    transpose_split<<<dim3(EMB / 32, SEQ / 32), dim3(32, 8)>>>(FL(Vf), BF(Vthi), BF(Vtlo));

    // fused attention: scores + softmax + ctx, attn written once
    attention_fused<<<dim3(SEQ / 128, NH), 256, FA_SMEM>>>(
        BF(Qhi), BF(Qlo), BF(Khi), BF(Klo), BF(Vthi), BF(Vtlo),
        attn, BF(chi), BF(clo));

    // out = ctx @ Wo^T + bo
    proj_gemm<<<dim3(EMB / 128, SEQ / 128, 1), 256, SMEM3>>>(
        BF(chi), BF(clo), Wo, nullptr, nullptr, bo, nullptr, nullptr,
        nullptr, nullptr, nullptr, nullptr, out, 1);
#undef BF
#undef FL
}

// round 9
// speedup vs baseline: 3.3305x; 1.1005x over previous
#include <cuda_runtime.h>
#include <cuda_bf16.h>
#include <cstdint>
#include <math.h>

#define SEQ 2048
#define EMB 1024
#define NH  16
#define HD  64

// ============================ helpers ============================
#define CP_ASYNC16(dst, src) \
    asm volatile("cp.async.cg.shared.global [%0], [%1], 16;" :: "r"(dst), "l"(src) : "memory")
#define CP_ASYNC_COMMIT() asm volatile("cp.async.commit_group;" ::: "memory")
#define CP_ASYNC_WAIT0()  asm volatile("cp.async.wait_group 0;" ::: "memory")
#define CP_ASYNC_WAIT1()  asm volatile("cp.async.wait_group 1;" ::: "memory")

#define LDSM4(r, addr) \
    asm volatile("ldmatrix.sync.aligned.m8n8.x4.shared.b16 {%0,%1,%2,%3}, [%4];" \
        : "=r"((r)[0]), "=r"((r)[1]), "=r"((r)[2]), "=r"((r)[3]) : "r"(addr))

__device__ __forceinline__ void mma16816(float* d, const uint32_t* a, const uint32_t* b) {
    asm volatile(
        "mma.sync.aligned.m16n8k16.row.col.f32.bf16.bf16.f32 "
        "{%0,%1,%2,%3}, {%4,%5,%6,%7}, {%8,%9}, {%0,%1,%2,%3};"
        : "+f"(d[0]), "+f"(d[1]), "+f"(d[2]), "+f"(d[3])
        : "r"(a[0]), "r"(a[1]), "r"(a[2]), "r"(a[3]), "r"(b[0]), "r"(b[1]));
}

__device__ __forceinline__ uint32_t pack2(float x, float y) {
    __nv_bfloat162 t = __floats2bfloat162_rn(x, y);
    return *(uint32_t*)&t;
}

// ============================ device scratch ============================
__device__ __align__(256) float g_Vf[SEQ * EMB];

__device__ __align__(256) __nv_bfloat16 g_xhi[SEQ * EMB],  g_xlo[SEQ * EMB];
__device__ __align__(256) __nv_bfloat16 g_Qhi[SEQ * EMB],  g_Qlo[SEQ * EMB];   // [NH][SEQ][64]
__device__ __align__(256) __nv_bfloat16 g_Khi[SEQ * EMB],  g_Klo[SEQ * EMB];   // [NH][SEQ][64]
__device__ __align__(256) __nv_bfloat16 g_Vthi[EMB * SEQ], g_Vtlo[EMB * SEQ];  // V^T [EMB][SEQ]
__device__ __align__(256) __nv_bfloat16 g_chi[SEQ * EMB],  g_clo[SEQ * EMB];   // ctx [SEQ][EMB]

// ============================ split / transpose ============================
__global__ __launch_bounds__(256)
void split_pair(const float* __restrict__ src, __nv_bfloat16* __restrict__ hi,
                __nv_bfloat16* __restrict__ lo, int n)
{
    int i = blockIdx.x * 256 + threadIdx.x;
    if (i < n) {
        float v = src[i];
        __nv_bfloat16 h = __float2bfloat16(v);
        hi[i] = h;
        lo[i] = __float2bfloat16(v - __bfloat162float(h));
    }
}

__global__ __launch_bounds__(256)
void transpose_split(const float* __restrict__ V, __nv_bfloat16* __restrict__ hi,
                     __nv_bfloat16* __restrict__ lo)
{
    __shared__ float t[32][33];
    int e0 = blockIdx.x * 32, s0 = blockIdx.y * 32;
    int tx = threadIdx.x, ty = threadIdx.y;  // 32 x 8
#pragma unroll
    for (int i = 0; i < 32; i += 8)
        t[ty + i][tx] = V[(size_t)(s0 + ty + i) * EMB + e0 + tx];
    __syncthreads();
#pragma unroll
    for (int i = 0; i < 32; i += 8) {
        float v = t[tx][ty + i];
        size_t o = (size_t)(e0 + ty + i) * SEQ + s0 + tx;
        __nv_bfloat16 hh = __float2bfloat16(v);
        hi[o] = hh;
        lo[o] = __float2bfloat16(v - __bfloat162float(hh));
    }
}

// ============================ split-bf16 HMMA NT projection GEMM ============================
// BM=256, BN=64 tiles. kind 0 (QKV): z selects {Wq,Wk,Wv}; kind 1 (Wo).
// A = bf16 hi/lo planes (row stride 1024). B = fp32 weights, split in-loader.
// 3-stage cp.async pipeline, BK=32. 8 warps = 4(m: 64 rows) x 2(n: 32 cols).
__global__ __launch_bounds__(256, 1)
void proj_gemm(const __nv_bfloat16* __restrict__ Ahi, const __nv_bfloat16* __restrict__ Alo,
               const float* __restrict__ W0, const float* __restrict__ W1,
               const float* __restrict__ W2,
               const float* __restrict__ b0, const float* __restrict__ b1,
               const float* __restrict__ b2,
               __nv_bfloat16* __restrict__ P0hi, __nv_bfloat16* __restrict__ P0lo,
               __nv_bfloat16* __restrict__ P1hi, __nv_bfloat16* __restrict__ P1lo,
               float* __restrict__ Cf, int kind)
{
    constexpr int APLANE = 256 * 80;   // 20480
    constexpr int BPLANE = 64 * 80;    // 5120
    constexpr int STAGE  = 2 * APLANE + 2 * BPLANE;  // 51200
    constexpr int NC = EMB / 32;       // 32

    extern __shared__ char dsm[];
    const uint32_t smem0 = (uint32_t)__cvta_generic_to_shared(dsm);

    const int tid  = threadIdx.x;
    const int wid  = tid >> 5;
    const int lane = tid & 31;
    const int wm = wid & 3;
    const int wn = wid >> 2;
    const int rl = lane >> 2;

    const int z = blockIdx.z;
    const float* Bf   = (z == 0) ? W0 : (z == 1) ? W1 : W2;
    const float* bias = (z == 0) ? b0 : (z == 1) ? b1 : b2;
    const int mode = (kind == 1 || z == 2) ? 0 : 2;
    __nv_bfloat16* Chi = (z == 0) ? P0hi : P1hi;
    __nv_bfloat16* Clo = (z == 0) ? P0lo : P1lo;

    const int row0 = blockIdx.y * 256;
    const int col0 = blockIdx.x * 64;

    float acc[4][4][4];
#pragma unroll
    for (int mi = 0; mi < 4; mi++)
#pragma unroll
        for (int ni = 0; ni < 4; ni++)
#pragma unroll
            for (int j = 0; j < 4; j++) acc[mi][ni][j] = 0.f;

    auto load_A = [&](int c) {
        const uint32_t sb = smem0 + (c % 3) * STAGE;
        for (int i = tid; i < 2048; i += 256) {
            int pl = i >> 10;
            int rem = i & 1023;
            int r = rem >> 2, g = rem & 3;
            const __nv_bfloat16* src =
                (pl ? Alo : Ahi) + (size_t)(row0 + r) * EMB + c * 32 + g * 8;
            CP_ASYNC16(sb + pl * APLANE + r * 80 + g * 16, src);
        }
        CP_ASYNC_COMMIT();
    };

    float4 breg[2];
    const int br = tid >> 2;           // 0..63
    const int bseg = (tid & 3) * 8;    // 0,8,16,24 floats
    auto ldg_B = [&](int c) {
        const float* src = Bf + (size_t)(col0 + br) * EMB + c * 32 + bseg;
        breg[0] = *(const float4*)(src);
        breg[1] = *(const float4*)(src + 4);
    };
    auto sts_B = [&](int c) {
        const uint32_t off = (uint32_t)((c % 3) * STAGE + 2 * APLANE + br * 80 + bseg * 2);
        uint4 hi4, lo4;
        uint32_t* h = (uint32_t*)&hi4;
        uint32_t* l = (uint32_t*)&lo4;
        float4 v0 = breg[0], v1 = breg[1];
        h[0] = pack2(v0.x, v0.y); h[1] = pack2(v0.z, v0.w);
        h[2] = pack2(v1.x, v1.y); h[3] = pack2(v1.z, v1.w);
        __nv_bfloat162* hb = (__nv_bfloat162*)h;
        l[0] = pack2(v0.x - __low2float(hb[0]), v0.y - __high2float(hb[0]));
        l[1] = pack2(v0.z - __low2float(hb[1]), v0.w - __high2float(hb[1]));
        l[2] = pack2(v1.x - __low2float(hb[2]), v1.y - __high2float(hb[2]));
        l[3] = pack2(v1.z - __low2float(hb[3]), v1.w - __high2float(hb[3]));
        *(uint4*)(dsm + off) = hi4;
        *(uint4*)(dsm + off + BPLANE) = lo4;
    };

    auto compute = [&](int c) {
        const uint32_t sb = smem0 + (c % 3) * STAGE;
        const uint32_t aAddr = sb + (wm * 64 + (lane & 15)) * 80 + (lane >> 4) * 16;
        const uint32_t bAddr = sb + 2 * APLANE
            + (wn * 32 + (lane >> 4) * 8 + (lane & 7)) * 80 + ((lane >> 3) & 1) * 16;
#pragma unroll
        for (int kk = 0; kk < 2; kk++) {
            uint32_t a[2][4][4];
#pragma unroll
            for (int pl = 0; pl < 2; pl++)
#pragma unroll
                for (int mi = 0; mi < 4; mi++)
                    LDSM4(a[pl][mi], aAddr + pl * APLANE + mi * 16 * 80 + kk * 32);
            uint32_t b[2][4][2];
#pragma unroll
            for (int pl = 0; pl < 2; pl++)
#pragma unroll
                for (int np = 0; np < 2; np++) {
                    uint32_t r4[4];
                    LDSM4(r4, bAddr + pl * BPLANE + np * 16 * 80 + kk * 32);
                    b[pl][2 * np][0] = r4[0]; b[pl][2 * np][1] = r4[1];
                    b[pl][2 * np + 1][0] = r4[2]; b[pl][2 * np + 1][1] = r4[3];
                }
#pragma unroll
            for (int mi = 0; mi < 4; mi++)
#pragma unroll
                for (int ni = 0; ni < 4; ni++) {
                    mma16816(acc[mi][ni], a[0][mi], b[0][ni]);
                    mma16816(acc[mi][ni], a[0][mi], b[1][ni]);
                    mma16816(acc[mi][ni], a[1][mi], b[0][ni]);
                }
        }
    };

    ldg_B(0); sts_B(0); load_A(0);
    ldg_B(1); sts_B(1); load_A(1);
    ldg_B(2);

    for (int c = 0; c < NC; c++) {
        if (c + 1 < NC) { CP_ASYNC_WAIT1(); } else { CP_ASYNC_WAIT0(); }
        __syncthreads();
        compute(c);
        if (c + 2 < NC) {
            sts_B(c + 2);
            load_A(c + 2);
            if (c + 3 < NC) ldg_B(c + 3);
        }
    }

    const int cl = (lane & 3) * 2;
#pragma unroll
    for (int mi = 0; mi < 4; mi++) {
        const int r = row0 + wm * 64 + mi * 16 + rl;
#pragma unroll
        for (int ni = 0; ni < 4; ni++) {
            const int cc = col0 + wn * 32 + ni * 8 + cl;
            const float bb0 = bias[cc], bb1 = bias[cc + 1];
            float v00 = acc[mi][ni][0] + bb0;
            float v01 = acc[mi][ni][1] + bb1;
            float v10 = acc[mi][ni][2] + bb0;
            float v11 = acc[mi][ni][3] + bb1;
            if (mode == 0) {
                *(float2*)(Cf + (size_t)r * EMB + cc) = make_float2(v00, v01);
                *(float2*)(Cf + (size_t)(r + 8) * EMB + cc) = make_float2(v10, v11);
            } else {
                size_t o0 = (size_t)(cc >> 6) * ((size_t)SEQ * 64) + (size_t)r * 64 + (cc & 63);
                size_t o1 = o0 + 8 * 64;
                uint32_t h0 = pack2(v00, v01), h1 = pack2(v10, v11);
                __nv_bfloat162 hb0 = *(__nv_bfloat162*)&h0;
                __nv_bfloat162 hb1 = *(__nv_bfloat162*)&h1;
                uint32_t l0 = pack2(v00 - __low2float(hb0), v01 - __high2float(hb0));
                uint32_t l1 = pack2(v10 - __low2float(hb1), v11 - __high2float(hb1));
                *(uint32_t*)(Chi + o0) = h0;
                *(uint32_t*)(Chi + o1) = h1;
                *(uint32_t*)(Clo + o0) = l0;
                *(uint32_t*)(Clo + o1) = l1;
            }
        }
    }
}

// ============================ fused attention ============================
// Phase 1: S = Q@K^T/32 (3-product), P=exp(S), rowsum, ctx += P@V (unnormalized).
// Phase 2: recompute S with 1 product (Qhi*Khi), write exp(S)*inv_sum.
static constexpr int FA_OFF_K   = 36864;
static constexpr int FA_OFF_V   = 110592;
static constexpr int FA_OFF_RED = 180224;
static constexpr int FA_SMEM    = 181760;

__global__ __launch_bounds__(256, 1)
void attention_fused(const __nv_bfloat16* __restrict__ Qhi, const __nv_bfloat16* __restrict__ Qlo,
                     const __nv_bfloat16* __restrict__ Khi, const __nv_bfloat16* __restrict__ Klo,
                     const __nv_bfloat16* __restrict__ Vthi, const __nv_bfloat16* __restrict__ Vtlo,
                     float* __restrict__ attn,
                     __nv_bfloat16* __restrict__ chi, __nv_bfloat16* __restrict__ clo)
{
    extern __shared__ char sm[];
    const uint32_t sb = (uint32_t)__cvta_generic_to_shared(sm);

    const int tid  = threadIdx.x;
    const int lane = tid & 31, wid = tid >> 5;
    const int wm = wid & 3, wn = wid >> 2;
    const int rl = lane >> 2;
    const int h  = blockIdx.y;
    const int q0 = blockIdx.x * 128;

    auto loadQ = [&]() {
        for (int i = tid; i < 2048; i += 256) {
            int pl = i >> 10, rem = i & 1023, r = rem >> 3, g = rem & 7;
            const __nv_bfloat16* src = (pl ? Qlo : Qhi) + ((size_t)h * SEQ + q0 + r) * 64 + g * 8;
            CP_ASYNC16(sb + pl * 18432 + r * 144 + g * 16, src);
        }
    };
    auto loadK = [&](int j) {
        int st = (j & 1) * 36864;
        for (int i = tid; i < 2048; i += 256) {
            int pl = i >> 10, rem = i & 1023, r = rem >> 3, g = rem & 7;
            const __nv_bfloat16* src = (pl ? Klo : Khi) + ((size_t)h * SEQ + j * 128 + r) * 64 + g * 8;
            CP_ASYNC16(sb + FA_OFF_K + st + pl * 18432 + r * 144 + g * 16, src);
        }
    };
    auto loadK_hi = [&](int j) {
        int st = (j & 1) * 36864;
        for (int i = tid; i < 1024; i += 256) {
            int r = i >> 3, g = i & 7;
            const __nv_bfloat16* src = Khi + ((size_t)h * SEQ + j * 128 + r) * 64 + g * 8;
            CP_ASYNC16(sb + FA_OFF_K + st + r * 144 + g * 16, src);
        }
    };
    auto loadV = [&](int j) {
        int st = (j & 1) * 34816;
        for (int i = tid; i < 2048; i += 256) {
            int pl = i >> 10, rem = i & 1023, d = rem >> 4, g = rem & 15;
            const __nv_bfloat16* src = (pl ? Vtlo : Vthi) + ((size_t)(h * 64 + d)) * SEQ + j * 128 + g * 8;
            CP_ASYNC16(sb + FA_OFF_V + st + pl * 17408 + d * 272 + g * 16, src);
        }
    };

    const uint32_t aBase  = sb + (wm * 32 + (lane & 15)) * 144 + (lane >> 4) * 16;
    const uint32_t bBaseK = sb + FA_OFF_K + (wn * 64 + (lane >> 4) * 8 + (lane & 7)) * 144
                            + ((lane >> 3) & 1) * 16;
    const uint32_t bBaseV = sb + FA_OFF_V + ((lane >> 4) * 8 + (lane & 7)) * 272
                            + ((lane >> 3) & 1) * 16 + wn * 128;

    float ctx[2][8][4];
#pragma unroll
    for (int mi = 0; mi < 2; mi++)
#pragma unroll
        for (int nd = 0; nd < 8; nd++)
#pragma unroll
            for (int j = 0; j < 4; j++) ctx[mi][nd][j] = 0.f;
    float rs[4] = {0.f, 0.f, 0.f, 0.f};

    auto computeS = [&](int j, float s[2][8][4]) {   // 3-product
        const uint32_t kst = (uint32_t)((j & 1) * 36864);
#pragma unroll
        for (int kk = 0; kk < 4; kk++) {
            uint32_t a[2][2][4];
#pragma unroll
            for (int pl = 0; pl < 2; pl++)
#pragma unroll
                for (int mi = 0; mi < 2; mi++)
                    LDSM4(a[pl][mi], aBase + pl * 18432 + mi * 2304 + kk * 32);
            uint32_t bk[2][8][2];
#pragma unroll
            for (int pl = 0; pl < 2; pl++)
#pragma unroll
                for (int np = 0; np < 4; np++) {
                    uint32_t r4[4];
                    LDSM4(r4, bBaseK + kst + pl * 18432 + np * 2304 + kk * 32);
                    bk[pl][2 * np][0] = r4[0]; bk[pl][2 * np][1] = r4[1];
                    bk[pl][2 * np + 1][0] = r4[2]; bk[pl][2 * np + 1][1] = r4[3];
                }
#pragma unroll
            for (int mi = 0; mi < 2; mi++)
#pragma unroll
                for (int ni = 0; ni < 8; ni++) {
                    mma16816(s[mi][ni], a[0][mi], bk[0][ni]);
                    mma16816(s[mi][ni], a[0][mi], bk[1][ni]);
                    mma16816(s[mi][ni], a[1][mi], bk[0][ni]);
                }
        }
    };

    auto computeS2 = [&](int j, float s[2][8][4]) {  // 1-product (Qhi*Khi)
        const uint32_t kst = (uint32_t)((j & 1) * 36864);
#pragma unroll
        for (int kk = 0; kk < 4; kk++) {
            uint32_t a[2][4];
#pragma unroll
            for (int mi = 0; mi < 2; mi++)
                LDSM4(a[mi], aBase + mi * 2304 + kk * 32);
            uint32_t bk[8][2];
#pragma unroll
            for (int np = 0; np < 4; np++) {
                uint32_t r4[4];
                LDSM4(r4, bBaseK + kst + np * 2304 + kk * 32);
                bk[2 * np][0] = r4[0]; bk[2 * np][1] = r4[1];
                bk[2 * np + 1][0] = r4[2]; bk[2 * np + 1][1] = r4[3];
            }
#pragma unroll
            for (int mi = 0; mi < 2; mi++)
#pragma unroll
                for (int ni = 0; ni < 8; ni++)
                    mma16816(s[mi][ni], a[mi], bk[ni]);
        }
    };

    loadQ(); loadK(0); loadV(0); CP_ASYNC_COMMIT();
    loadK(1); loadV(1); CP_ASYNC_COMMIT();

    for (int j = 0; j < 16; j++) {
        if (j < 15) { CP_ASYNC_WAIT1(); } else { CP_ASYNC_WAIT0(); }
        __syncthreads();

        float s[2][8][4];
#pragma unroll
        for (int mi = 0; mi < 2; mi++)
#pragma unroll
            for (int ni = 0; ni < 8; ni++)
#pragma unroll
                for (int q = 0; q < 4; q++) s[mi][ni][q] = 0.f;
        computeS(j, s);

        const uint32_t vst = (uint32_t)((j & 1) * 34816);
#pragma unroll
        for (int kk = 0; kk < 4; kk++) {
            uint32_t bv[2][8][2];
#pragma unroll
            for (int pl = 0; pl < 2; pl++)
#pragma unroll
                for (int np = 0; np < 4; np++) {
                    uint32_t r4[4];
                    LDSM4(r4, bBaseV + vst + pl * 17408 + np * 4352 + kk * 32);
                    bv[pl][2 * np][0] = r4[0]; bv[pl][2 * np][1] = r4[1];
                    bv[pl][2 * np + 1][0] = r4[2]; bv[pl][2 * np + 1][1] = r4[3];
                }
#pragma unroll
            for (int mi = 0; mi < 2; mi++) {
                const int e = 2 * kk, o = 2 * kk + 1;
                float pe0 = __expf(s[mi][e][0] * 0.03125f);
                float pe1 = __expf(s[mi][e][1] * 0.03125f);
                float pe2 = __expf(s[mi][e][2] * 0.03125f);
                float pe3 = __expf(s[mi][e][3] * 0.03125f);
                float po0 = __expf(s[mi][o][0] * 0.03125f);
                float po1 = __expf(s[mi][o][1] * 0.03125f);
                float po2 = __expf(s[mi][o][2] * 0.03125f);
                float po3 = __expf(s[mi][o][3] * 0.03125f);
                rs[mi * 2 + 0] += pe0 + pe1 + po0 + po1;
                rs[mi * 2 + 1] += pe2 + pe3 + po2 + po3;
                uint32_t ah[4], al[4];
                ah[0] = pack2(pe0, pe1); ah[1] = pack2(pe2, pe3);
                ah[2] = pack2(po0, po1); ah[3] = pack2(po2, po3);
                __nv_bfloat162* hb = (__nv_bfloat162*)ah;
                al[0] = pack2(pe0 - __low2float(hb[0]), pe1 - __high2float(hb[0]));
                al[1] = pack2(pe2 - __low2float(hb[1]), pe3 - __high2float(hb[1]));
                al[2] = pack2(po0 - __low2float(hb[2]), po1 - __high2float(hb[2]));
                al[3] = pack2(po2 - __low2float(hb[3]), po3 - __high2float(hb[3]));
#pragma unroll
                for (int nd = 0; nd < 8; nd++) {
                    mma16816(ctx[mi][nd], ah, bv[0][nd]);
                    mma16816(ctx[mi][nd], ah, bv[1][nd]);
                    mma16816(ctx[mi][nd], al, bv[0][nd]);
                }
            }
        }
        __syncthreads();
        if (j + 2 < 16) { loadK(j + 2); loadV(j + 2); CP_ASYNC_COMMIT(); }
    }

#pragma unroll
    for (int i = 0; i < 4; i++) {
        rs[i] += __shfl_xor_sync(0xffffffffu, rs[i], 1);
        rs[i] += __shfl_xor_sync(0xffffffffu, rs[i], 2);
    }
    float* redp = (float*)(sm + FA_OFF_RED);
    float* invp = (float*)(sm + FA_OFF_RED + 1024);
    if ((lane & 3) == 0) {
#pragma unroll
        for (int mi = 0; mi < 2; mi++) {
            redp[wn * 128 + wm * 32 + mi * 16 + rl]     = rs[mi * 2 + 0];
            redp[wn * 128 + wm * 32 + mi * 16 + rl + 8] = rs[mi * 2 + 1];
        }
    }
    __syncthreads();
    if (tid < 128) invp[tid] = 1.0f / (redp[tid] + redp[128 + tid]);
    __syncthreads();

    float* credp = (float*)(sm + FA_OFF_V);
    if (wn == 1) {
#pragma unroll
        for (int mi = 0; mi < 2; mi++) {
            const int r = wm * 32 + mi * 16 + rl;
#pragma unroll
            for (int nd = 0; nd < 8; nd++) {
                const int c = nd * 8 + (lane & 3) * 2;
                *(float2*)(credp + r * 64 + c)       = make_float2(ctx[mi][nd][0], ctx[mi][nd][1]);
                *(float2*)(credp + (r + 8) * 64 + c) = make_float2(ctx[mi][nd][2], ctx[mi][nd][3]);
            }
        }
    }
    __syncthreads();
    if (wn == 0) {
#pragma unroll
        for (int mi = 0; mi < 2; mi++) {
            const int r = wm * 32 + mi * 16 + rl;
            const float i0 = invp[r], i1 = invp[r + 8];
#pragma unroll
            for (int nd = 0; nd < 8; nd++) {
                const int c = nd * 8 + (lane & 3) * 2;
                float2 p0 = *(float2*)(credp + r * 64 + c);
                float2 p1 = *(float2*)(credp + (r + 8) * 64 + c);
                float v00 = (ctx[mi][nd][0] + p0.x) * i0;
                float v01 = (ctx[mi][nd][1] + p0.y) * i0;
                float v10 = (ctx[mi][nd][2] + p1.x) * i1;
                float v11 = (ctx[mi][nd][3] + p1.y) * i1;
                size_t o0 = (size_t)(q0 + r) * EMB + h * 64 + c;
                size_t o1 = (size_t)(q0 + r + 8) * EMB + h * 64 + c;
                uint32_t h0 = pack2(v00, v01), h1 = pack2(v10, v11);
                __nv_bfloat162 hb0 = *(__nv_bfloat162*)&h0;
                __nv_bfloat162 hb1 = *(__nv_bfloat162*)&h1;
                uint32_t l0 = pack2(v00 - __low2float(hb0), v01 - __high2float(hb0));
                uint32_t l1 = pack2(v10 - __low2float(hb1), v11 - __high2float(hb1));
                *(uint32_t*)(chi + o0) = h0;
                *(uint32_t*)(chi + o1) = h1;
                *(uint32_t*)(clo + o0) = l0;
                *(uint32_t*)(clo + o1) = l1;
            }
        }
    }
    __syncthreads();

    loadK_hi(0); CP_ASYNC_COMMIT();
    loadK_hi(1); CP_ASYNC_COMMIT();
    for (int j = 0; j < 16; j++) {
        if (j < 15) { CP_ASYNC_WAIT1(); } else { CP_ASYNC_WAIT0(); }
        __syncthreads();

        float s[2][8][4];
#pragma unroll
        for (int mi = 0; mi < 2; mi++)
#pragma unroll
            for (int ni = 0; ni < 8; ni++)
#pragma unroll
                for (int q = 0; q < 4; q++) s[mi][ni][q] = 0.f;
        computeS2(j, s);

#pragma unroll
        for (int mi = 0; mi < 2; mi++) {
            const int r = wm * 32 + mi * 16 + rl;
            const float i0 = invp[r], i1 = invp[r + 8];
#pragma unroll
            for (int ni = 0; ni < 8; ni++) {
                const int c = wn * 64 + ni * 8 + (lane & 3) * 2;
                float2 v0 = make_float2(__expf(s[mi][ni][0] * 0.03125f) * i0,
                                        __expf(s[mi][ni][1] * 0.03125f) * i0);
                float2 v1 = make_float2(__expf(s[mi][ni][2] * 0.03125f) * i1,
                                        __expf(s[mi][ni][3] * 0.03125f) * i1);
                size_t base = ((size_t)h * SEQ + q0 + r) * (size_t)SEQ + j * 128 + c;
                *(float2*)(attn + base) = v0;
                *(float2*)(attn + base + 8 * SEQ) = v1;
            }
        }
        __syncthreads();
        if (j + 2 < 16) { loadK_hi(j + 2); CP_ASYNC_COMMIT(); }
    }
}

// ============================ host launch ============================
static constexpr int SMEM3 = 3 * (2 * 256 * 80 + 2 * 64 * 80);  // 153600

extern "C" void kernel_launch(void* const* d_in, const int* in_sizes, int n_in,
                              void* d_out, int out_size)
{
    const float* x  = (const float*)d_in[0];
    const float* Wq = (const float*)d_in[1];
    const float* bq = (const float*)d_in[2];
    const float* Wk = (const float*)d_in[3];
    const float* bk = (const float*)d_in[4];
    const float* Wv = (const float*)d_in[5];
    const float* bv = (const float*)d_in[6];
    const float* Wo = (const float*)d_in[7];
    const float* bo = (const float*)d_in[8];

    float* out  = (float*)d_out;
    float* attn = out + (size_t)SEQ * EMB;

#define SYM(p, s) void* p##_v; cudaGetSymbolAddress(&p##_v, s);
    SYM(Vf, g_Vf)
    SYM(xhi, g_xhi) SYM(xlo, g_xlo)
    SYM(Qhi, g_Qhi) SYM(Qlo, g_Qlo) SYM(Khi, g_Khi) SYM(Klo, g_Klo)
    SYM(Vthi, g_Vthi) SYM(Vtlo, g_Vtlo)
    SYM(chi, g_chi) SYM(clo, g_clo)
#undef SYM
#define BF(p) ((__nv_bfloat16*)p##_v)
#define FL(p) ((float*)p##_v)

    cudaFuncSetAttribute(proj_gemm, cudaFuncAttributeMaxDynamicSharedMemorySize, SMEM3);
    cudaFuncSetAttribute(attention_fused, cudaFuncAttributeMaxDynamicSharedMemorySize, FA_SMEM);

    const int nSE = SEQ * EMB;

    split_pair<<<nSE / 256, 256>>>(x, BF(xhi), BF(xlo), nSE);

    // QKV in one launch (z selects weight/output); BM=256 x BN=64 tiles
    proj_gemm<<<dim3(EMB / 64, SEQ / 256, 3), 256, SMEM3>>>(
        BF(xhi), BF(xlo), Wq, Wk, Wv, bq, bk, bv,
        BF(Qhi), BF(Qlo), BF(Khi), BF(Klo), FL(Vf), 0);

    transpose_split<<<dim3(EMB / 32, SEQ / 32), dim3(32, 8)>>>(FL(Vf), BF(Vthi), BF(Vtlo));

    // fused attention: scores + softmax + ctx, attn written once
    attention_fused<<<dim3(SEQ / 128, NH), 256, FA_SMEM>>>(
        BF(Qhi), BF(Qlo), BF(Khi), BF(Klo), BF(Vthi), BF(Vtlo),
        attn, BF(chi), BF(clo));

    // out = ctx @ Wo^T + bo
    proj_gemm<<<dim3(EMB / 64, SEQ / 256, 1), 256, SMEM3>>>(
        BF(chi), BF(clo), Wo, nullptr, nullptr, bo, nullptr, nullptr,
        nullptr, nullptr, nullptr, nullptr, out, 1);
#undef BF
#undef FL
}

// round 10
// speedup vs baseline: 3.5246x; 1.0583x over previous
#include <cuda_runtime.h>
#include <cuda_bf16.h>
#include <cstdint>
#include <math.h>

#define SEQ 2048
#define EMB 1024
#define NH  16
#define HD  64

// ============================ helpers ============================
#define CP_ASYNC16(dst, src) \
    asm volatile("cp.async.cg.shared.global [%0], [%1], 16;" :: "r"(dst), "l"(src) : "memory")
#define CP_ASYNC_COMMIT() asm volatile("cp.async.commit_group;" ::: "memory")
#define CP_ASYNC_WAIT0()  asm volatile("cp.async.wait_group 0;" ::: "memory")
#define CP_ASYNC_WAIT1()  asm volatile("cp.async.wait_group 1;" ::: "memory")

#define LDSM4(r, addr) \
    asm volatile("ldmatrix.sync.aligned.m8n8.x4.shared.b16 {%0,%1,%2,%3}, [%4];" \
        : "=r"((r)[0]), "=r"((r)[1]), "=r"((r)[2]), "=r"((r)[3]) : "r"(addr))

__device__ __forceinline__ void mma16816(float* d, const uint32_t* a, const uint32_t* b) {
    asm volatile(
        "mma.sync.aligned.m16n8k16.row.col.f32.bf16.bf16.f32 "
        "{%0,%1,%2,%3}, {%4,%5,%6,%7}, {%8,%9}, {%0,%1,%2,%3};"
        : "+f"(d[0]), "+f"(d[1]), "+f"(d[2]), "+f"(d[3])
        : "r"(a[0]), "r"(a[1]), "r"(a[2]), "r"(a[3]), "r"(b[0]), "r"(b[1]));
}

__device__ __forceinline__ uint32_t pack2(float x, float y) {
    __nv_bfloat162 t = __floats2bfloat162_rn(x, y);
    return *(uint32_t*)&t;
}

// ============================ device scratch ============================
__device__ __align__(256) float g_Vf[SEQ * EMB];
__device__ __align__(256) float g_invsum[NH * SEQ];

__device__ __align__(256) __nv_bfloat16 g_xhi[SEQ * EMB],  g_xlo[SEQ * EMB];
__device__ __align__(256) __nv_bfloat16 g_Qhi[SEQ * EMB],  g_Qlo[SEQ * EMB];   // [NH][SEQ][64]
__device__ __align__(256) __nv_bfloat16 g_Khi[SEQ * EMB],  g_Klo[SEQ * EMB];   // [NH][SEQ][64]
__device__ __align__(256) __nv_bfloat16 g_Vthi[EMB * SEQ], g_Vtlo[EMB * SEQ];  // V^T [EMB][SEQ]
__device__ __align__(256) __nv_bfloat16 g_chi[SEQ * EMB],  g_clo[SEQ * EMB];   // ctx [SEQ][EMB]

// ============================ split / transpose ============================
__global__ __launch_bounds__(256)
void split_pair(const float* __restrict__ src, __nv_bfloat16* __restrict__ hi,
                __nv_bfloat16* __restrict__ lo, int n)
{
    int i = blockIdx.x * 256 + threadIdx.x;
    if (i < n) {
        float v = src[i];
        __nv_bfloat16 h = __float2bfloat16(v);
        hi[i] = h;
        lo[i] = __float2bfloat16(v - __bfloat162float(h));
    }
}

__global__ __launch_bounds__(256)
void transpose_split(const float* __restrict__ V, __nv_bfloat16* __restrict__ hi,
                     __nv_bfloat16* __restrict__ lo)
{
    __shared__ float t[32][33];
    int e0 = blockIdx.x * 32, s0 = blockIdx.y * 32;
    int tx = threadIdx.x, ty = threadIdx.y;  // 32 x 8
#pragma unroll
    for (int i = 0; i < 32; i += 8)
        t[ty + i][tx] = V[(size_t)(s0 + ty + i) * EMB + e0 + tx];
    __syncthreads();
#pragma unroll
    for (int i = 0; i < 32; i += 8) {
        float v = t[tx][ty + i];
        size_t o = (size_t)(e0 + ty + i) * SEQ + s0 + tx;
        __nv_bfloat16 hh = __float2bfloat16(v);
        hi[o] = hh;
        lo[o] = __float2bfloat16(v - __bfloat162float(hh));
    }
}

// ============================ split-bf16 HMMA NT projection GEMM ============================
// BM=256, BN=64 tiles. kind 0 (QKV): z selects {Wq,Wk,Wv}; kind 1 (Wo).
__global__ __launch_bounds__(256, 1)
void proj_gemm(const __nv_bfloat16* __restrict__ Ahi, const __nv_bfloat16* __restrict__ Alo,
               const float* __restrict__ W0, const float* __restrict__ W1,
               const float* __restrict__ W2,
               const float* __restrict__ b0, const float* __restrict__ b1,
               const float* __restrict__ b2,
               __nv_bfloat16* __restrict__ P0hi, __nv_bfloat16* __restrict__ P0lo,
               __nv_bfloat16* __restrict__ P1hi, __nv_bfloat16* __restrict__ P1lo,
               float* __restrict__ Cf, int kind)
{
    constexpr int APLANE = 256 * 80;   // 20480
    constexpr int BPLANE = 64 * 80;    // 5120
    constexpr int STAGE  = 2 * APLANE + 2 * BPLANE;  // 51200
    constexpr int NC = EMB / 32;       // 32

    extern __shared__ char dsm[];
    const uint32_t smem0 = (uint32_t)__cvta_generic_to_shared(dsm);

    const int tid  = threadIdx.x;
    const int wid  = tid >> 5;
    const int lane = tid & 31;
    const int wm = wid & 3;
    const int wn = wid >> 2;
    const int rl = lane >> 2;

    const int z = blockIdx.z;
    const float* Bf   = (z == 0) ? W0 : (z == 1) ? W1 : W2;
    const float* bias = (z == 0) ? b0 : (z == 1) ? b1 : b2;
    const int mode = (kind == 1 || z == 2) ? 0 : 2;
    __nv_bfloat16* Chi = (z == 0) ? P0hi : P1hi;
    __nv_bfloat16* Clo = (z == 0) ? P0lo : P1lo;

    const int row0 = blockIdx.y * 256;
    const int col0 = blockIdx.x * 64;

    float acc[4][4][4];
#pragma unroll
    for (int mi = 0; mi < 4; mi++)
#pragma unroll
        for (int ni = 0; ni < 4; ni++)
#pragma unroll
            for (int j = 0; j < 4; j++) acc[mi][ni][j] = 0.f;

    auto load_A = [&](int c) {
        const uint32_t sb = smem0 + (c % 3) * STAGE;
        for (int i = tid; i < 2048; i += 256) {
            int pl = i >> 10;
            int rem = i & 1023;
            int r = rem >> 2, g = rem & 3;
            const __nv_bfloat16* src =
                (pl ? Alo : Ahi) + (size_t)(row0 + r) * EMB + c * 32 + g * 8;
            CP_ASYNC16(sb + pl * APLANE + r * 80 + g * 16, src);
        }
        CP_ASYNC_COMMIT();
    };

    float4 breg[2];
    const int br = tid >> 2;
    const int bseg = (tid & 3) * 8;
    auto ldg_B = [&](int c) {
        const float* src = Bf + (size_t)(col0 + br) * EMB + c * 32 + bseg;
        breg[0] = *(const float4*)(src);
        breg[1] = *(const float4*)(src + 4);
    };
    auto sts_B = [&](int c) {
        const uint32_t off = (uint32_t)((c % 3) * STAGE + 2 * APLANE + br * 80 + bseg * 2);
        uint4 hi4, lo4;
        uint32_t* h = (uint32_t*)&hi4;
        uint32_t* l = (uint32_t*)&lo4;
        float4 v0 = breg[0], v1 = breg[1];
        h[0] = pack2(v0.x, v0.y); h[1] = pack2(v0.z, v0.w);
        h[2] = pack2(v1.x, v1.y); h[3] = pack2(v1.z, v1.w);
        __nv_bfloat162* hb = (__nv_bfloat162*)h;
        l[0] = pack2(v0.x - __low2float(hb[0]), v0.y - __high2float(hb[0]));
        l[1] = pack2(v0.z - __low2float(hb[1]), v0.w - __high2float(hb[1]));
        l[2] = pack2(v1.x - __low2float(hb[2]), v1.y - __high2float(hb[2]));
        l[3] = pack2(v1.z - __low2float(hb[3]), v1.w - __high2float(hb[3]));
        *(uint4*)(dsm + off) = hi4;
        *(uint4*)(dsm + off + BPLANE) = lo4;
    };

    auto compute = [&](int c) {
        const uint32_t sb = smem0 + (c % 3) * STAGE;
        const uint32_t aAddr = sb + (wm * 64 + (lane & 15)) * 80 + (lane >> 4) * 16;
        const uint32_t bAddr = sb + 2 * APLANE
            + (wn * 32 + (lane >> 4) * 8 + (lane & 7)) * 80 + ((lane >> 3) & 1) * 16;
#pragma unroll
        for (int kk = 0; kk < 2; kk++) {
            uint32_t a[2][4][4];
#pragma unroll
            for (int pl = 0; pl < 2; pl++)
#pragma unroll
                for (int mi = 0; mi < 4; mi++)
                    LDSM4(a[pl][mi], aAddr + pl * APLANE + mi * 16 * 80 + kk * 32);
            uint32_t b[2][4][2];
#pragma unroll
            for (int pl = 0; pl < 2; pl++)
#pragma unroll
                for (int np = 0; np < 2; np++) {
                    uint32_t r4[4];
                    LDSM4(r4, bAddr + pl * BPLANE + np * 16 * 80 + kk * 32);
                    b[pl][2 * np][0] = r4[0]; b[pl][2 * np][1] = r4[1];
                    b[pl][2 * np + 1][0] = r4[2]; b[pl][2 * np + 1][1] = r4[3];
                }
#pragma unroll
            for (int mi = 0; mi < 4; mi++)
#pragma unroll
                for (int ni = 0; ni < 4; ni++) {
                    mma16816(acc[mi][ni], a[0][mi], b[0][ni]);
                    mma16816(acc[mi][ni], a[0][mi], b[1][ni]);
                    mma16816(acc[mi][ni], a[1][mi], b[0][ni]);
                }
        }
    };

    ldg_B(0); sts_B(0); load_A(0);
    ldg_B(1); sts_B(1); load_A(1);
    ldg_B(2);

    for (int c = 0; c < NC; c++) {
        if (c + 1 < NC) { CP_ASYNC_WAIT1(); } else { CP_ASYNC_WAIT0(); }
        __syncthreads();
        compute(c);
        if (c + 2 < NC) {
            sts_B(c + 2);
            load_A(c + 2);
            if (c + 3 < NC) ldg_B(c + 3);
        }
    }

    const int cl = (lane & 3) * 2;
#pragma unroll
    for (int mi = 0; mi < 4; mi++) {
        const int r = row0 + wm * 64 + mi * 16 + rl;
#pragma unroll
        for (int ni = 0; ni < 4; ni++) {
            const int cc = col0 + wn * 32 + ni * 8 + cl;
            const float bb0 = bias[cc], bb1 = bias[cc + 1];
            float v00 = acc[mi][ni][0] + bb0;
            float v01 = acc[mi][ni][1] + bb1;
            float v10 = acc[mi][ni][2] + bb0;
            float v11 = acc[mi][ni][3] + bb1;
            if (mode == 0) {
                *(float2*)(Cf + (size_t)r * EMB + cc) = make_float2(v00, v01);
                *(float2*)(Cf + (size_t)(r + 8) * EMB + cc) = make_float2(v10, v11);
            } else {
                size_t o0 = (size_t)(cc >> 6) * ((size_t)SEQ * 64) + (size_t)r * 64 + (cc & 63);
                size_t o1 = o0 + 8 * 64;
                uint32_t h0 = pack2(v00, v01), h1 = pack2(v10, v11);
                __nv_bfloat162 hb0 = *(__nv_bfloat162*)&h0;
                __nv_bfloat162 hb1 = *(__nv_bfloat162*)&h1;
                uint32_t l0 = pack2(v00 - __low2float(hb0), v01 - __high2float(hb0));
                uint32_t l1 = pack2(v10 - __low2float(hb1), v11 - __high2float(hb1));
                *(uint32_t*)(Chi + o0) = h0;
                *(uint32_t*)(Chi + o1) = h1;
                *(uint32_t*)(Clo + o0) = l0;
                *(uint32_t*)(Clo + o1) = l1;
            }
        }
    }
}

// ============================ attention phase 1 ============================
// S = Qhi@(Khi+Klo)^T /32 (2-product), P=exp(S), rowsum->g_invsum, ctx += P@V.
// smem: Qhi 18432 | K 2 stages x 36864 | V 2 stages x 34816 | red 1536
static constexpr int FA_OFF_K   = 18432;
static constexpr int FA_OFF_V   = 92160;
static constexpr int FA_OFF_RED = 161792;
static constexpr int FA_SMEM    = 163328;

__global__ __launch_bounds__(256, 1)
void attention_phase1(const __nv_bfloat16* __restrict__ Qhi,
                      const __nv_bfloat16* __restrict__ Khi, const __nv_bfloat16* __restrict__ Klo,
                      const __nv_bfloat16* __restrict__ Vthi, const __nv_bfloat16* __restrict__ Vtlo,
                      float* __restrict__ invsum,
                      __nv_bfloat16* __restrict__ chi, __nv_bfloat16* __restrict__ clo)
{
    extern __shared__ char sm[];
    const uint32_t sb = (uint32_t)__cvta_generic_to_shared(sm);

    const int tid  = threadIdx.x;
    const int lane = tid & 31, wid = tid >> 5;
    const int wm = wid & 3, wn = wid >> 2;
    const int rl = lane >> 2;
    const int h  = blockIdx.y;
    const int q0 = blockIdx.x * 128;

    auto loadQ = [&]() {
        for (int i = tid; i < 1024; i += 256) {
            int r = i >> 3, g = i & 7;
            const __nv_bfloat16* src = Qhi + ((size_t)h * SEQ + q0 + r) * 64 + g * 8;
            CP_ASYNC16(sb + r * 144 + g * 16, src);
        }
    };
    auto loadK = [&](int j) {
        int st = (j & 1) * 36864;
        for (int i = tid; i < 2048; i += 256) {
            int pl = i >> 10, rem = i & 1023, r = rem >> 3, g = rem & 7;
            const __nv_bfloat16* src = (pl ? Klo : Khi) + ((size_t)h * SEQ + j * 128 + r) * 64 + g * 8;
            CP_ASYNC16(sb + FA_OFF_K + st + pl * 18432 + r * 144 + g * 16, src);
        }
    };
    auto loadV = [&](int j) {
        int st = (j & 1) * 34816;
        for (int i = tid; i < 2048; i += 256) {
            int pl = i >> 10, rem = i & 1023, d = rem >> 4, g = rem & 15;
            const __nv_bfloat16* src = (pl ? Vtlo : Vthi) + ((size_t)(h * 64 + d)) * SEQ + j * 128 + g * 8;
            CP_ASYNC16(sb + FA_OFF_V + st + pl * 17408 + d * 272 + g * 16, src);
        }
    };

    const uint32_t aBase  = sb + (wm * 32 + (lane & 15)) * 144 + (lane >> 4) * 16;
    const uint32_t bBaseK = sb + FA_OFF_K + (wn * 64 + (lane >> 4) * 8 + (lane & 7)) * 144
                            + ((lane >> 3) & 1) * 16;
    const uint32_t bBaseV = sb + FA_OFF_V + ((lane >> 4) * 8 + (lane & 7)) * 272
                            + ((lane >> 3) & 1) * 16 + wn * 128;

    float ctx[2][8][4];
#pragma unroll
    for (int mi = 0; mi < 2; mi++)
#pragma unroll
        for (int nd = 0; nd < 8; nd++)
#pragma unroll
            for (int j = 0; j < 4; j++) ctx[mi][nd][j] = 0.f;
    float rs[4] = {0.f, 0.f, 0.f, 0.f};

    loadQ(); loadK(0); loadV(0); CP_ASYNC_COMMIT();
    loadK(1); loadV(1); CP_ASYNC_COMMIT();

    for (int j = 0; j < 16; j++) {
        if (j < 15) { CP_ASYNC_WAIT1(); } else { CP_ASYNC_WAIT0(); }
        __syncthreads();

        float s[2][8][4];
#pragma unroll
        for (int mi = 0; mi < 2; mi++)
#pragma unroll
            for (int ni = 0; ni < 8; ni++)
#pragma unroll
                for (int q = 0; q < 4; q++) s[mi][ni][q] = 0.f;

        // S: 2-product (Qhi*Khi + Qhi*Klo)
        const uint32_t kst = (uint32_t)((j & 1) * 36864);
#pragma unroll
        for (int kk = 0; kk < 4; kk++) {
            uint32_t a[2][4];
#pragma unroll
            for (int mi = 0; mi < 2; mi++)
                LDSM4(a[mi], aBase + mi * 2304 + kk * 32);
            uint32_t bk[2][8][2];
#pragma unroll
            for (int pl = 0; pl < 2; pl++)
#pragma unroll
                for (int np = 0; np < 4; np++) {
                    uint32_t r4[4];
                    LDSM4(r4, bBaseK + kst + pl * 18432 + np * 2304 + kk * 32);
                    bk[pl][2 * np][0] = r4[0]; bk[pl][2 * np][1] = r4[1];
                    bk[pl][2 * np + 1][0] = r4[2]; bk[pl][2 * np + 1][1] = r4[3];
                }
#pragma unroll
            for (int mi = 0; mi < 2; mi++)
#pragma unroll
                for (int ni = 0; ni < 8; ni++) {
                    mma16816(s[mi][ni], a[mi], bk[0][ni]);
                    mma16816(s[mi][ni], a[mi], bk[1][ni]);
                }
        }

        // PV
        const uint32_t vst = (uint32_t)((j & 1) * 34816);
#pragma unroll
        for (int kk = 0; kk < 4; kk++) {
            uint32_t bv[2][8][2];
#pragma unroll
            for (int pl = 0; pl < 2; pl++)
#pragma unroll
                for (int np = 0; np < 4; np++) {
                    uint32_t r4[4];
                    LDSM4(r4, bBaseV + vst + pl * 17408 + np * 4352 + kk * 32);
                    bv[pl][2 * np][0] = r4[0]; bv[pl][2 * np][1] = r4[1];
                    bv[pl][2 * np + 1][0] = r4[2]; bv[pl][2 * np + 1][1] = r4[3];
                }
#pragma unroll
            for (int mi = 0; mi < 2; mi++) {
                const int e = 2 * kk, o = 2 * kk + 1;
                float pe0 = __expf(s[mi][e][0] * 0.03125f);
                float pe1 = __expf(s[mi][e][1] * 0.03125f);
                float pe2 = __expf(s[mi][e][2] * 0.03125f);
                float pe3 = __expf(s[mi][e][3] * 0.03125f);
                float po0 = __expf(s[mi][o][0] * 0.03125f);
                float po1 = __expf(s[mi][o][1] * 0.03125f);
                float po2 = __expf(s[mi][o][2] * 0.03125f);
                float po3 = __expf(s[mi][o][3] * 0.03125f);
                rs[mi * 2 + 0] += pe0 + pe1 + po0 + po1;
                rs[mi * 2 + 1] += pe2 + pe3 + po2 + po3;
                uint32_t ah[4], al[4];
                ah[0] = pack2(pe0, pe1); ah[1] = pack2(pe2, pe3);
                ah[2] = pack2(po0, po1); ah[3] = pack2(po2, po3);
                __nv_bfloat162* hb = (__nv_bfloat162*)ah;
                al[0] = pack2(pe0 - __low2float(hb[0]), pe1 - __high2float(hb[0]));
                al[1] = pack2(pe2 - __low2float(hb[1]), pe3 - __high2float(hb[1]));
                al[2] = pack2(po0 - __low2float(hb[2]), po1 - __high2float(hb[2]));
                al[3] = pack2(po2 - __low2float(hb[3]), po3 - __high2float(hb[3]));
#pragma unroll
                for (int nd = 0; nd < 8; nd++) {
                    mma16816(ctx[mi][nd], ah, bv[0][nd]);
                    mma16816(ctx[mi][nd], ah, bv[1][nd]);
                    mma16816(ctx[mi][nd], al, bv[0][nd]);
                }
            }
        }
        __syncthreads();
        if (j + 2 < 16) { loadK(j + 2); loadV(j + 2); CP_ASYNC_COMMIT(); }
    }

#pragma unroll
    for (int i = 0; i < 4; i++) {
        rs[i] += __shfl_xor_sync(0xffffffffu, rs[i], 1);
        rs[i] += __shfl_xor_sync(0xffffffffu, rs[i], 2);
    }
    float* redp = (float*)(sm + FA_OFF_RED);
    float* invp = (float*)(sm + FA_OFF_RED + 1024);
    if ((lane & 3) == 0) {
#pragma unroll
        for (int mi = 0; mi < 2; mi++) {
            redp[wn * 128 + wm * 32 + mi * 16 + rl]     = rs[mi * 2 + 0];
            redp[wn * 128 + wm * 32 + mi * 16 + rl + 8] = rs[mi * 2 + 1];
        }
    }
    __syncthreads();
    if (tid < 128) {
        float inv = 1.0f / (redp[tid] + redp[128 + tid]);
        invp[tid] = inv;
        invsum[(size_t)h * SEQ + q0 + tid] = inv;
    }
    __syncthreads();

    float* credp = (float*)(sm + FA_OFF_V);
    if (wn == 1) {
#pragma unroll
        for (int mi = 0; mi < 2; mi++) {
            const int r = wm * 32 + mi * 16 + rl;
#pragma unroll
            for (int nd = 0; nd < 8; nd++) {
                const int c = nd * 8 + (lane & 3) * 2;
                *(float2*)(credp + r * 64 + c)       = make_float2(ctx[mi][nd][0], ctx[mi][nd][1]);
                *(float2*)(credp + (r + 8) * 64 + c) = make_float2(ctx[mi][nd][2], ctx[mi][nd][3]);
            }
        }
    }
    __syncthreads();
    if (wn == 0) {
#pragma unroll
        for (int mi = 0; mi < 2; mi++) {
            const int r = wm * 32 + mi * 16 + rl;
            const float i0 = invp[r], i1 = invp[r + 8];
#pragma unroll
            for (int nd = 0; nd < 8; nd++) {
                const int c = nd * 8 + (lane & 3) * 2;
                float2 p0 = *(float2*)(credp + r * 64 + c);
                float2 p1 = *(float2*)(credp + (r + 8) * 64 + c);
                float v00 = (ctx[mi][nd][0] + p0.x) * i0;
                float v01 = (ctx[mi][nd][1] + p0.y) * i0;
                float v10 = (ctx[mi][nd][2] + p1.x) * i1;
                float v11 = (ctx[mi][nd][3] + p1.y) * i1;
                size_t o0 = (size_t)(q0 + r) * EMB + h * 64 + c;
                size_t o1 = (size_t)(q0 + r + 8) * EMB + h * 64 + c;
                uint32_t h0 = pack2(v00, v01), h1 = pack2(v10, v11);
                __nv_bfloat162 hb0 = *(__nv_bfloat162*)&h0;
                __nv_bfloat162 hb1 = *(__nv_bfloat162*)&h1;
                uint32_t l0 = pack2(v00 - __low2float(hb0), v01 - __high2float(hb0));
                uint32_t l1 = pack2(v10 - __low2float(hb1), v11 - __high2float(hb1));
                *(uint32_t*)(chi + o0) = h0;
                *(uint32_t*)(chi + o1) = h1;
                *(uint32_t*)(clo + o0) = l0;
                *(uint32_t*)(clo + o1) = l1;
            }
        }
    }
}

// ============================ attention phase 2 ============================
// Recompute S with Qhi*Khi only; write exp(S)*inv_sum to attn. High occupancy.
static constexpr int P2_OFF_K   = 18432;
static constexpr int P2_OFF_INV = 55296;
static constexpr int P2_SMEM    = 55808;

__global__ __launch_bounds__(256)
void attention_phase2(const __nv_bfloat16* __restrict__ Qhi,
                      const __nv_bfloat16* __restrict__ Khi,
                      const float* __restrict__ invsum,
                      float* __restrict__ attn)
{
    extern __shared__ char sm[];
    const uint32_t sb = (uint32_t)__cvta_generic_to_shared(sm);

    const int tid  = threadIdx.x;
    const int lane = tid & 31, wid = tid >> 5;
    const int wm = wid & 3, wn = wid >> 2;
    const int rl = lane >> 2;
    const int h  = blockIdx.y;
    const int q0 = blockIdx.x * 128;

    float* invp = (float*)(sm + P2_OFF_INV);
    if (tid < 128) invp[tid] = invsum[(size_t)h * SEQ + q0 + tid];

    auto loadQ = [&]() {
        for (int i = tid; i < 1024; i += 256) {
            int r = i >> 3, g = i & 7;
            const __nv_bfloat16* src = Qhi + ((size_t)h * SEQ + q0 + r) * 64 + g * 8;
            CP_ASYNC16(sb + r * 144 + g * 16, src);
        }
    };
    auto loadK = [&](int j) {
        int st = (j & 1) * 18432;
        for (int i = tid; i < 1024; i += 256) {
            int r = i >> 3, g = i & 7;
            const __nv_bfloat16* src = Khi + ((size_t)h * SEQ + j * 128 + r) * 64 + g * 8;
            CP_ASYNC16(sb + P2_OFF_K + st + r * 144 + g * 16, src);
        }
    };

    const uint32_t aBase  = sb + (wm * 32 + (lane & 15)) * 144 + (lane >> 4) * 16;
    const uint32_t bBaseK = sb + P2_OFF_K + (wn * 64 + (lane >> 4) * 8 + (lane & 7)) * 144
                            + ((lane >> 3) & 1) * 16;

    loadQ(); loadK(0); CP_ASYNC_COMMIT();
    loadK(1); CP_ASYNC_COMMIT();

    for (int j = 0; j < 16; j++) {
        if (j < 15) { CP_ASYNC_WAIT1(); } else { CP_ASYNC_WAIT0(); }
        __syncthreads();

        float s[2][8][4];
#pragma unroll
        for (int mi = 0; mi < 2; mi++)
#pragma unroll
            for (int ni = 0; ni < 8; ni++)
#pragma unroll
                for (int q = 0; q < 4; q++) s[mi][ni][q] = 0.f;

        const uint32_t kst = (uint32_t)((j & 1) * 18432);
#pragma unroll
        for (int kk = 0; kk < 4; kk++) {
            uint32_t a[2][4];
#pragma unroll
            for (int mi = 0; mi < 2; mi++)
                LDSM4(a[mi], aBase + mi * 2304 + kk * 32);
            uint32_t bk[8][2];
#pragma unroll
            for (int np = 0; np < 4; np++) {
                uint32_t r4[4];
                LDSM4(r4, bBaseK + kst + np * 2304 + kk * 32);
                bk[2 * np][0] = r4[0]; bk[2 * np][1] = r4[1];
                bk[2 * np + 1][0] = r4[2]; bk[2 * np + 1][1] = r4[3];
            }
#pragma unroll
            for (int mi = 0; mi < 2; mi++)
#pragma unroll
                for (int ni = 0; ni < 8; ni++)
                    mma16816(s[mi][ni], a[mi], bk[ni]);
        }

#pragma unroll
        for (int mi = 0; mi < 2; mi++) {
            const int r = wm * 32 + mi * 16 + rl;
            const float i0 = invp[r], i1 = invp[r + 8];
#pragma unroll
            for (int ni = 0; ni < 8; ni++) {
                const int c = wn * 64 + ni * 8 + (lane & 3) * 2;
                float2 v0 = make_float2(__expf(s[mi][ni][0] * 0.03125f) * i0,
                                        __expf(s[mi][ni][1] * 0.03125f) * i0);
                float2 v1 = make_float2(__expf(s[mi][ni][2] * 0.03125f) * i1,
                                        __expf(s[mi][ni][3] * 0.03125f) * i1);
                size_t base = ((size_t)h * SEQ + q0 + r) * (size_t)SEQ + j * 128 + c;
                *(float2*)(attn + base) = v0;
                *(float2*)(attn + base + 8 * SEQ) = v1;
            }
        }
        __syncthreads();
        if (j + 2 < 16) { loadK(j + 2); CP_ASYNC_COMMIT(); }
    }
}

// ============================ host launch ============================
static constexpr int SMEM3 = 3 * (2 * 256 * 80 + 2 * 64 * 80);  // 153600

extern "C" void kernel_launch(void* const* d_in, const int* in_sizes, int n_in,
                              void* d_out, int out_size)
{
    const float* x  = (const float*)d_in[0];
    const float* Wq = (const float*)d_in[1];
    const float* bq = (const float*)d_in[2];
    const float* Wk = (const float*)d_in[3];
    const float* bk = (const float*)d_in[4];
    const float* Wv = (const float*)d_in[5];
    const float* bv = (const float*)d_in[6];
    const float* Wo = (const float*)d_in[7];
    const float* bo = (const float*)d_in[8];

    float* out  = (float*)d_out;
    float* attn = out + (size_t)SEQ * EMB;

#define SYM(p, s) void* p##_v; cudaGetSymbolAddress(&p##_v, s);
    SYM(Vf, g_Vf) SYM(invs, g_invsum)
    SYM(xhi, g_xhi) SYM(xlo, g_xlo)
    SYM(Qhi, g_Qhi) SYM(Qlo, g_Qlo) SYM(Khi, g_Khi) SYM(Klo, g_Klo)
    SYM(Vthi, g_Vthi) SYM(Vtlo, g_Vtlo)
    SYM(chi, g_chi) SYM(clo, g_clo)
#undef SYM
#define BF(p) ((__nv_bfloat16*)p##_v)
#define FL(p) ((float*)p##_v)

    cudaFuncSetAttribute(proj_gemm, cudaFuncAttributeMaxDynamicSharedMemorySize, SMEM3);
    cudaFuncSetAttribute(attention_phase1, cudaFuncAttributeMaxDynamicSharedMemorySize, FA_SMEM);
    cudaFuncSetAttribute(attention_phase2, cudaFuncAttributeMaxDynamicSharedMemorySize, P2_SMEM);

    const int nSE = SEQ * EMB;

    split_pair<<<nSE / 256, 256>>>(x, BF(xhi), BF(xlo), nSE);

    // QKV in one launch; BM=256 x BN=64 tiles
    proj_gemm<<<dim3(EMB / 64, SEQ / 256, 3), 256, SMEM3>>>(
        BF(xhi), BF(xlo), Wq, Wk, Wv, bq, bk, bv,
        BF(Qhi), BF(Qlo), BF(Khi), BF(Klo), FL(Vf), 0);

    transpose_split<<<dim3(EMB / 32, SEQ / 32), dim3(32, 8)>>>(FL(Vf), BF(Vthi), BF(Vtlo));

    // attention phase 1: softmax stats + ctx
    attention_phase1<<<dim3(SEQ / 128, NH), 256, FA_SMEM>>>(
        BF(Qhi), BF(Khi), BF(Klo), BF(Vthi), BF(Vtlo),
        FL(invs), BF(chi), BF(clo));

    // out = ctx @ Wo^T + bo
    proj_gemm<<<dim3(EMB / 64, SEQ / 256, 1), 256, SMEM3>>>(
        BF(chi), BF(clo), Wo, nullptr, nullptr, bo, nullptr, nullptr,
        nullptr, nullptr, nullptr, nullptr, out, 1);

    // attention phase 2: write normalized attn (high occupancy, store-bound)
    attention_phase2<<<dim3(SEQ / 128, NH), 256, P2_SMEM>>>(
        BF(Qhi), BF(Khi), FL(invs), attn);
#undef BF
#undef FL
}

// round 11
// speedup vs baseline: 4.0374x; 1.1455x over previous
#include <cuda_runtime.h>
#include <cuda_bf16.h>
#include <cuda_fp16.h>
#include <cstdint>
#include <math.h>

#define SEQ 2048
#define EMB 1024
#define NH  16
#define HD  64

// ============================ helpers ============================
#define CP_ASYNC16(dst, src) \
    asm volatile("cp.async.cg.shared.global [%0], [%1], 16;" :: "r"(dst), "l"(src) : "memory")
#define CP_ASYNC_COMMIT() asm volatile("cp.async.commit_group;" ::: "memory")
#define CP_ASYNC_WAIT0()  asm volatile("cp.async.wait_group 0;" ::: "memory")
#define CP_ASYNC_WAIT1()  asm volatile("cp.async.wait_group 1;" ::: "memory")

#define LDSM4(r, addr) \
    asm volatile("ldmatrix.sync.aligned.m8n8.x4.shared.b16 {%0,%1,%2,%3}, [%4];" \
        : "=r"((r)[0]), "=r"((r)[1]), "=r"((r)[2]), "=r"((r)[3]) : "r"(addr))

__device__ __forceinline__ void mma16816(float* d, const uint32_t* a, const uint32_t* b) {
    asm volatile(
        "mma.sync.aligned.m16n8k16.row.col.f32.bf16.bf16.f32 "
        "{%0,%1,%2,%3}, {%4,%5,%6,%7}, {%8,%9}, {%0,%1,%2,%3};"
        : "+f"(d[0]), "+f"(d[1]), "+f"(d[2]), "+f"(d[3])
        : "r"(a[0]), "r"(a[1]), "r"(a[2]), "r"(a[3]), "r"(b[0]), "r"(b[1]));
}

__device__ __forceinline__ void mma16816h(float* d, const uint32_t* a, const uint32_t* b) {
    asm volatile(
        "mma.sync.aligned.m16n8k16.row.col.f32.f16.f16.f32 "
        "{%0,%1,%2,%3}, {%4,%5,%6,%7}, {%8,%9}, {%0,%1,%2,%3};"
        : "+f"(d[0]), "+f"(d[1]), "+f"(d[2]), "+f"(d[3])
        : "r"(a[0]), "r"(a[1]), "r"(a[2]), "r"(a[3]), "r"(b[0]), "r"(b[1]));
}

__device__ __forceinline__ uint32_t pack2(float x, float y) {
    __nv_bfloat162 t = __floats2bfloat162_rn(x, y);
    return *(uint32_t*)&t;
}
__device__ __forceinline__ uint32_t hpack2(float x, float y) {
    __half2 t = __floats2half2_rn(x, y);
    return *(uint32_t*)&t;
}

// ============================ device scratch ============================
__device__ __align__(256) float g_Vf[SEQ * EMB];
__device__ __align__(256) float g_invsum[NH * SEQ];

__device__ __align__(256) __nv_bfloat16 g_xhi[SEQ * EMB],  g_xlo[SEQ * EMB];
__device__ __align__(256) __nv_bfloat16 g_Qhi[SEQ * EMB];                      // [NH][SEQ][64]
__device__ __align__(256) __nv_bfloat16 g_Khi[SEQ * EMB];                      // [NH][SEQ][64]
__device__ __align__(256) __half        g_Vt16[EMB * SEQ];                     // V^T [EMB][SEQ] fp16
__device__ __align__(256) __nv_bfloat16 g_chi[SEQ * EMB],  g_clo[SEQ * EMB];   // ctx [SEQ][EMB]

// ============================ split / transpose ============================
__global__ __launch_bounds__(256)
void split_pair(const float* __restrict__ src, __nv_bfloat16* __restrict__ hi,
                __nv_bfloat16* __restrict__ lo, int n)
{
    int i = blockIdx.x * 256 + threadIdx.x;
    if (i < n) {
        float v = src[i];
        __nv_bfloat16 h = __float2bfloat16(v);
        hi[i] = h;
        lo[i] = __float2bfloat16(v - __bfloat162float(h));
    }
}

__global__ __launch_bounds__(256)
void transpose_f16(const float* __restrict__ V, __half* __restrict__ out)
{
    __shared__ float t[32][33];
    int e0 = blockIdx.x * 32, s0 = blockIdx.y * 32;
    int tx = threadIdx.x, ty = threadIdx.y;  // 32 x 8
#pragma unroll
    for (int i = 0; i < 32; i += 8)
        t[ty + i][tx] = V[(size_t)(s0 + ty + i) * EMB + e0 + tx];
    __syncthreads();
#pragma unroll
    for (int i = 0; i < 32; i += 8) {
        size_t o = (size_t)(e0 + ty + i) * SEQ + s0 + tx;
        out[o] = __float2half(t[tx][ty + i]);
    }
}

// ============================ split-bf16 HMMA NT projection GEMM ============================
// BM=256, BN=64. kind 0 (QKV): z in {Wq->Qhi packed, Wk->Khi packed, Wv->fp32}; kind 1 (Wo).
__global__ __launch_bounds__(256, 1)
void proj_gemm(const __nv_bfloat16* __restrict__ Ahi, const __nv_bfloat16* __restrict__ Alo,
               const float* __restrict__ W0, const float* __restrict__ W1,
               const float* __restrict__ W2,
               const float* __restrict__ b0, const float* __restrict__ b1,
               const float* __restrict__ b2,
               __nv_bfloat16* __restrict__ P0hi, __nv_bfloat16* __restrict__ P1hi,
               float* __restrict__ Cf, int kind)
{
    constexpr int APLANE = 256 * 80;
    constexpr int BPLANE = 64 * 80;
    constexpr int STAGE  = 2 * APLANE + 2 * BPLANE;  // 51200
    constexpr int NC = EMB / 32;

    extern __shared__ char dsm[];
    const uint32_t smem0 = (uint32_t)__cvta_generic_to_shared(dsm);

    const int tid  = threadIdx.x;
    const int wid  = tid >> 5;
    const int lane = tid & 31;
    const int wm = wid & 3;
    const int wn = wid >> 2;
    const int rl = lane >> 2;

    const int z = blockIdx.z;
    const float* Bf   = (z == 0) ? W0 : (z == 1) ? W1 : W2;
    const float* bias = (z == 0) ? b0 : (z == 1) ? b1 : b2;
    const int mode = (kind == 1 || z == 2) ? 0 : 2;
    __nv_bfloat16* Chi = (z == 0) ? P0hi : P1hi;

    const int row0 = blockIdx.y * 256;
    const int col0 = blockIdx.x * 64;

    float acc[4][4][4];
#pragma unroll
    for (int mi = 0; mi < 4; mi++)
#pragma unroll
        for (int ni = 0; ni < 4; ni++)
#pragma unroll
            for (int j = 0; j < 4; j++) acc[mi][ni][j] = 0.f;

    auto load_A = [&](int c) {
        const uint32_t sb = smem0 + (c % 3) * STAGE;
        for (int i = tid; i < 2048; i += 256) {
            int pl = i >> 10;
            int rem = i & 1023;
            int r = rem >> 2, g = rem & 3;
            const __nv_bfloat16* src =
                (pl ? Alo : Ahi) + (size_t)(row0 + r) * EMB + c * 32 + g * 8;
            CP_ASYNC16(sb + pl * APLANE + r * 80 + g * 16, src);
        }
        CP_ASYNC_COMMIT();
    };

    float4 breg[2];
    const int br = tid >> 2;
    const int bseg = (tid & 3) * 8;
    auto ldg_B = [&](int c) {
        const float* src = Bf + (size_t)(col0 + br) * EMB + c * 32 + bseg;
        breg[0] = *(const float4*)(src);
        breg[1] = *(const float4*)(src + 4);
    };
    auto sts_B = [&](int c) {
        const uint32_t off = (uint32_t)((c % 3) * STAGE + 2 * APLANE + br * 80 + bseg * 2);
        uint4 hi4, lo4;
        uint32_t* h = (uint32_t*)&hi4;
        uint32_t* l = (uint32_t*)&lo4;
        float4 v0 = breg[0], v1 = breg[1];
        h[0] = pack2(v0.x, v0.y); h[1] = pack2(v0.z, v0.w);
        h[2] = pack2(v1.x, v1.y); h[3] = pack2(v1.z, v1.w);
        __nv_bfloat162* hb = (__nv_bfloat162*)h;
        l[0] = pack2(v0.x - __low2float(hb[0]), v0.y - __high2float(hb[0]));
        l[1] = pack2(v0.z - __low2float(hb[1]), v0.w - __high2float(hb[1]));
        l[2] = pack2(v1.x - __low2float(hb[2]), v1.y - __high2float(hb[2]));
        l[3] = pack2(v1.z - __low2float(hb[3]), v1.w - __high2float(hb[3]));
        *(uint4*)(dsm + off) = hi4;
        *(uint4*)(dsm + off + BPLANE) = lo4;
    };

    auto compute = [&](int c) {
        const uint32_t sb = smem0 + (c % 3) * STAGE;
        const uint32_t aAddr = sb + (wm * 64 + (lane & 15)) * 80 + (lane >> 4) * 16;
        const uint32_t bAddr = sb + 2 * APLANE
            + (wn * 32 + (lane >> 4) * 8 + (lane & 7)) * 80 + ((lane >> 3) & 1) * 16;
#pragma unroll
        for (int kk = 0; kk < 2; kk++) {
            uint32_t a[2][4][4];
#pragma unroll
            for (int pl = 0; pl < 2; pl++)
#pragma unroll
                for (int mi = 0; mi < 4; mi++)
                    LDSM4(a[pl][mi], aAddr + pl * APLANE + mi * 16 * 80 + kk * 32);
            uint32_t b[2][4][2];
#pragma unroll
            for (int pl = 0; pl < 2; pl++)
#pragma unroll
                for (int np = 0; np < 2; np++) {
                    uint32_t r4[4];
                    LDSM4(r4, bAddr + pl * BPLANE + np * 16 * 80 + kk * 32);
                    b[pl][2 * np][0] = r4[0]; b[pl][2 * np][1] = r4[1];
                    b[pl][2 * np + 1][0] = r4[2]; b[pl][2 * np + 1][1] = r4[3];
                }
#pragma unroll
            for (int mi = 0; mi < 4; mi++)
#pragma unroll
                for (int ni = 0; ni < 4; ni++) {
                    mma16816(acc[mi][ni], a[0][mi], b[0][ni]);
                    mma16816(acc[mi][ni], a[0][mi], b[1][ni]);
                    mma16816(acc[mi][ni], a[1][mi], b[0][ni]);
                }
        }
    };

    ldg_B(0); sts_B(0); load_A(0);
    ldg_B(1); sts_B(1); load_A(1);
    ldg_B(2);

    for (int c = 0; c < NC; c++) {
        if (c + 1 < NC) { CP_ASYNC_WAIT1(); } else { CP_ASYNC_WAIT0(); }
        __syncthreads();
        compute(c);
        if (c + 2 < NC) {
            sts_B(c + 2);
            load_A(c + 2);
            if (c + 3 < NC) ldg_B(c + 3);
        }
    }

    const int cl = (lane & 3) * 2;
#pragma unroll
    for (int mi = 0; mi < 4; mi++) {
        const int r = row0 + wm * 64 + mi * 16 + rl;
#pragma unroll
        for (int ni = 0; ni < 4; ni++) {
            const int cc = col0 + wn * 32 + ni * 8 + cl;
            const float bb0 = bias[cc], bb1 = bias[cc + 1];
            float v00 = acc[mi][ni][0] + bb0;
            float v01 = acc[mi][ni][1] + bb1;
            float v10 = acc[mi][ni][2] + bb0;
            float v11 = acc[mi][ni][3] + bb1;
            if (mode == 0) {
                *(float2*)(Cf + (size_t)r * EMB + cc) = make_float2(v00, v01);
                *(float2*)(Cf + (size_t)(r + 8) * EMB + cc) = make_float2(v10, v11);
            } else {
                // packed [NH][SEQ][64], hi plane only
                size_t o0 = (size_t)(cc >> 6) * ((size_t)SEQ * 64) + (size_t)r * 64 + (cc & 63);
                size_t o1 = o0 + 8 * 64;
                *(uint32_t*)(Chi + o0) = pack2(v00, v01);
                *(uint32_t*)(Chi + o1) = pack2(v10, v11);
            }
        }
    }
}

// ============================ attention phase 1 ============================
// S = Qhi@Khi^T /32 (hh only, == phase2 S), P=exp(S), rowsum->g_invsum,
// ctx += P@V with P as fp16 hi+lo, V single fp16 plane.
// smem: Qhi 18432 | K 2x18432 | V 2x17408 | red 1536  -> 91648
static constexpr int FA_OFF_K   = 18432;
static constexpr int FA_OFF_V   = 55296;
static constexpr int FA_OFF_RED = 90112;
static constexpr int FA_SMEM    = 91648;

__global__ __launch_bounds__(256, 1)
void attention_phase1(const __nv_bfloat16* __restrict__ Qhi,
                      const __nv_bfloat16* __restrict__ Khi,
                      const __half* __restrict__ Vt16,
                      float* __restrict__ invsum,
                      __nv_bfloat16* __restrict__ chi, __nv_bfloat16* __restrict__ clo)
{
    extern __shared__ char sm[];
    const uint32_t sb = (uint32_t)__cvta_generic_to_shared(sm);

    const int tid  = threadIdx.x;
    const int lane = tid & 31, wid = tid >> 5;
    const int wm = wid & 3, wn = wid >> 2;
    const int rl = lane >> 2;
    const int h  = blockIdx.y;
    const int q0 = blockIdx.x * 128;

    auto loadQ = [&]() {
        for (int i = tid; i < 1024; i += 256) {
            int r = i >> 3, g = i & 7;
            const __nv_bfloat16* src = Qhi + ((size_t)h * SEQ + q0 + r) * 64 + g * 8;
            CP_ASYNC16(sb + r * 144 + g * 16, src);
        }
    };
    auto loadK = [&](int j) {
        int st = (j & 1) * 18432;
        for (int i = tid; i < 1024; i += 256) {
            int r = i >> 3, g = i & 7;
            const __nv_bfloat16* src = Khi + ((size_t)h * SEQ + j * 128 + r) * 64 + g * 8;
            CP_ASYNC16(sb + FA_OFF_K + st + r * 144 + g * 16, src);
        }
    };
    auto loadV = [&](int j) {
        int st = (j & 1) * 17408;
        for (int i = tid; i < 1024; i += 256) {
            int d = i >> 4, g = i & 15;
            const __half* src = Vt16 + ((size_t)(h * 64 + d)) * SEQ + j * 128 + g * 8;
            CP_ASYNC16(sb + FA_OFF_V + st + d * 272 + g * 16, src);
        }
    };

    const uint32_t aBase  = sb + (wm * 32 + (lane & 15)) * 144 + (lane >> 4) * 16;
    const uint32_t bBaseK = sb + FA_OFF_K + (wn * 64 + (lane >> 4) * 8 + (lane & 7)) * 144
                            + ((lane >> 3) & 1) * 16;
    const uint32_t bBaseV = sb + FA_OFF_V + ((lane >> 4) * 8 + (lane & 7)) * 272
                            + ((lane >> 3) & 1) * 16 + wn * 128;

    float ctx[2][8][4];
#pragma unroll
    for (int mi = 0; mi < 2; mi++)
#pragma unroll
        for (int nd = 0; nd < 8; nd++)
#pragma unroll
            for (int j = 0; j < 4; j++) ctx[mi][nd][j] = 0.f;
    float rs[4] = {0.f, 0.f, 0.f, 0.f};

    loadQ(); loadK(0); loadV(0); CP_ASYNC_COMMIT();
    loadK(1); loadV(1); CP_ASYNC_COMMIT();

    for (int j = 0; j < 16; j++) {
        if (j < 15) { CP_ASYNC_WAIT1(); } else { CP_ASYNC_WAIT0(); }
        __syncthreads();

        float s[2][8][4];
#pragma unroll
        for (int mi = 0; mi < 2; mi++)
#pragma unroll
            for (int ni = 0; ni < 8; ni++)
#pragma unroll
                for (int q = 0; q < 4; q++) s[mi][ni][q] = 0.f;

        // S: hh-only (identical to phase2)
        const uint32_t kst = (uint32_t)((j & 1) * 18432);
#pragma unroll
        for (int kk = 0; kk < 4; kk++) {
            uint32_t a[2][4];
#pragma unroll
            for (int mi = 0; mi < 2; mi++)
                LDSM4(a[mi], aBase + mi * 2304 + kk * 32);
            uint32_t bk[8][2];
#pragma unroll
            for (int np = 0; np < 4; np++) {
                uint32_t r4[4];
                LDSM4(r4, bBaseK + kst + np * 2304 + kk * 32);
                bk[2 * np][0] = r4[0]; bk[2 * np][1] = r4[1];
                bk[2 * np + 1][0] = r4[2]; bk[2 * np + 1][1] = r4[3];
            }
#pragma unroll
            for (int mi = 0; mi < 2; mi++)
#pragma unroll
                for (int ni = 0; ni < 8; ni++)
                    mma16816(s[mi][ni], a[mi], bk[ni]);
        }

        // PV: P fp16 hi+lo, V fp16 single plane
        const uint32_t vst = (uint32_t)((j & 1) * 17408);
#pragma unroll
        for (int kk = 0; kk < 4; kk++) {
            uint32_t bv[8][2];
#pragma unroll
            for (int np = 0; np < 4; np++) {
                uint32_t r4[4];
                LDSM4(r4, bBaseV + vst + np * 4352 + kk * 32);
                bv[2 * np][0] = r4[0]; bv[2 * np][1] = r4[1];
                bv[2 * np + 1][0] = r4[2]; bv[2 * np + 1][1] = r4[3];
            }
#pragma unroll
            for (int mi = 0; mi < 2; mi++) {
                const int e = 2 * kk, o = 2 * kk + 1;
                float pe0 = __expf(s[mi][e][0] * 0.03125f);
                float pe1 = __expf(s[mi][e][1] * 0.03125f);
                float pe2 = __expf(s[mi][e][2] * 0.03125f);
                float pe3 = __expf(s[mi][e][3] * 0.03125f);
                float po0 = __expf(s[mi][o][0] * 0.03125f);
                float po1 = __expf(s[mi][o][1] * 0.03125f);
                float po2 = __expf(s[mi][o][2] * 0.03125f);
                float po3 = __expf(s[mi][o][3] * 0.03125f);
                rs[mi * 2 + 0] += pe0 + pe1 + po0 + po1;
                rs[mi * 2 + 1] += pe2 + pe3 + po2 + po3;
                uint32_t ah[4], al[4];
                ah[0] = hpack2(pe0, pe1); ah[1] = hpack2(pe2, pe3);
                ah[2] = hpack2(po0, po1); ah[3] = hpack2(po2, po3);
                __half2* hh = (__half2*)ah;
                float2 f0 = __half22float2(hh[0]);
                float2 f1 = __half22float2(hh[1]);
                float2 f2 = __half22float2(hh[2]);
                float2 f3 = __half22float2(hh[3]);
                al[0] = hpack2(pe0 - f0.x, pe1 - f0.y);
                al[1] = hpack2(pe2 - f1.x, pe3 - f1.y);
                al[2] = hpack2(po0 - f2.x, po1 - f2.y);
                al[3] = hpack2(po2 - f3.x, po3 - f3.y);
#pragma unroll
                for (int nd = 0; nd < 8; nd++) {
                    mma16816h(ctx[mi][nd], ah, bv[nd]);
                    mma16816h(ctx[mi][nd], al, bv[nd]);
                }
            }
        }
        __syncthreads();
        if (j + 2 < 16) { loadK(j + 2); loadV(j + 2); CP_ASYNC_COMMIT(); }
    }

#pragma unroll
    for (int i = 0; i < 4; i++) {
        rs[i] += __shfl_xor_sync(0xffffffffu, rs[i], 1);
        rs[i] += __shfl_xor_sync(0xffffffffu, rs[i], 2);
    }
    float* redp = (float*)(sm + FA_OFF_RED);
    float* invp = (float*)(sm + FA_OFF_RED + 1024);
    if ((lane & 3) == 0) {
#pragma unroll
        for (int mi = 0; mi < 2; mi++) {
            redp[wn * 128 + wm * 32 + mi * 16 + rl]     = rs[mi * 2 + 0];
            redp[wn * 128 + wm * 32 + mi * 16 + rl + 8] = rs[mi * 2 + 1];
        }
    }
    __syncthreads();
    if (tid < 128) {
        float inv = 1.0f / (redp[tid] + redp[128 + tid]);
        invp[tid] = inv;
        invsum[(size_t)h * SEQ + q0 + tid] = inv;
    }
    __syncthreads();

    float* credp = (float*)(sm + FA_OFF_V);   // reuse V area (32KB needed, 34KB avail)
    if (wn == 1) {
#pragma unroll
        for (int mi = 0; mi < 2; mi++) {
            const int r = wm * 32 + mi * 16 + rl;
#pragma unroll
            for (int nd = 0; nd < 8; nd++) {
                const int c = nd * 8 + (lane & 3) * 2;
                *(float2*)(credp + r * 64 + c)       = make_float2(ctx[mi][nd][0], ctx[mi][nd][1]);
                *(float2*)(credp + (r + 8) * 64 + c) = make_float2(ctx[mi][nd][2], ctx[mi][nd][3]);
            }
        }
    }
    __syncthreads();
    if (wn == 0) {
#pragma unroll
        for (int mi = 0; mi < 2; mi++) {
            const int r = wm * 32 + mi * 16 + rl;
            const float i0 = invp[r], i1 = invp[r + 8];
#pragma unroll
            for (int nd = 0; nd < 8; nd++) {
                const int c = nd * 8 + (lane & 3) * 2;
                float2 p0 = *(float2*)(credp + r * 64 + c);
                float2 p1 = *(float2*)(credp + (r + 8) * 64 + c);
                float v00 = (ctx[mi][nd][0] + p0.x) * i0;
                float v01 = (ctx[mi][nd][1] + p0.y) * i0;
                float v10 = (ctx[mi][nd][2] + p1.x) * i1;
                float v11 = (ctx[mi][nd][3] + p1.y) * i1;
                size_t o0 = (size_t)(q0 + r) * EMB + h * 64 + c;
                size_t o1 = (size_t)(q0 + r + 8) * EMB + h * 64 + c;
                uint32_t h0 = pack2(v00, v01), h1 = pack2(v10, v11);
                __nv_bfloat162 hb0 = *(__nv_bfloat162*)&h0;
                __nv_bfloat162 hb1 = *(__nv_bfloat162*)&h1;
                uint32_t l0 = pack2(v00 - __low2float(hb0), v01 - __high2float(hb0));
                uint32_t l1 = pack2(v10 - __low2float(hb1), v11 - __high2float(hb1));
                *(uint32_t*)(chi + o0) = h0;
                *(uint32_t*)(chi + o1) = h1;
                *(uint32_t*)(clo + o0) = l0;
                *(uint32_t*)(clo + o1) = l1;
            }
        }
    }
}

// ============================ attention phase 2 ============================
static constexpr int P2_OFF_K   = 18432;
static constexpr int P2_OFF_INV = 55296;
static constexpr int P2_SMEM    = 55808;

__global__ __launch_bounds__(256)
void attention_phase2(const __nv_bfloat16* __restrict__ Qhi,
                      const __nv_bfloat16* __restrict__ Khi,
                      const float* __restrict__ invsum,
                      float* __restrict__ attn)
{
    extern __shared__ char sm[];
    const uint32_t sb = (uint32_t)__cvta_generic_to_shared(sm);

    const int tid  = threadIdx.x;
    const int lane = tid & 31, wid = tid >> 5;
    const int wm = wid & 3, wn = wid >> 2;
    const int rl = lane >> 2;
    const int h  = blockIdx.y;
    const int q0 = blockIdx.x * 128;

    float* invp = (float*)(sm + P2_OFF_INV);
    if (tid < 128) invp[tid] = invsum[(size_t)h * SEQ + q0 + tid];

    auto loadQ = [&]() {
        for (int i = tid; i < 1024; i += 256) {
            int r = i >> 3, g = i & 7;
            const __nv_bfloat16* src = Qhi + ((size_t)h * SEQ + q0 + r) * 64 + g * 8;
            CP_ASYNC16(sb + r * 144 + g * 16, src);
        }
    };
    auto loadK = [&](int j) {
        int st = (j & 1) * 18432;
        for (int i = tid; i < 1024; i += 256) {
            int r = i >> 3, g = i & 7;
            const __nv_bfloat16* src = Khi + ((size_t)h * SEQ + j * 128 + r) * 64 + g * 8;
            CP_ASYNC16(sb + P2_OFF_K + st + r * 144 + g * 16, src);
        }
    };

    const uint32_t aBase  = sb + (wm * 32 + (lane & 15)) * 144 + (lane >> 4) * 16;
    const uint32_t bBaseK = sb + P2_OFF_K + (wn * 64 + (lane >> 4) * 8 + (lane & 7)) * 144
                            + ((lane >> 3) & 1) * 16;

    loadQ(); loadK(0); CP_ASYNC_COMMIT();
    loadK(1); CP_ASYNC_COMMIT();

    for (int j = 0; j < 16; j++) {
        if (j < 15) { CP_ASYNC_WAIT1(); } else { CP_ASYNC_WAIT0(); }
        __syncthreads();

        float s[2][8][4];
#pragma unroll
        for (int mi = 0; mi < 2; mi++)
#pragma unroll
            for (int ni = 0; ni < 8; ni++)
#pragma unroll
                for (int q = 0; q < 4; q++) s[mi][ni][q] = 0.f;

        const uint32_t kst = (uint32_t)((j & 1) * 18432);
#pragma unroll
        for (int kk = 0; kk < 4; kk++) {
            uint32_t a[2][4];
#pragma unroll
            for (int mi = 0; mi < 2; mi++)
                LDSM4(a[mi], aBase + mi * 2304 + kk * 32);
            uint32_t bk[8][2];
#pragma unroll
            for (int np = 0; np < 4; np++) {
                uint32_t r4[4];
                LDSM4(r4, bBaseK + kst + np * 2304 + kk * 32);
                bk[2 * np][0] = r4[0]; bk[2 * np][1] = r4[1];
                bk[2 * np + 1][0] = r4[2]; bk[2 * np + 1][1] = r4[3];
            }
#pragma unroll
            for (int mi = 0; mi < 2; mi++)
#pragma unroll
                for (int ni = 0; ni < 8; ni++)
                    mma16816(s[mi][ni], a[mi], bk[ni]);
        }

#pragma unroll
        for (int mi = 0; mi < 2; mi++) {
            const int r = wm * 32 + mi * 16 + rl;
            const float i0 = invp[r], i1 = invp[r + 8];
#pragma unroll
            for (int ni = 0; ni < 8; ni++) {
                const int c = wn * 64 + ni * 8 + (lane & 3) * 2;
                float2 v0 = make_float2(__expf(s[mi][ni][0] * 0.03125f) * i0,
                                        __expf(s[mi][ni][1] * 0.03125f) * i0);
                float2 v1 = make_float2(__expf(s[mi][ni][2] * 0.03125f) * i1,
                                        __expf(s[mi][ni][3] * 0.03125f) * i1);
                size_t base = ((size_t)h * SEQ + q0 + r) * (size_t)SEQ + j * 128 + c;
                *(float2*)(attn + base) = v0;
                *(float2*)(attn + base + 8 * SEQ) = v1;
            }
        }
        __syncthreads();
        if (j + 2 < 16) { loadK(j + 2); CP_ASYNC_COMMIT(); }
    }
}

// ============================ host launch ============================
static constexpr int SMEM3 = 3 * (2 * 256 * 80 + 2 * 64 * 80);  // 153600

extern "C" void kernel_launch(void* const* d_in, const int* in_sizes, int n_in,
                              void* d_out, int out_size)
{
    const float* x  = (const float*)d_in[0];
    const float* Wq = (const float*)d_in[1];
    const float* bq = (const float*)d_in[2];
    const float* Wk = (const float*)d_in[3];
    const float* bk = (const float*)d_in[4];
    const float* Wv = (const float*)d_in[5];
    const float* bv = (const float*)d_in[6];
    const float* Wo = (const float*)d_in[7];
    const float* bo = (const float*)d_in[8];

    float* out  = (float*)d_out;
    float* attn = out + (size_t)SEQ * EMB;

#define SYM(p, s) void* p##_v; cudaGetSymbolAddress(&p##_v, s);
    SYM(Vf, g_Vf) SYM(invs, g_invsum)
    SYM(xhi, g_xhi) SYM(xlo, g_xlo)
    SYM(Qhi, g_Qhi) SYM(Khi, g_Khi) SYM(Vt16, g_Vt16)
    SYM(chi, g_chi) SYM(clo, g_clo)
#undef SYM
#define BF(p) ((__nv_bfloat16*)p##_v)
#define FL(p) ((float*)p##_v)

    cudaFuncSetAttribute(proj_gemm, cudaFuncAttributeMaxDynamicSharedMemorySize, SMEM3);
    cudaFuncSetAttribute(attention_phase1, cudaFuncAttributeMaxDynamicSharedMemorySize, FA_SMEM);
    cudaFuncSetAttribute(attention_phase2, cudaFuncAttributeMaxDynamicSharedMemorySize, P2_SMEM);

    const int nSE = SEQ * EMB;

    split_pair<<<nSE / 256, 256>>>(x, BF(xhi), BF(xlo), nSE);

    // QKV in one launch; BM=256 x BN=64 tiles
    proj_gemm<<<dim3(EMB / 64, SEQ / 256, 3), 256, SMEM3>>>(
        BF(xhi), BF(xlo), Wq, Wk, Wv, bq, bk, bv,
        BF(Qhi), BF(Khi), FL(Vf), 0);

    transpose_f16<<<dim3(EMB / 32, SEQ / 32), dim3(32, 8)>>>(FL(Vf), (__half*)Vt16_v);

    // attention phase 1: softmax stats + ctx
    attention_phase1<<<dim3(SEQ / 128, NH), 256, FA_SMEM>>>(
        BF(Qhi), BF(Khi), (const __half*)Vt16_v, FL(invs), BF(chi), BF(clo));

    // out = ctx @ Wo^T + bo
    proj_gemm<<<dim3(EMB / 64, SEQ / 256, 1), 256, SMEM3>>>(
        BF(chi), BF(clo), Wo, nullptr, nullptr, bo, nullptr, nullptr,
        nullptr, nullptr, out, 1);

    // attention phase 2: write normalized attn
    attention_phase2<<<dim3(SEQ / 128, NH), 256, P2_SMEM>>>(
        BF(Qhi), BF(Khi), FL(invs), attn);
#undef BF
#undef FL
}

// round 12
// speedup vs baseline: 4.5014x; 1.1149x over previous
#include <cuda_runtime.h>
#include <cuda_bf16.h>
#include <cuda_fp16.h>
#include <cstdint>
#include <math.h>

#define SEQ 2048
#define EMB 1024
#define NH  16
#define HD  64

// ============================ helpers ============================
#define CP_ASYNC16(dst, src) \
    asm volatile("cp.async.cg.shared.global [%0], [%1], 16;" :: "r"(dst), "l"(src) : "memory")
#define CP_ASYNC_COMMIT() asm volatile("cp.async.commit_group;" ::: "memory")
#define CP_ASYNC_WAIT0()  asm volatile("cp.async.wait_group 0;" ::: "memory")
#define CP_ASYNC_WAIT1()  asm volatile("cp.async.wait_group 1;" ::: "memory")

#define LDSM4(r, addr) \
    asm volatile("ldmatrix.sync.aligned.m8n8.x4.shared.b16 {%0,%1,%2,%3}, [%4];" \
        : "=r"((r)[0]), "=r"((r)[1]), "=r"((r)[2]), "=r"((r)[3]) : "r"(addr))

__device__ __forceinline__ void mma16816(float* d, const uint32_t* a, const uint32_t* b) {
    asm volatile(
        "mma.sync.aligned.m16n8k16.row.col.f32.bf16.bf16.f32 "
        "{%0,%1,%2,%3}, {%4,%5,%6,%7}, {%8,%9}, {%0,%1,%2,%3};"
        : "+f"(d[0]), "+f"(d[1]), "+f"(d[2]), "+f"(d[3])
        : "r"(a[0]), "r"(a[1]), "r"(a[2]), "r"(a[3]), "r"(b[0]), "r"(b[1]));
}

__device__ __forceinline__ void mma16816h(float* d, const uint32_t* a, const uint32_t* b) {
    asm volatile(
        "mma.sync.aligned.m16n8k16.row.col.f32.f16.f16.f32 "
        "{%0,%1,%2,%3}, {%4,%5,%6,%7}, {%8,%9}, {%0,%1,%2,%3};"
        : "+f"(d[0]), "+f"(d[1]), "+f"(d[2]), "+f"(d[3])
        : "r"(a[0]), "r"(a[1]), "r"(a[2]), "r"(a[3]), "r"(b[0]), "r"(b[1]));
}

__device__ __forceinline__ uint32_t pack2(float x, float y) {
    __nv_bfloat162 t = __floats2bfloat162_rn(x, y);
    return *(uint32_t*)&t;
}
__device__ __forceinline__ uint32_t hpack2(float x, float y) {
    __half2 t = __floats2half2_rn(x, y);
    return *(uint32_t*)&t;
}

// ============================ device scratch ============================
__device__ __align__(256) float g_Vf[SEQ * EMB];
__device__ __align__(256) float g_invsum[NH * SEQ];

__device__ __align__(256) __nv_bfloat16 g_xhi[SEQ * EMB],  g_xlo[SEQ * EMB];
__device__ __align__(256) __nv_bfloat16 g_Qhi[SEQ * EMB];                      // [NH][SEQ][64]
__device__ __align__(256) __nv_bfloat16 g_Khi[SEQ * EMB];                      // [NH][SEQ][64]
__device__ __align__(256) __half        g_Vt16[EMB * SEQ];                     // V^T [EMB][SEQ] fp16
__device__ __align__(256) __nv_bfloat16 g_chi[SEQ * EMB],  g_clo[SEQ * EMB];   // ctx [SEQ][EMB]

// ============================ split / transpose ============================
__global__ __launch_bounds__(256)
void split_pair(const float* __restrict__ src, __nv_bfloat16* __restrict__ hi,
                __nv_bfloat16* __restrict__ lo, int n)
{
    int i = blockIdx.x * 256 + threadIdx.x;
    if (i < n) {
        float v = src[i];
        __nv_bfloat16 h = __float2bfloat16(v);
        hi[i] = h;
        lo[i] = __float2bfloat16(v - __bfloat162float(h));
    }
}

__global__ __launch_bounds__(256)
void transpose_f16(const float* __restrict__ V, __half* __restrict__ out)
{
    __shared__ float t[32][33];
    int e0 = blockIdx.x * 32, s0 = blockIdx.y * 32;
    int tx = threadIdx.x, ty = threadIdx.y;  // 32 x 8
#pragma unroll
    for (int i = 0; i < 32; i += 8)
        t[ty + i][tx] = V[(size_t)(s0 + ty + i) * EMB + e0 + tx];
    __syncthreads();
#pragma unroll
    for (int i = 0; i < 32; i += 8) {
        size_t o = (size_t)(e0 + ty + i) * SEQ + s0 + tx;
        out[o] = __float2half(t[tx][ty + i]);
    }
}

// ============================ split-bf16 HMMA NT projection GEMM ============================
// BM=256, BN=64. kind 0 (QKV): z in {Wq->Qhi packed (2-prod), Wk->Khi packed (2-prod),
// Wv->fp32 (3-prod)}; kind 1 (Wo, 3-prod).
__global__ __launch_bounds__(256, 1)
void proj_gemm(const __nv_bfloat16* __restrict__ Ahi, const __nv_bfloat16* __restrict__ Alo,
               const float* __restrict__ W0, const float* __restrict__ W1,
               const float* __restrict__ W2,
               const float* __restrict__ b0, const float* __restrict__ b1,
               const float* __restrict__ b2,
               __nv_bfloat16* __restrict__ P0hi, __nv_bfloat16* __restrict__ P1hi,
               float* __restrict__ Cf, int kind)
{
    constexpr int APLANE = 256 * 80;
    constexpr int BPLANE = 64 * 80;
    constexpr int STAGE  = 2 * APLANE + 2 * BPLANE;  // 51200
    constexpr int NC = EMB / 32;

    extern __shared__ char dsm[];
    const uint32_t smem0 = (uint32_t)__cvta_generic_to_shared(dsm);

    const int tid  = threadIdx.x;
    const int wid  = tid >> 5;
    const int lane = tid & 31;
    const int wm = wid & 3;
    const int wn = wid >> 2;
    const int rl = lane >> 2;

    const int z = blockIdx.z;
    const float* Bf   = (z == 0) ? W0 : (z == 1) ? W1 : W2;
    const float* bias = (z == 0) ? b0 : (z == 1) ? b1 : b2;
    const int mode = (kind == 1 || z == 2) ? 0 : 2;
    const bool three = (kind == 1 || z == 2);   // full 3-product precision
    __nv_bfloat16* Chi = (z == 0) ? P0hi : P1hi;

    const int row0 = blockIdx.y * 256;
    const int col0 = blockIdx.x * 64;

    float acc[4][4][4];
#pragma unroll
    for (int mi = 0; mi < 4; mi++)
#pragma unroll
        for (int ni = 0; ni < 4; ni++)
#pragma unroll
            for (int j = 0; j < 4; j++) acc[mi][ni][j] = 0.f;

    const int nA = three ? 2048 : 1024;   // skip A-lo plane when 2-product
    auto load_A = [&](int c) {
        const uint32_t sb = smem0 + (c % 3) * STAGE;
        for (int i = tid; i < nA; i += 256) {
            int pl = i >> 10;
            int rem = i & 1023;
            int r = rem >> 2, g = rem & 3;
            const __nv_bfloat16* src =
                (pl ? Alo : Ahi) + (size_t)(row0 + r) * EMB + c * 32 + g * 8;
            CP_ASYNC16(sb + pl * APLANE + r * 80 + g * 16, src);
        }
        CP_ASYNC_COMMIT();
    };

    float4 breg[2];
    const int br = tid >> 2;
    const int bseg = (tid & 3) * 8;
    auto ldg_B = [&](int c) {
        const float* src = Bf + (size_t)(col0 + br) * EMB + c * 32 + bseg;
        breg[0] = *(const float4*)(src);
        breg[1] = *(const float4*)(src + 4);
    };
    auto sts_B = [&](int c) {
        const uint32_t off = (uint32_t)((c % 3) * STAGE + 2 * APLANE + br * 80 + bseg * 2);
        uint4 hi4, lo4;
        uint32_t* h = (uint32_t*)&hi4;
        uint32_t* l = (uint32_t*)&lo4;
        float4 v0 = breg[0], v1 = breg[1];
        h[0] = pack2(v0.x, v0.y); h[1] = pack2(v0.z, v0.w);
        h[2] = pack2(v1.x, v1.y); h[3] = pack2(v1.z, v1.w);
        __nv_bfloat162* hb = (__nv_bfloat162*)h;
        l[0] = pack2(v0.x - __low2float(hb[0]), v0.y - __high2float(hb[0]));
        l[1] = pack2(v0.z - __low2float(hb[1]), v0.w - __high2float(hb[1]));
        l[2] = pack2(v1.x - __low2float(hb[2]), v1.y - __high2float(hb[2]));
        l[3] = pack2(v1.z - __low2float(hb[3]), v1.w - __high2float(hb[3]));
        *(uint4*)(dsm + off) = hi4;
        *(uint4*)(dsm + off + BPLANE) = lo4;
    };

    auto compute = [&](int c) {
        const uint32_t sb = smem0 + (c % 3) * STAGE;
        const uint32_t aAddr = sb + (wm * 64 + (lane & 15)) * 80 + (lane >> 4) * 16;
        const uint32_t bAddr = sb + 2 * APLANE
            + (wn * 32 + (lane >> 4) * 8 + (lane & 7)) * 80 + ((lane >> 3) & 1) * 16;
#pragma unroll
        for (int kk = 0; kk < 2; kk++) {
            uint32_t a0[4][4], a1[4][4];
#pragma unroll
            for (int mi = 0; mi < 4; mi++)
                LDSM4(a0[mi], aAddr + mi * 16 * 80 + kk * 32);
            if (three) {
#pragma unroll
                for (int mi = 0; mi < 4; mi++)
                    LDSM4(a1[mi], aAddr + APLANE + mi * 16 * 80 + kk * 32);
            }
            uint32_t b[2][4][2];
#pragma unroll
            for (int pl = 0; pl < 2; pl++)
#pragma unroll
                for (int np = 0; np < 2; np++) {
                    uint32_t r4[4];
                    LDSM4(r4, bAddr + pl * BPLANE + np * 16 * 80 + kk * 32);
                    b[pl][2 * np][0] = r4[0]; b[pl][2 * np][1] = r4[1];
                    b[pl][2 * np + 1][0] = r4[2]; b[pl][2 * np + 1][1] = r4[3];
                }
#pragma unroll
            for (int mi = 0; mi < 4; mi++)
#pragma unroll
                for (int ni = 0; ni < 4; ni++) {
                    mma16816(acc[mi][ni], a0[mi], b[0][ni]);
                    mma16816(acc[mi][ni], a0[mi], b[1][ni]);
                }
            if (three) {
#pragma unroll
                for (int mi = 0; mi < 4; mi++)
#pragma unroll
                    for (int ni = 0; ni < 4; ni++)
                        mma16816(acc[mi][ni], a1[mi], b[0][ni]);
            }
        }
    };

    ldg_B(0); sts_B(0); load_A(0);
    ldg_B(1); sts_B(1); load_A(1);
    ldg_B(2);

    for (int c = 0; c < NC; c++) {
        if (c + 1 < NC) { CP_ASYNC_WAIT1(); } else { CP_ASYNC_WAIT0(); }
        __syncthreads();
        compute(c);
        if (c + 2 < NC) {
            sts_B(c + 2);
            load_A(c + 2);
            if (c + 3 < NC) ldg_B(c + 3);
        }
    }

    const int cl = (lane & 3) * 2;
#pragma unroll
    for (int mi = 0; mi < 4; mi++) {
        const int r = row0 + wm * 64 + mi * 16 + rl;
#pragma unroll
        for (int ni = 0; ni < 4; ni++) {
            const int cc = col0 + wn * 32 + ni * 8 + cl;
            const float bb0 = bias[cc], bb1 = bias[cc + 1];
            float v00 = acc[mi][ni][0] + bb0;
            float v01 = acc[mi][ni][1] + bb1;
            float v10 = acc[mi][ni][2] + bb0;
            float v11 = acc[mi][ni][3] + bb1;
            if (mode == 0) {
                *(float2*)(Cf + (size_t)r * EMB + cc) = make_float2(v00, v01);
                *(float2*)(Cf + (size_t)(r + 8) * EMB + cc) = make_float2(v10, v11);
            } else {
                size_t o0 = (size_t)(cc >> 6) * ((size_t)SEQ * 64) + (size_t)r * 64 + (cc & 63);
                size_t o1 = o0 + 8 * 64;
                *(uint32_t*)(Chi + o0) = pack2(v00, v01);
                *(uint32_t*)(Chi + o1) = pack2(v10, v11);
            }
        }
    }
}

// ============================ attention phase 1 ============================
// S = Qhi@Khi^T /32 (hh only, == phase2), P=exp(S) fp16 (single plane),
// rowsum->g_invsum, ctx += P@V with V single fp16 plane.
static constexpr int FA_OFF_K   = 18432;
static constexpr int FA_OFF_V   = 55296;
static constexpr int FA_OFF_RED = 90112;
static constexpr int FA_SMEM    = 91648;

__global__ __launch_bounds__(256, 1)
void attention_phase1(const __nv_bfloat16* __restrict__ Qhi,
                      const __nv_bfloat16* __restrict__ Khi,
                      const __half* __restrict__ Vt16,
                      float* __restrict__ invsum,
                      __nv_bfloat16* __restrict__ chi, __nv_bfloat16* __restrict__ clo)
{
    extern __shared__ char sm[];
    const uint32_t sb = (uint32_t)__cvta_generic_to_shared(sm);

    const int tid  = threadIdx.x;
    const int lane = tid & 31, wid = tid >> 5;
    const int wm = wid & 3, wn = wid >> 2;
    const int rl = lane >> 2;
    const int h  = blockIdx.y;
    const int q0 = blockIdx.x * 128;

    auto loadQ = [&]() {
        for (int i = tid; i < 1024; i += 256) {
            int r = i >> 3, g = i & 7;
            const __nv_bfloat16* src = Qhi + ((size_t)h * SEQ + q0 + r) * 64 + g * 8;
            CP_ASYNC16(sb + r * 144 + g * 16, src);
        }
    };
    auto loadK = [&](int j) {
        int st = (j & 1) * 18432;
        for (int i = tid; i < 1024; i += 256) {
            int r = i >> 3, g = i & 7;
            const __nv_bfloat16* src = Khi + ((size_t)h * SEQ + j * 128 + r) * 64 + g * 8;
            CP_ASYNC16(sb + FA_OFF_K + st + r * 144 + g * 16, src);
        }
    };
    auto loadV = [&](int j) {
        int st = (j & 1) * 17408;
        for (int i = tid; i < 1024; i += 256) {
            int d = i >> 4, g = i & 15;
            const __half* src = Vt16 + ((size_t)(h * 64 + d)) * SEQ + j * 128 + g * 8;
            CP_ASYNC16(sb + FA_OFF_V + st + d * 272 + g * 16, src);
        }
    };

    const uint32_t aBase  = sb + (wm * 32 + (lane & 15)) * 144 + (lane >> 4) * 16;
    const uint32_t bBaseK = sb + FA_OFF_K + (wn * 64 + (lane >> 4) * 8 + (lane & 7)) * 144
                            + ((lane >> 3) & 1) * 16;
    const uint32_t bBaseV = sb + FA_OFF_V + ((lane >> 4) * 8 + (lane & 7)) * 272
                            + ((lane >> 3) & 1) * 16 + wn * 128;

    float ctx[2][8][4];
#pragma unroll
    for (int mi = 0; mi < 2; mi++)
#pragma unroll
        for (int nd = 0; nd < 8; nd++)
#pragma unroll
            for (int j = 0; j < 4; j++) ctx[mi][nd][j] = 0.f;
    float rs[4] = {0.f, 0.f, 0.f, 0.f};

    loadQ(); loadK(0); loadV(0); CP_ASYNC_COMMIT();
    loadK(1); loadV(1); CP_ASYNC_COMMIT();

    for (int j = 0; j < 16; j++) {
        if (j < 15) { CP_ASYNC_WAIT1(); } else { CP_ASYNC_WAIT0(); }
        __syncthreads();

        float s[2][8][4];
#pragma unroll
        for (int mi = 0; mi < 2; mi++)
#pragma unroll
            for (int ni = 0; ni < 8; ni++)
#pragma unroll
                for (int q = 0; q < 4; q++) s[mi][ni][q] = 0.f;

        const uint32_t kst = (uint32_t)((j & 1) * 18432);
#pragma unroll
        for (int kk = 0; kk < 4; kk++) {
            uint32_t a[2][4];
#pragma unroll
            for (int mi = 0; mi < 2; mi++)
                LDSM4(a[mi], aBase + mi * 2304 + kk * 32);
            uint32_t bk[8][2];
#pragma unroll
            for (int np = 0; np < 4; np++) {
                uint32_t r4[4];
                LDSM4(r4, bBaseK + kst + np * 2304 + kk * 32);
                bk[2 * np][0] = r4[0]; bk[2 * np][1] = r4[1];
                bk[2 * np + 1][0] = r4[2]; bk[2 * np + 1][1] = r4[3];
            }
#pragma unroll
            for (int mi = 0; mi < 2; mi++)
#pragma unroll
                for (int ni = 0; ni < 8; ni++)
                    mma16816(s[mi][ni], a[mi], bk[ni]);
        }

        // PV: P single fp16 plane, V single fp16 plane
        const uint32_t vst = (uint32_t)((j & 1) * 17408);
#pragma unroll
        for (int kk = 0; kk < 4; kk++) {
            uint32_t bv[8][2];
#pragma unroll
            for (int np = 0; np < 4; np++) {
                uint32_t r4[4];
                LDSM4(r4, bBaseV + vst + np * 4352 + kk * 32);
                bv[2 * np][0] = r4[0]; bv[2 * np][1] = r4[1];
                bv[2 * np + 1][0] = r4[2]; bv[2 * np + 1][1] = r4[3];
            }
#pragma unroll
            for (int mi = 0; mi < 2; mi++) {
                const int e = 2 * kk, o = 2 * kk + 1;
                float pe0 = __expf(s[mi][e][0] * 0.03125f);
                float pe1 = __expf(s[mi][e][1] * 0.03125f);
                float pe2 = __expf(s[mi][e][2] * 0.03125f);
                float pe3 = __expf(s[mi][e][3] * 0.03125f);
                float po0 = __expf(s[mi][o][0] * 0.03125f);
                float po1 = __expf(s[mi][o][1] * 0.03125f);
                float po2 = __expf(s[mi][o][2] * 0.03125f);
                float po3 = __expf(s[mi][o][3] * 0.03125f);
                rs[mi * 2 + 0] += pe0 + pe1 + po0 + po1;
                rs[mi * 2 + 1] += pe2 + pe3 + po2 + po3;
                uint32_t ah[4];
                ah[0] = hpack2(pe0, pe1); ah[1] = hpack2(pe2, pe3);
                ah[2] = hpack2(po0, po1); ah[3] = hpack2(po2, po3);
#pragma unroll
                for (int nd = 0; nd < 8; nd++)
                    mma16816h(ctx[mi][nd], ah, bv[nd]);
            }
        }
        __syncthreads();
        if (j + 2 < 16) { loadK(j + 2); loadV(j + 2); CP_ASYNC_COMMIT(); }
    }

#pragma unroll
    for (int i = 0; i < 4; i++) {
        rs[i] += __shfl_xor_sync(0xffffffffu, rs[i], 1);
        rs[i] += __shfl_xor_sync(0xffffffffu, rs[i], 2);
    }
    float* redp = (float*)(sm + FA_OFF_RED);
    float* invp = (float*)(sm + FA_OFF_RED + 1024);
    if ((lane & 3) == 0) {
#pragma unroll
        for (int mi = 0; mi < 2; mi++) {
            redp[wn * 128 + wm * 32 + mi * 16 + rl]     = rs[mi * 2 + 0];
            redp[wn * 128 + wm * 32 + mi * 16 + rl + 8] = rs[mi * 2 + 1];
        }
    }
    __syncthreads();
    if (tid < 128) {
        float inv = 1.0f / (redp[tid] + redp[128 + tid]);
        invp[tid] = inv;
        invsum[(size_t)h * SEQ + q0 + tid] = inv;
    }
    __syncthreads();

    float* credp = (float*)(sm + FA_OFF_V);
    if (wn == 1) {
#pragma unroll
        for (int mi = 0; mi < 2; mi++) {
            const int r = wm * 32 + mi * 16 + rl;
#pragma unroll
            for (int nd = 0; nd < 8; nd++) {
                const int c = nd * 8 + (lane & 3) * 2;
                *(float2*)(credp + r * 64 + c)       = make_float2(ctx[mi][nd][0], ctx[mi][nd][1]);
                *(float2*)(credp + (r + 8) * 64 + c) = make_float2(ctx[mi][nd][2], ctx[mi][nd][3]);
            }
        }
    }
    __syncthreads();
    if (wn == 0) {
#pragma unroll
        for (int mi = 0; mi < 2; mi++) {
            const int r = wm * 32 + mi * 16 + rl;
            const float i0 = invp[r], i1 = invp[r + 8];
#pragma unroll
            for (int nd = 0; nd < 8; nd++) {
                const int c = nd * 8 + (lane & 3) * 2;
                float2 p0 = *(float2*)(credp + r * 64 + c);
                float2 p1 = *(float2*)(credp + (r + 8) * 64 + c);
                float v00 = (ctx[mi][nd][0] + p0.x) * i0;
                float v01 = (ctx[mi][nd][1] + p0.y) * i0;
                float v10 = (ctx[mi][nd][2] + p1.x) * i1;
                float v11 = (ctx[mi][nd][3] + p1.y) * i1;
                size_t o0 = (size_t)(q0 + r) * EMB + h * 64 + c;
                size_t o1 = (size_t)(q0 + r + 8) * EMB + h * 64 + c;
                uint32_t h0 = pack2(v00, v01), h1 = pack2(v10, v11);
                __nv_bfloat162 hb0 = *(__nv_bfloat162*)&h0;
                __nv_bfloat162 hb1 = *(__nv_bfloat162*)&h1;
                uint32_t l0 = pack2(v00 - __low2float(hb0), v01 - __high2float(hb0));
                uint32_t l1 = pack2(v10 - __low2float(hb1), v11 - __high2float(hb1));
                *(uint32_t*)(chi + o0) = h0;
                *(uint32_t*)(chi + o1) = h1;
                *(uint32_t*)(clo + o0) = l0;
                *(uint32_t*)(clo + o1) = l1;
            }
        }
    }
}

// ============================ attention phase 2 ============================
static constexpr int P2_OFF_K   = 18432;
static constexpr int P2_OFF_INV = 55296;
static constexpr int P2_SMEM    = 55808;

__global__ __launch_bounds__(256)
void attention_phase2(const __nv_bfloat16* __restrict__ Qhi,
                      const __nv_bfloat16* __restrict__ Khi,
                      const float* __restrict__ invsum,
                      float* __restrict__ attn)
{
    extern __shared__ char sm[];
    const uint32_t sb = (uint32_t)__cvta_generic_to_shared(sm);

    const int tid  = threadIdx.x;
    const int lane = tid & 31, wid = tid >> 5;
    const int wm = wid & 3, wn = wid >> 2;
    const int rl = lane >> 2;
    const int h  = blockIdx.y;
    const int q0 = blockIdx.x * 128;

    float* invp = (float*)(sm + P2_OFF_INV);
    if (tid < 128) invp[tid] = invsum[(size_t)h * SEQ + q0 + tid];

    auto loadQ = [&]() {
        for (int i = tid; i < 1024; i += 256) {
            int r = i >> 3, g = i & 7;
            const __nv_bfloat16* src = Qhi + ((size_t)h * SEQ + q0 + r) * 64 + g * 8;
            CP_ASYNC16(sb + r * 144 + g * 16, src);
        }
    };
    auto loadK = [&](int j) {
        int st = (j & 1) * 18432;
        for (int i = tid; i < 1024; i += 256) {
            int r = i >> 3, g = i & 7;
            const __nv_bfloat16* src = Khi + ((size_t)h * SEQ + j * 128 + r) * 64 + g * 8;
            CP_ASYNC16(sb + P2_OFF_K + st + r * 144 + g * 16, src);
        }
    };

    const uint32_t aBase  = sb + (wm * 32 + (lane & 15)) * 144 + (lane >> 4) * 16;
    const uint32_t bBaseK = sb + P2_OFF_K + (wn * 64 + (lane >> 4) * 8 + (lane & 7)) * 144
                            + ((lane >> 3) & 1) * 16;

    loadQ(); loadK(0); CP_ASYNC_COMMIT();
    loadK(1); CP_ASYNC_COMMIT();

    for (int j = 0; j < 16; j++) {
        if (j < 15) { CP_ASYNC_WAIT1(); } else { CP_ASYNC_WAIT0(); }
        __syncthreads();

        float s[2][8][4];
#pragma unroll
        for (int mi = 0; mi < 2; mi++)
#pragma unroll
            for (int ni = 0; ni < 8; ni++)
#pragma unroll
                for (int q = 0; q < 4; q++) s[mi][ni][q] = 0.f;

        const uint32_t kst = (uint32_t)((j & 1) * 18432);
#pragma unroll
        for (int kk = 0; kk < 4; kk++) {
            uint32_t a[2][4];
#pragma unroll
            for (int mi = 0; mi < 2; mi++)
                LDSM4(a[mi], aBase + mi * 2304 + kk * 32);
            uint32_t bk[8][2];
#pragma unroll
            for (int np = 0; np < 4; np++) {
                uint32_t r4[4];
                LDSM4(r4, bBaseK + kst + np * 2304 + kk * 32);
                bk[2 * np][0] = r4[0]; bk[2 * np][1] = r4[1];
                bk[2 * np + 1][0] = r4[2]; bk[2 * np + 1][1] = r4[3];
            }
#pragma unroll
            for (int mi = 0; mi < 2; mi++)
#pragma unroll
                for (int ni = 0; ni < 8; ni++)
                    mma16816(s[mi][ni], a[mi], bk[ni]);
        }

#pragma unroll
        for (int mi = 0; mi < 2; mi++) {
            const int r = wm * 32 + mi * 16 + rl;
            const float i0 = invp[r], i1 = invp[r + 8];
#pragma unroll
            for (int ni = 0; ni < 8; ni++) {
                const int c = wn * 64 + ni * 8 + (lane & 3) * 2;
                float2 v0 = make_float2(__expf(s[mi][ni][0] * 0.03125f) * i0,
                                        __expf(s[mi][ni][1] * 0.03125f) * i0);
                float2 v1 = make_float2(__expf(s[mi][ni][2] * 0.03125f) * i1,
                                        __expf(s[mi][ni][3] * 0.03125f) * i1);
                size_t base = ((size_t)h * SEQ + q0 + r) * (size_t)SEQ + j * 128 + c;
                *(float2*)(attn + base) = v0;
                *(float2*)(attn + base + 8 * SEQ) = v1;
            }
        }
        __syncthreads();
        if (j + 2 < 16) { loadK(j + 2); CP_ASYNC_COMMIT(); }
    }
}

// ============================ host launch ============================
static constexpr int SMEM3 = 3 * (2 * 256 * 80 + 2 * 64 * 80);  // 153600

extern "C" void kernel_launch(void* const* d_in, const int* in_sizes, int n_in,
                              void* d_out, int out_size)
{
    const float* x  = (const float*)d_in[0];
    const float* Wq = (const float*)d_in[1];
    const float* bq = (const float*)d_in[2];
    const float* Wk = (const float*)d_in[3];
    const float* bk = (const float*)d_in[4];
    const float* Wv = (const float*)d_in[5];
    const float* bv = (const float*)d_in[6];
    const float* Wo = (const float*)d_in[7];
    const float* bo = (const float*)d_in[8];

    float* out  = (float*)d_out;
    float* attn = out + (size_t)SEQ * EMB;

#define SYM(p, s) void* p##_v; cudaGetSymbolAddress(&p##_v, s);
    SYM(Vf, g_Vf) SYM(invs, g_invsum)
    SYM(xhi, g_xhi) SYM(xlo, g_xlo)
    SYM(Qhi, g_Qhi) SYM(Khi, g_Khi) SYM(Vt16, g_Vt16)
    SYM(chi, g_chi) SYM(clo, g_clo)
#undef SYM
#define BF(p) ((__nv_bfloat16*)p##_v)
#define FL(p) ((float*)p##_v)

    cudaFuncSetAttribute(proj_gemm, cudaFuncAttributeMaxDynamicSharedMemorySize, SMEM3);
    cudaFuncSetAttribute(attention_phase1, cudaFuncAttributeMaxDynamicSharedMemorySize, FA_SMEM);
    cudaFuncSetAttribute(attention_phase2, cudaFuncAttributeMaxDynamicSharedMemorySize, P2_SMEM);

    const int nSE = SEQ * EMB;

    split_pair<<<nSE / 256, 256>>>(x, BF(xhi), BF(xlo), nSE);

    // QKV in one launch; Q/K use 2-product, V 3-product
    proj_gemm<<<dim3(EMB / 64, SEQ / 256, 3), 256, SMEM3>>>(
        BF(xhi), BF(xlo), Wq, Wk, Wv, bq, bk, bv,
        BF(Qhi), BF(Khi), FL(Vf), 0);

    transpose_f16<<<dim3(EMB / 32, SEQ / 32), dim3(32, 8)>>>(FL(Vf), (__half*)Vt16_v);

    // attention phase 1: softmax stats + ctx
    attention_phase1<<<dim3(SEQ / 128, NH), 256, FA_SMEM>>>(
        BF(Qhi), BF(Khi), (const __half*)Vt16_v, FL(invs), BF(chi), BF(clo));

    // out = ctx @ Wo^T + bo (full 3-product)
    proj_gemm<<<dim3(EMB / 64, SEQ / 256, 1), 256, SMEM3>>>(
        BF(chi), BF(clo), Wo, nullptr, nullptr, bo, nullptr, nullptr,
        nullptr, nullptr, out, 1);

    // attention phase 2: write normalized attn
    attention_phase2<<<dim3(SEQ / 128, NH), 256, P2_SMEM>>>(
        BF(Qhi), BF(Khi), FL(invs), attn);
#undef BF
#undef FL
}

// round 13
// speedup vs baseline: 4.8517x; 1.0778x over previous
#include <cuda_runtime.h>
#include <cuda_bf16.h>
#include <cuda_fp16.h>
#include <cstdint>
#include <math.h>

#define SEQ 2048
#define EMB 1024
#define NH  16
#define HD  64

// Q prescale: log2(e)/32 — S is computed in log2 domain, P = 2^S.
#define QSCALE 0.0450842151f

// ============================ helpers ============================
#define CP_ASYNC16(dst, src) \
    asm volatile("cp.async.cg.shared.global [%0], [%1], 16;" :: "r"(dst), "l"(src) : "memory")
#define CP_ASYNC_COMMIT() asm volatile("cp.async.commit_group;" ::: "memory")
#define CP_ASYNC_WAIT0()  asm volatile("cp.async.wait_group 0;" ::: "memory")
#define CP_ASYNC_WAIT1()  asm volatile("cp.async.wait_group 1;" ::: "memory")

#define LDSM4(r, addr) \
    asm volatile("ldmatrix.sync.aligned.m8n8.x4.shared.b16 {%0,%1,%2,%3}, [%4];" \
        : "=r"((r)[0]), "=r"((r)[1]), "=r"((r)[2]), "=r"((r)[3]) : "r"(addr))

__device__ __forceinline__ void mma16816(float* d, const uint32_t* a, const uint32_t* b) {
    asm volatile(
        "mma.sync.aligned.m16n8k16.row.col.f32.bf16.bf16.f32 "
        "{%0,%1,%2,%3}, {%4,%5,%6,%7}, {%8,%9}, {%0,%1,%2,%3};"
        : "+f"(d[0]), "+f"(d[1]), "+f"(d[2]), "+f"(d[3])
        : "r"(a[0]), "r"(a[1]), "r"(a[2]), "r"(a[3]), "r"(b[0]), "r"(b[1]));
}

__device__ __forceinline__ void mma16816h(float* d, const uint32_t* a, const uint32_t* b) {
    asm volatile(
        "mma.sync.aligned.m16n8k16.row.col.f32.f16.f16.f32 "
        "{%0,%1,%2,%3}, {%4,%5,%6,%7}, {%8,%9}, {%0,%1,%2,%3};"
        : "+f"(d[0]), "+f"(d[1]), "+f"(d[2]), "+f"(d[3])
        : "r"(a[0]), "r"(a[1]), "r"(a[2]), "r"(a[3]), "r"(b[0]), "r"(b[1]));
}

__device__ __forceinline__ uint32_t pack2(float x, float y) {
    __nv_bfloat162 t = __floats2bfloat162_rn(x, y);
    return *(uint32_t*)&t;
}
__device__ __forceinline__ uint32_t hpack2(float x, float y) {
    __half2 t = __floats2half2_rn(x, y);
    return *(uint32_t*)&t;
}
__device__ __forceinline__ float ex2f(float x) {
    float r;
    asm("ex2.approx.ftz.f32 %0, %1;" : "=f"(r) : "f"(x));
    return r;
}

// ============================ device scratch ============================
__device__ __align__(256) float g_Vf[SEQ * EMB];
__device__ __align__(256) float g_invsum[NH * SEQ];

__device__ __align__(256) __nv_bfloat16 g_xhi[SEQ * EMB],  g_xlo[SEQ * EMB];
__device__ __align__(256) __nv_bfloat16 g_Qhi[SEQ * EMB];                      // [NH][SEQ][64], prescaled
__device__ __align__(256) __nv_bfloat16 g_Khi[SEQ * EMB];                      // [NH][SEQ][64]
__device__ __align__(256) __half        g_Vt16[EMB * SEQ];                     // V^T [EMB][SEQ] fp16
__device__ __align__(256) __nv_bfloat16 g_chi[SEQ * EMB],  g_clo[SEQ * EMB];   // ctx [SEQ][EMB]

// ============================ split / transpose ============================
__global__ __launch_bounds__(256)
void split_pair(const float* __restrict__ src, __nv_bfloat16* __restrict__ hi,
                __nv_bfloat16* __restrict__ lo, int n)
{
    int i = blockIdx.x * 256 + threadIdx.x;
    if (i < n) {
        float v = src[i];
        __nv_bfloat16 h = __float2bfloat16(v);
        hi[i] = h;
        lo[i] = __float2bfloat16(v - __bfloat162float(h));
    }
}

__global__ __launch_bounds__(256)
void transpose_f16(const float* __restrict__ V, __half* __restrict__ out)
{
    __shared__ float t[32][33];
    int e0 = blockIdx.x * 32, s0 = blockIdx.y * 32;
    int tx = threadIdx.x, ty = threadIdx.y;  // 32 x 8
#pragma unroll
    for (int i = 0; i < 32; i += 8)
        t[ty + i][tx] = V[(size_t)(s0 + ty + i) * EMB + e0 + tx];
    __syncthreads();
#pragma unroll
    for (int i = 0; i < 32; i += 8) {
        size_t o = (size_t)(e0 + ty + i) * SEQ + s0 + tx;
        out[o] = __float2half(t[tx][ty + i]);
    }
}

// ============================ HMMA NT projection GEMM ============================
// BM=256, BN=64. kind 0 (QKV): z0: Wq -> Qhi packed (1-prod, prescaled by QSCALE);
// z1: Wk -> Khi packed (1-prod); z2: Wv -> fp32 (3-prod). kind 1 (Wo, 3-prod).
__global__ __launch_bounds__(256, 1)
void proj_gemm(const __nv_bfloat16* __restrict__ Ahi, const __nv_bfloat16* __restrict__ Alo,
               const float* __restrict__ W0, const float* __restrict__ W1,
               const float* __restrict__ W2,
               const float* __restrict__ b0, const float* __restrict__ b1,
               const float* __restrict__ b2,
               __nv_bfloat16* __restrict__ P0hi, __nv_bfloat16* __restrict__ P1hi,
               float* __restrict__ Cf, int kind)
{
    constexpr int APLANE = 256 * 80;
    constexpr int BPLANE = 64 * 80;
    constexpr int STAGE  = 2 * APLANE + 2 * BPLANE;  // 51200
    constexpr int NC = EMB / 32;

    extern __shared__ char dsm[];
    const uint32_t smem0 = (uint32_t)__cvta_generic_to_shared(dsm);

    const int tid  = threadIdx.x;
    const int wid  = tid >> 5;
    const int lane = tid & 31;
    const int wm = wid & 3;
    const int wn = wid >> 2;
    const int rl = lane >> 2;

    const int z = blockIdx.z;
    const float* Bf   = (z == 0) ? W0 : (z == 1) ? W1 : W2;
    const float* bias = (z == 0) ? b0 : (z == 1) ? b1 : b2;
    const int mode = (kind == 1 || z == 2) ? 0 : 2;
    const bool three = (kind == 1 || z == 2);   // full 3-product; else 1-product
    __nv_bfloat16* Chi = (z == 0) ? P0hi : P1hi;
    const float oscale = (mode == 2 && z == 0) ? QSCALE : 1.0f;

    const int row0 = blockIdx.y * 256;
    const int col0 = blockIdx.x * 64;

    float acc[4][4][4];
#pragma unroll
    for (int mi = 0; mi < 4; mi++)
#pragma unroll
        for (int ni = 0; ni < 4; ni++)
#pragma unroll
            for (int j = 0; j < 4; j++) acc[mi][ni][j] = 0.f;

    const int nA = three ? 2048 : 1024;
    auto load_A = [&](int c) {
        const uint32_t sb = smem0 + (c % 3) * STAGE;
        for (int i = tid; i < nA; i += 256) {
            int pl = i >> 10;
            int rem = i & 1023;
            int r = rem >> 2, g = rem & 3;
            const __nv_bfloat16* src =
                (pl ? Alo : Ahi) + (size_t)(row0 + r) * EMB + c * 32 + g * 8;
            CP_ASYNC16(sb + pl * APLANE + r * 80 + g * 16, src);
        }
        CP_ASYNC_COMMIT();
    };

    float4 breg[2];
    const int br = tid >> 2;
    const int bseg = (tid & 3) * 8;
    auto ldg_B = [&](int c) {
        const float* src = Bf + (size_t)(col0 + br) * EMB + c * 32 + bseg;
        breg[0] = *(const float4*)(src);
        breg[1] = *(const float4*)(src + 4);
    };
    auto sts_B = [&](int c) {
        const uint32_t off = (uint32_t)((c % 3) * STAGE + 2 * APLANE + br * 80 + bseg * 2);
        uint4 hi4;
        uint32_t* h = (uint32_t*)&hi4;
        float4 v0 = breg[0], v1 = breg[1];
        h[0] = pack2(v0.x, v0.y); h[1] = pack2(v0.z, v0.w);
        h[2] = pack2(v1.x, v1.y); h[3] = pack2(v1.z, v1.w);
        *(uint4*)(dsm + off) = hi4;
        if (three) {
            uint4 lo4;
            uint32_t* l = (uint32_t*)&lo4;
            __nv_bfloat162* hb = (__nv_bfloat162*)h;
            l[0] = pack2(v0.x - __low2float(hb[0]), v0.y - __high2float(hb[0]));
            l[1] = pack2(v0.z - __low2float(hb[1]), v0.w - __high2float(hb[1]));
            l[2] = pack2(v1.x - __low2float(hb[2]), v1.y - __high2float(hb[2]));
            l[3] = pack2(v1.z - __low2float(hb[3]), v1.w - __high2float(hb[3]));
            *(uint4*)(dsm + off + BPLANE) = lo4;
        }
    };

    auto compute = [&](int c) {
        const uint32_t sb = smem0 + (c % 3) * STAGE;
        const uint32_t aAddr = sb + (wm * 64 + (lane & 15)) * 80 + (lane >> 4) * 16;
        const uint32_t bAddr = sb + 2 * APLANE
            + (wn * 32 + (lane >> 4) * 8 + (lane & 7)) * 80 + ((lane >> 3) & 1) * 16;
#pragma unroll
        for (int kk = 0; kk < 2; kk++) {
            uint32_t a0[4][4], a1[4][4];
#pragma unroll
            for (int mi = 0; mi < 4; mi++)
                LDSM4(a0[mi], aAddr + mi * 16 * 80 + kk * 32);
            if (three) {
#pragma unroll
                for (int mi = 0; mi < 4; mi++)
                    LDSM4(a1[mi], aAddr + APLANE + mi * 16 * 80 + kk * 32);
            }
            uint32_t b0r[4][2], b1r[4][2];
            {
#pragma unroll
                for (int np = 0; np < 2; np++) {
                    uint32_t r4[4];
                    LDSM4(r4, bAddr + np * 16 * 80 + kk * 32);
                    b0r[2 * np][0] = r4[0]; b0r[2 * np][1] = r4[1];
                    b0r[2 * np + 1][0] = r4[2]; b0r[2 * np + 1][1] = r4[3];
                }
                if (three) {
#pragma unroll
                    for (int np = 0; np < 2; np++) {
                        uint32_t r4[4];
                        LDSM4(r4, bAddr + BPLANE + np * 16 * 80 + kk * 32);
                        b1r[2 * np][0] = r4[0]; b1r[2 * np][1] = r4[1];
                        b1r[2 * np + 1][0] = r4[2]; b1r[2 * np + 1][1] = r4[3];
                    }
                }
            }
#pragma unroll
            for (int mi = 0; mi < 4; mi++)
#pragma unroll
                for (int ni = 0; ni < 4; ni++)
                    mma16816(acc[mi][ni], a0[mi], b0r[ni]);
            if (three) {
#pragma unroll
                for (int mi = 0; mi < 4; mi++)
#pragma unroll
                    for (int ni = 0; ni < 4; ni++) {
                        mma16816(acc[mi][ni], a0[mi], b1r[ni]);
                        mma16816(acc[mi][ni], a1[mi], b0r[ni]);
                    }
            }
        }
    };

    ldg_B(0); sts_B(0); load_A(0);
    ldg_B(1); sts_B(1); load_A(1);
    ldg_B(2);

    for (int c = 0; c < NC; c++) {
        if (c + 1 < NC) { CP_ASYNC_WAIT1(); } else { CP_ASYNC_WAIT0(); }
        __syncthreads();
        compute(c);
        if (c + 2 < NC) {
            sts_B(c + 2);
            load_A(c + 2);
            if (c + 3 < NC) ldg_B(c + 3);
        }
    }

    const int cl = (lane & 3) * 2;
#pragma unroll
    for (int mi = 0; mi < 4; mi++) {
        const int r = row0 + wm * 64 + mi * 16 + rl;
#pragma unroll
        for (int ni = 0; ni < 4; ni++) {
            const int cc = col0 + wn * 32 + ni * 8 + cl;
            const float bb0 = bias[cc], bb1 = bias[cc + 1];
            float v00 = (acc[mi][ni][0] + bb0) * oscale;
            float v01 = (acc[mi][ni][1] + bb1) * oscale;
            float v10 = (acc[mi][ni][2] + bb0) * oscale;
            float v11 = (acc[mi][ni][3] + bb1) * oscale;
            if (mode == 0) {
                *(float2*)(Cf + (size_t)r * EMB + cc) = make_float2(v00, v01);
                *(float2*)(Cf + (size_t)(r + 8) * EMB + cc) = make_float2(v10, v11);
            } else {
                size_t o0 = (size_t)(cc >> 6) * ((size_t)SEQ * 64) + (size_t)r * 64 + (cc & 63);
                size_t o1 = o0 + 8 * 64;
                *(uint32_t*)(Chi + o0) = pack2(v00, v01);
                *(uint32_t*)(Chi + o1) = pack2(v10, v11);
            }
        }
    }
}

// ============================ attention phase 1 ============================
// S = Qhi@Khi^T (log2 domain, Q prescaled), P = 2^S via ex2.approx.f16x2,
// rowsum->g_invsum, ctx += P@V (fp16 x fp16).
static constexpr int FA_OFF_K   = 18432;
static constexpr int FA_OFF_V   = 55296;
static constexpr int FA_OFF_RED = 90112;
static constexpr int FA_SMEM    = 91648;

__global__ __launch_bounds__(256, 1)
void attention_phase1(const __nv_bfloat16* __restrict__ Qhi,
                      const __nv_bfloat16* __restrict__ Khi,
                      const __half* __restrict__ Vt16,
                      float* __restrict__ invsum,
                      __nv_bfloat16* __restrict__ chi, __nv_bfloat16* __restrict__ clo)
{
    extern __shared__ char sm[];
    const uint32_t sb = (uint32_t)__cvta_generic_to_shared(sm);

    const int tid  = threadIdx.x;
    const int lane = tid & 31, wid = tid >> 5;
    const int wm = wid & 3, wn = wid >> 2;
    const int rl = lane >> 2;
    const int h  = blockIdx.y;
    const int q0 = blockIdx.x * 128;

    auto loadQ = [&]() {
        for (int i = tid; i < 1024; i += 256) {
            int r = i >> 3, g = i & 7;
            const __nv_bfloat16* src = Qhi + ((size_t)h * SEQ + q0 + r) * 64 + g * 8;
            CP_ASYNC16(sb + r * 144 + g * 16, src);
        }
    };
    auto loadK = [&](int j) {
        int st = (j & 1) * 18432;
        for (int i = tid; i < 1024; i += 256) {
            int r = i >> 3, g = i & 7;
            const __nv_bfloat16* src = Khi + ((size_t)h * SEQ + j * 128 + r) * 64 + g * 8;
            CP_ASYNC16(sb + FA_OFF_K + st + r * 144 + g * 16, src);
        }
    };
    auto loadV = [&](int j) {
        int st = (j & 1) * 17408;
        for (int i = tid; i < 1024; i += 256) {
            int d = i >> 4, g = i & 15;
            const __half* src = Vt16 + ((size_t)(h * 64 + d)) * SEQ + j * 128 + g * 8;
            CP_ASYNC16(sb + FA_OFF_V + st + d * 272 + g * 16, src);
        }
    };

    const uint32_t aBase  = sb + (wm * 32 + (lane & 15)) * 144 + (lane >> 4) * 16;
    const uint32_t bBaseK = sb + FA_OFF_K + (wn * 64 + (lane >> 4) * 8 + (lane & 7)) * 144
                            + ((lane >> 3) & 1) * 16;
    const uint32_t bBaseV = sb + FA_OFF_V + ((lane >> 4) * 8 + (lane & 7)) * 272
                            + ((lane >> 3) & 1) * 16 + wn * 128;

    float ctx[2][8][4];
#pragma unroll
    for (int mi = 0; mi < 2; mi++)
#pragma unroll
        for (int nd = 0; nd < 8; nd++)
#pragma unroll
            for (int j = 0; j < 4; j++) ctx[mi][nd][j] = 0.f;
    float rs[4] = {0.f, 0.f, 0.f, 0.f};

    loadQ(); loadK(0); loadV(0); CP_ASYNC_COMMIT();
    loadK(1); loadV(1); CP_ASYNC_COMMIT();

    for (int j = 0; j < 16; j++) {
        if (j < 15) { CP_ASYNC_WAIT1(); } else { CP_ASYNC_WAIT0(); }
        __syncthreads();

        float s[2][8][4];
#pragma unroll
        for (int mi = 0; mi < 2; mi++)
#pragma unroll
            for (int ni = 0; ni < 8; ni++)
#pragma unroll
                for (int q = 0; q < 4; q++) s[mi][ni][q] = 0.f;

        const uint32_t kst = (uint32_t)((j & 1) * 18432);
#pragma unroll
        for (int kk = 0; kk < 4; kk++) {
            uint32_t a[2][4];
#pragma unroll
            for (int mi = 0; mi < 2; mi++)
                LDSM4(a[mi], aBase + mi * 2304 + kk * 32);
            uint32_t bk[8][2];
#pragma unroll
            for (int np = 0; np < 4; np++) {
                uint32_t r4[4];
                LDSM4(r4, bBaseK + kst + np * 2304 + kk * 32);
                bk[2 * np][0] = r4[0]; bk[2 * np][1] = r4[1];
                bk[2 * np + 1][0] = r4[2]; bk[2 * np + 1][1] = r4[3];
            }
#pragma unroll
            for (int mi = 0; mi < 2; mi++)
#pragma unroll
                for (int ni = 0; ni < 8; ni++)
                    mma16816(s[mi][ni], a[mi], bk[ni]);
        }

        // PV: P = 2^s via ex2.approx.f16x2 (s already log2-scaled)
        const uint32_t vst = (uint32_t)((j & 1) * 17408);
#pragma unroll
        for (int kk = 0; kk < 4; kk++) {
            uint32_t bv[8][2];
#pragma unroll
            for (int np = 0; np < 4; np++) {
                uint32_t r4[4];
                LDSM4(r4, bBaseV + vst + np * 4352 + kk * 32);
                bv[2 * np][0] = r4[0]; bv[2 * np][1] = r4[1];
                bv[2 * np + 1][0] = r4[2]; bv[2 * np + 1][1] = r4[3];
            }
#pragma unroll
            for (int mi = 0; mi < 2; mi++) {
                const int e = 2 * kk, o = 2 * kk + 1;
                uint32_t ah[4];
                ah[0] = hpack2(s[mi][e][0], s[mi][e][1]);
                ah[1] = hpack2(s[mi][e][2], s[mi][e][3]);
                ah[2] = hpack2(s[mi][o][0], s[mi][o][1]);
                ah[3] = hpack2(s[mi][o][2], s[mi][o][3]);
#pragma unroll
                for (int q = 0; q < 4; q++)
                    asm("ex2.approx.f16x2 %0, %0;" : "+r"(ah[q]));
                __half2 t0 = __hadd2(*(__half2*)&ah[0], *(__half2*)&ah[2]);
                __half2 t1 = __hadd2(*(__half2*)&ah[1], *(__half2*)&ah[3]);
                float2 f0 = __half22float2(t0), f1 = __half22float2(t1);
                rs[mi * 2 + 0] += f0.x + f0.y;
                rs[mi * 2 + 1] += f1.x + f1.y;
#pragma unroll
                for (int nd = 0; nd < 8; nd++)
                    mma16816h(ctx[mi][nd], ah, bv[nd]);
            }
        }
        __syncthreads();
        if (j + 2 < 16) { loadK(j + 2); loadV(j + 2); CP_ASYNC_COMMIT(); }
    }

#pragma unroll
    for (int i = 0; i < 4; i++) {
        rs[i] += __shfl_xor_sync(0xffffffffu, rs[i], 1);
        rs[i] += __shfl_xor_sync(0xffffffffu, rs[i], 2);
    }
    float* redp = (float*)(sm + FA_OFF_RED);
    float* invp = (float*)(sm + FA_OFF_RED + 1024);
    if ((lane & 3) == 0) {
#pragma unroll
        for (int mi = 0; mi < 2; mi++) {
            redp[wn * 128 + wm * 32 + mi * 16 + rl]     = rs[mi * 2 + 0];
            redp[wn * 128 + wm * 32 + mi * 16 + rl + 8] = rs[mi * 2 + 1];
        }
    }
    __syncthreads();
    if (tid < 128) {
        float inv = 1.0f / (redp[tid] + redp[128 + tid]);
        invp[tid] = inv;
        invsum[(size_t)h * SEQ + q0 + tid] = inv;
    }
    __syncthreads();

    float* credp = (float*)(sm + FA_OFF_V);
    if (wn == 1) {
#pragma unroll
        for (int mi = 0; mi < 2; mi++) {
            const int r = wm * 32 + mi * 16 + rl;
#pragma unroll
            for (int nd = 0; nd < 8; nd++) {
                const int c = nd * 8 + (lane & 3) * 2;
                *(float2*)(credp + r * 64 + c)       = make_float2(ctx[mi][nd][0], ctx[mi][nd][1]);
                *(float2*)(credp + (r + 8) * 64 + c) = make_float2(ctx[mi][nd][2], ctx[mi][nd][3]);
            }
        }
    }
    __syncthreads();
    if (wn == 0) {
#pragma unroll
        for (int mi = 0; mi < 2; mi++) {
            const int r = wm * 32 + mi * 16 + rl;
            const float i0 = invp[r], i1 = invp[r + 8];
#pragma unroll
            for (int nd = 0; nd < 8; nd++) {
                const int c = nd * 8 + (lane & 3) * 2;
                float2 p0 = *(float2*)(credp + r * 64 + c);
                float2 p1 = *(float2*)(credp + (r + 8) * 64 + c);
                float v00 = (ctx[mi][nd][0] + p0.x) * i0;
                float v01 = (ctx[mi][nd][1] + p0.y) * i0;
                float v10 = (ctx[mi][nd][2] + p1.x) * i1;
                float v11 = (ctx[mi][nd][3] + p1.y) * i1;
                size_t o0 = (size_t)(q0 + r) * EMB + h * 64 + c;
                size_t o1 = (size_t)(q0 + r + 8) * EMB + h * 64 + c;
                uint32_t h0 = pack2(v00, v01), h1 = pack2(v10, v11);
                __nv_bfloat162 hb0 = *(__nv_bfloat162*)&h0;
                __nv_bfloat162 hb1 = *(__nv_bfloat162*)&h1;
                uint32_t l0 = pack2(v00 - __low2float(hb0), v01 - __high2float(hb0));
                uint32_t l1 = pack2(v10 - __low2float(hb1), v11 - __high2float(hb1));
                *(uint32_t*)(chi + o0) = h0;
                *(uint32_t*)(chi + o1) = h1;
                *(uint32_t*)(clo + o0) = l0;
                *(uint32_t*)(clo + o1) = l1;
            }
        }
    }
}

// ============================ attention phase 2 ============================
static constexpr int P2_OFF_K   = 18432;
static constexpr int P2_OFF_INV = 55296;
static constexpr int P2_SMEM    = 55808;

__global__ __launch_bounds__(256)
void attention_phase2(const __nv_bfloat16* __restrict__ Qhi,
                      const __nv_bfloat16* __restrict__ Khi,
                      const float* __restrict__ invsum,
                      float* __restrict__ attn)
{
    extern __shared__ char sm[];
    const uint32_t sb = (uint32_t)__cvta_generic_to_shared(sm);

    const int tid  = threadIdx.x;
    const int lane = tid & 31, wid = tid >> 5;
    const int wm = wid & 3, wn = wid >> 2;
    const int rl = lane >> 2;
    const int h  = blockIdx.y;
    const int q0 = blockIdx.x * 128;

    float* invp = (float*)(sm + P2_OFF_INV);
    if (tid < 128) invp[tid] = invsum[(size_t)h * SEQ + q0 + tid];

    auto loadQ = [&]() {
        for (int i = tid; i < 1024; i += 256) {
            int r = i >> 3, g = i & 7;
            const __nv_bfloat16* src = Qhi + ((size_t)h * SEQ + q0 + r) * 64 + g * 8;
            CP_ASYNC16(sb + r * 144 + g * 16, src);
        }
    };
    auto loadK = [&](int j) {
        int st = (j & 1) * 18432;
        for (int i = tid; i < 1024; i += 256) {
            int r = i >> 3, g = i & 7;
            const __nv_bfloat16* src = Khi + ((size_t)h * SEQ + j * 128 + r) * 64 + g * 8;
            CP_ASYNC16(sb + P2_OFF_K + st + r * 144 + g * 16, src);
        }
    };

    const uint32_t aBase  = sb + (wm * 32 + (lane & 15)) * 144 + (lane >> 4) * 16;
    const uint32_t bBaseK = sb + P2_OFF_K + (wn * 64 + (lane >> 4) * 8 + (lane & 7)) * 144
                            + ((lane >> 3) & 1) * 16;

    loadQ(); loadK(0); CP_ASYNC_COMMIT();
    loadK(1); CP_ASYNC_COMMIT();

    for (int j = 0; j < 16; j++) {
        if (j < 15) { CP_ASYNC_WAIT1(); } else { CP_ASYNC_WAIT0(); }
        __syncthreads();

        float s[2][8][4];
#pragma unroll
        for (int mi = 0; mi < 2; mi++)
#pragma unroll
            for (int ni = 0; ni < 8; ni++)
#pragma unroll
                for (int q = 0; q < 4; q++) s[mi][ni][q] = 0.f;

        const uint32_t kst = (uint32_t)((j & 1) * 18432);
#pragma unroll
        for (int kk = 0; kk < 4; kk++) {
            uint32_t a[2][4];
#pragma unroll
            for (int mi = 0; mi < 2; mi++)
                LDSM4(a[mi], aBase + mi * 2304 + kk * 32);
            uint32_t bk[8][2];
#pragma unroll
            for (int np = 0; np < 4; np++) {
                uint32_t r4[4];
                LDSM4(r4, bBaseK + kst + np * 2304 + kk * 32);
                bk[2 * np][0] = r4[0]; bk[2 * np][1] = r4[1];
                bk[2 * np + 1][0] = r4[2]; bk[2 * np + 1][1] = r4[3];
            }
#pragma unroll
            for (int mi = 0; mi < 2; mi++)
#pragma unroll
                for (int ni = 0; ni < 8; ni++)
                    mma16816(s[mi][ni], a[mi], bk[ni]);
        }

#pragma unroll
        for (int mi = 0; mi < 2; mi++) {
            const int r = wm * 32 + mi * 16 + rl;
            const float i0 = invp[r], i1 = invp[r + 8];
#pragma unroll
            for (int ni = 0; ni < 8; ni++) {
                const int c = wn * 64 + ni * 8 + (lane & 3) * 2;
                float2 v0 = make_float2(ex2f(s[mi][ni][0]) * i0,
                                        ex2f(s[mi][ni][1]) * i0);
                float2 v1 = make_float2(ex2f(s[mi][ni][2]) * i1,
                                        ex2f(s[mi][ni][3]) * i1);
                size_t base = ((size_t)h * SEQ + q0 + r) * (size_t)SEQ + j * 128 + c;
                *(float2*)(attn + base) = v0;
                *(float2*)(attn + base + 8 * SEQ) = v1;
            }
        }
        __syncthreads();
        if (j + 2 < 16) { loadK(j + 2); CP_ASYNC_COMMIT(); }
    }
}

// ============================ host launch ============================
static constexpr int SMEM3 = 3 * (2 * 256 * 80 + 2 * 64 * 80);  // 153600

extern "C" void kernel_launch(void* const* d_in, const int* in_sizes, int n_in,
                              void* d_out, int out_size)
{
    const float* x  = (const float*)d_in[0];
    const float* Wq = (const float*)d_in[1];
    const float* bq = (const float*)d_in[2];
    const float* Wk = (const float*)d_in[3];
    const float* bk = (const float*)d_in[4];
    const float* Wv = (const float*)d_in[5];
    const float* bv = (const float*)d_in[6];
    const float* Wo = (const float*)d_in[7];
    const float* bo = (const float*)d_in[8];

    float* out  = (float*)d_out;
    float* attn = out + (size_t)SEQ * EMB;

#define SYM(p, s) void* p##_v; cudaGetSymbolAddress(&p##_v, s);
    SYM(Vf, g_Vf) SYM(invs, g_invsum)
    SYM(xhi, g_xhi) SYM(xlo, g_xlo)
    SYM(Qhi, g_Qhi) SYM(Khi, g_Khi) SYM(Vt16, g_Vt16)
    SYM(chi, g_chi) SYM(clo, g_clo)
#undef SYM
#define BF(p) ((__nv_bfloat16*)p##_v)
#define FL(p) ((float*)p##_v)

    cudaFuncSetAttribute(proj_gemm, cudaFuncAttributeMaxDynamicSharedMemorySize, SMEM3);
    cudaFuncSetAttribute(attention_phase1, cudaFuncAttributeMaxDynamicSharedMemorySize, FA_SMEM);
    cudaFuncSetAttribute(attention_phase2, cudaFuncAttributeMaxDynamicSharedMemorySize, P2_SMEM);

    const int nSE = SEQ * EMB;

    split_pair<<<nSE / 256, 256>>>(x, BF(xhi), BF(xlo), nSE);

    // QKV: Q (1-prod, prescaled log2e/32), K (1-prod), V (3-prod fp32)
    proj_gemm<<<dim3(EMB / 64, SEQ / 256, 3), 256, SMEM3>>>(
        BF(xhi), BF(xlo), Wq, Wk, Wv, bq, bk, bv,
        BF(Qhi), BF(Khi), FL(Vf), 0);

    transpose_f16<<<dim3(EMB / 32, SEQ / 32), dim3(32, 8)>>>(FL(Vf), (__half*)Vt16_v);

    // attention phase 1: softmax stats + ctx
    attention_phase1<<<dim3(SEQ / 128, NH), 256, FA_SMEM>>>(
        BF(Qhi), BF(Khi), (const __half*)Vt16_v, FL(invs), BF(chi), BF(clo));

    // out = ctx @ Wo^T + bo (full 3-product)
    proj_gemm<<<dim3(EMB / 64, SEQ / 256, 1), 256, SMEM3>>>(
        BF(chi), BF(clo), Wo, nullptr, nullptr, bo, nullptr, nullptr,
        nullptr, nullptr, out, 1);

    // attention phase 2: write normalized attn (P = 2^s)
    attention_phase2<<<dim3(SEQ / 128, NH), 256, P2_SMEM>>>(
        BF(Qhi), BF(Khi), FL(invs), attn);
#undef BF
#undef FL
}